// round 3
// baseline (speedup 1.0000x reference)
#include <cuda_runtime.h>
#include <math.h>

#define EMBED   2048
#define NHEADS  16
#define NKV     4
#define HDIM    128
#define BATCH   2
#define SEQ     2048
#define NTOK    (BATCH*SEQ)      // 4096
#define KVDIM   1024             // k(512) + v(512)

// Scratch (device globals: allowed; no runtime allocation)
__device__ float g_q [NTOK * EMBED];   // [tok, h*128+d]
__device__ float g_kv[NTOK * KVDIM];   // [tok, (k: kvh*128+d) | 512 + (v: kvh*128+d)]
__device__ float g_o [NTOK * EMBED];   // attention output per token

// ---------------------------------------------------------------------------
// GEMM: C[M,N] = A[M,K] @ W[N,K]^T (+bias).  Both operands K-major (row-major).
// 128x128 block, BK=16, 256 threads, 8x8 per-thread register tile.
// ---------------------------------------------------------------------------
__global__ __launch_bounds__(256) void gemm_kernel(
    const float* __restrict__ A, const float* __restrict__ W,
    const float* __restrict__ bias, float* __restrict__ C,
    int M, int N, int K)
{
    __shared__ float As[16][132];   // [k][m], pad->float4-aligned rows
    __shared__ float Bs[16][132];   // [k][n]

    const int bm  = blockIdx.y * 128;
    const int bn  = blockIdx.x * 128;
    const int tid = threadIdx.x;
    const int tx  = tid & 15, ty = tid >> 4;
    const int row0 = ty * 8, col0 = tx * 8;

    float acc[8][8];
#pragma unroll
    for (int u = 0; u < 8; u++)
#pragma unroll
        for (int v = 0; v < 8; v++) acc[u][v] = 0.f;

    for (int kb = 0; kb < K; kb += 16) {
        // Load A & W tiles (128x16 each = 512 float4; 2 per thread)
#pragma unroll
        for (int p = 0; p < 2; p++) {
            int f  = tid + p * 256;
            int r  = f >> 2;      // 0..127
            int k4 = f & 3;       // 0..3
            float4 av = *(const float4*)(A + (size_t)(bm + r) * K + kb + k4 * 4);
            As[k4*4+0][r] = av.x; As[k4*4+1][r] = av.y;
            As[k4*4+2][r] = av.z; As[k4*4+3][r] = av.w;
            float4 bv = *(const float4*)(W + (size_t)(bn + r) * K + kb + k4 * 4);
            Bs[k4*4+0][r] = bv.x; Bs[k4*4+1][r] = bv.y;
            Bs[k4*4+2][r] = bv.z; Bs[k4*4+3][r] = bv.w;
        }
        __syncthreads();

#pragma unroll
        for (int kk = 0; kk < 16; kk++) {
            float4 a0 = *(const float4*)&As[kk][row0];
            float4 a1 = *(const float4*)&As[kk][row0 + 4];
            float4 b0 = *(const float4*)&Bs[kk][col0];
            float4 b1 = *(const float4*)&Bs[kk][col0 + 4];
            float a[8] = {a0.x,a0.y,a0.z,a0.w,a1.x,a1.y,a1.z,a1.w};
            float b[8] = {b0.x,b0.y,b0.z,b0.w,b1.x,b1.y,b1.z,b1.w};
#pragma unroll
            for (int u = 0; u < 8; u++)
#pragma unroll
                for (int v = 0; v < 8; v++) acc[u][v] += a[u] * b[v];
        }
        __syncthreads();
    }

    float bb[8];
#pragma unroll
    for (int v = 0; v < 8; v++) bb[v] = bias ? bias[bn + col0 + v] : 0.f;

#pragma unroll
    for (int u = 0; u < 8; u++) {
        int r = bm + row0 + u;
        float4 o0, o1;
        o0.x = acc[u][0] + bb[0]; o0.y = acc[u][1] + bb[1];
        o0.z = acc[u][2] + bb[2]; o0.w = acc[u][3] + bb[3];
        o1.x = acc[u][4] + bb[4]; o1.y = acc[u][5] + bb[5];
        o1.z = acc[u][6] + bb[6]; o1.w = acc[u][7] + bb[7];
        *(float4*)(C + (size_t)r * N + bn + col0)     = o0;
        *(float4*)(C + (size_t)r * N + bn + col0 + 4) = o1;
    }
}

// ---------------------------------------------------------------------------
// RoPE (in-place on g_q and k-half of g_kv). One thread per (token, head, i<64)
// ---------------------------------------------------------------------------
__global__ void rope_kernel(float* __restrict__ q, float* __restrict__ kv)
{
    const int QTOT = NTOK * NHEADS * 64;
    const int KTOT = NTOK * NKV * 64;
    int idx = blockIdx.x * blockDim.x + threadIdx.x;
    if (idx >= QTOT + KTOT) return;

    float* p0;
    int i, s;
    if (idx < QTOT) {
        i = idx & 63;
        int h = (idx >> 6) & 15;
        int t = idx >> 10;           // /(64*16)
        s = t & (SEQ - 1);
        p0 = q + (size_t)t * EMBED + h * HDIM + i;
    } else {
        int j = idx - QTOT;
        i = j & 63;
        int kvh = (j >> 6) & 3;
        int t = j >> 8;              // /(64*4)
        s = t & (SEQ - 1);
        p0 = kv + (size_t)t * KVDIM + kvh * HDIM + i;   // k occupies cols [0,512)
    }
    float freq = powf(10000.0f, -(float)(2 * i) * (1.0f / 128.0f));
    float ang  = (float)s * freq;
    float sn, cs;
    sincosf(ang, &sn, &cs);
    float x1 = p0[0], x2 = p0[64];
    p0[0]  = x1 * cs - x2 * sn;
    p0[64] = x2 * cs + x1 * sn;
}

// ---------------------------------------------------------------------------
// Flash attention: per block = (64 q rows, head, batch), online softmax over
// 64-wide kv tiles. 256 threads. Dynamic smem ~118KB.
// ---------------------------------------------------------------------------
#define QS_LD 68   // padded leading dim for transposed Q/K tiles
#define PS_LD 68

__global__ __launch_bounds__(256) void attn_kernel()
{
    extern __shared__ float sm[];
    float* Qs = sm;                      // [128][68] k-major
    float* Ks = Qs + 128 * QS_LD;        // [128][68] k-major
    float* Vs = Ks + 128 * QS_LD;        // [64][128] natural
    float* Ps = Vs + 64 * 128;           // [64][68]
    float* m_s    = Ps + 64 * PS_LD;     // [64]
    float* l_s    = m_s + 64;            // [64]
    float* corr_s = l_s + 64;            // [64]

    const int q0  = blockIdx.x * 64;
    const int h   = blockIdx.y;
    const int b   = blockIdx.z;
    const int kvh = h >> 2;
    const int tid = threadIdx.x;
    const int tx  = tid & 15, ty = tid >> 4;
    const int r0 = ty * 4;     // 4 q-rows per thread
    const int c0 = tx * 4;     // 4 score-cols per thread
    const int d0 = tx * 8;     // 8 output-dims per thread
    const float scale = 0.08838834764831845f;  // 1/sqrt(128)

    // Load Q tile transposed
    for (int e = tid; e < 64 * 128; e += 256) {
        int r = e >> 7, k = e & 127;
        Qs[k * QS_LD + r] = g_q[(size_t)(b * SEQ + q0 + r) * EMBED + h * HDIM + k];
    }
    if (tid < 64) { m_s[tid] = -INFINITY; l_s[tid] = 0.f; }

    float o_acc[4][8];
#pragma unroll
    for (int ri = 0; ri < 4; ri++)
#pragma unroll
        for (int u = 0; u < 8; u++) o_acc[ri][u] = 0.f;

    __syncthreads();

    for (int kt = 0; kt < SEQ / 64; kt++) {
        int kv0 = kt * 64;
        // Load K (transposed) + V tiles
        for (int e = tid; e < 64 * 128; e += 256) {
            int j = e >> 7, k = e & 127;
            size_t row = (size_t)(b * SEQ + kv0 + j) * KVDIM;
            Ks[k * QS_LD + j] = g_kv[row + kvh * HDIM + k];
            Vs[j * 128 + k]   = g_kv[row + 512 + kvh * HDIM + k];
        }
        __syncthreads();

        // S = scale * Q @ K^T   (each thread 4x4)
        float s_acc[4][4];
#pragma unroll
        for (int ri = 0; ri < 4; ri++)
#pragma unroll
            for (int ci = 0; ci < 4; ci++) s_acc[ri][ci] = 0.f;

#pragma unroll 8
        for (int k = 0; k < 128; k++) {
            float4 qa = *(const float4*)&Qs[k * QS_LD + r0];
            float4 kb = *(const float4*)&Ks[k * QS_LD + c0];
            float a[4] = {qa.x, qa.y, qa.z, qa.w};
            float bq[4] = {kb.x, kb.y, kb.z, kb.w};
#pragma unroll
            for (int ri = 0; ri < 4; ri++)
#pragma unroll
                for (int ci = 0; ci < 4; ci++) s_acc[ri][ci] += a[ri] * bq[ci];
        }
#pragma unroll
        for (int ri = 0; ri < 4; ri++) {
            float4 w;
            w.x = s_acc[ri][0] * scale; w.y = s_acc[ri][1] * scale;
            w.z = s_acc[ri][2] * scale; w.w = s_acc[ri][3] * scale;
            *(float4*)&Ps[(r0 + ri) * PS_LD + c0] = w;
        }
        __syncthreads();

        // Online softmax, one thread per row
        if (tid < 64) {
            int r = tid;
            float mold = m_s[r];
            float rmax = -INFINITY;
            for (int j = 0; j < 64; j++) rmax = fmaxf(rmax, Ps[r * PS_LD + j]);
            float mnew = fmaxf(mold, rmax);
            float corr = expf(mold - mnew);   // 0 on first tile (mold=-inf)
            float sum = 0.f;
            for (int j = 0; j < 64; j++) {
                float p = expf(Ps[r * PS_LD + j] - mnew);
                Ps[r * PS_LD + j] = p;
                sum += p;
            }
            l_s[r] = l_s[r] * corr + sum;
            m_s[r] = mnew;
            corr_s[r] = corr;
        }
        __syncthreads();

        // Rescale accumulators, then O += P @ V
        float cr[4];
#pragma unroll
        for (int ri = 0; ri < 4; ri++) {
            cr[ri] = corr_s[r0 + ri];
#pragma unroll
            for (int u = 0; u < 8; u++) o_acc[ri][u] *= cr[ri];
        }
#pragma unroll 4
        for (int j = 0; j < 64; j++) {
            float4 v0 = *(const float4*)&Vs[j * 128 + d0];
            float4 v1 = *(const float4*)&Vs[j * 128 + d0 + 4];
#pragma unroll
            for (int ri = 0; ri < 4; ri++) {
                float p = Ps[(r0 + ri) * PS_LD + j];
                o_acc[ri][0] += p * v0.x; o_acc[ri][1] += p * v0.y;
                o_acc[ri][2] += p * v0.z; o_acc[ri][3] += p * v0.w;
                o_acc[ri][4] += p * v1.x; o_acc[ri][5] += p * v1.y;
                o_acc[ri][6] += p * v1.z; o_acc[ri][7] += p * v1.w;
            }
        }
        __syncthreads();
    }

    // Normalize and write out
#pragma unroll
    for (int ri = 0; ri < 4; ri++) {
        float inv = 1.0f / l_s[r0 + ri];
        float4 o0, o1;
        o0.x = o_acc[ri][0] * inv; o0.y = o_acc[ri][1] * inv;
        o0.z = o_acc[ri][2] * inv; o0.w = o_acc[ri][3] * inv;
        o1.x = o_acc[ri][4] * inv; o1.y = o_acc[ri][5] * inv;
        o1.z = o_acc[ri][6] * inv; o1.w = o_acc[ri][7] * inv;
        size_t base = (size_t)(b * SEQ + q0 + r0 + ri) * EMBED + h * HDIM + d0;
        *(float4*)&g_o[base]     = o0;
        *(float4*)&g_o[base + 4] = o1;
    }
}

// ---------------------------------------------------------------------------
extern "C" void kernel_launch(void* const* d_in, const int* in_sizes, int n_in,
                              void* d_out, int out_size)
{
    const float* x   = (const float*)d_in[0];
    const float* Wq  = (const float*)d_in[1];
    const float* bq  = (const float*)d_in[2];
    const float* Wkv = (const float*)d_in[3];
    const float* bkv = (const float*)d_in[4];
    const float* Wo  = (const float*)d_in[5];
    float* out = (float*)d_out;

    float *qb, *kvb, *ob;
    cudaGetSymbolAddress((void**)&qb,  g_q);
    cudaGetSymbolAddress((void**)&kvb, g_kv);
    cudaGetSymbolAddress((void**)&ob,  g_o);

    const int ATTN_SMEM = (128*QS_LD*2 + 64*128 + 64*PS_LD + 192) * (int)sizeof(float);
    cudaFuncSetAttribute(attn_kernel, cudaFuncAttributeMaxDynamicSharedMemorySize, ATTN_SMEM);

    // 1) q = x @ Wq^T + bq     [4096, 2048]
    gemm_kernel<<<dim3(EMBED/128, NTOK/128), 256>>>(x, Wq, bq, qb, NTOK, EMBED, EMBED);
    // 2) kv = x @ Wkv^T + bkv  [4096, 1024]
    gemm_kernel<<<dim3(KVDIM/128, NTOK/128), 256>>>(x, Wkv, bkv, kvb, NTOK, KVDIM, EMBED);
    // 3) RoPE on q and k
    {
        int total = NTOK*NHEADS*64 + NTOK*NKV*64;
        rope_kernel<<<(total + 255)/256, 256>>>(qb, kvb);
    }
    // 4) flash attention -> g_o
    attn_kernel<<<dim3(SEQ/64, NHEADS, BATCH), 256, ATTN_SMEM>>>();
    // 5) out = o @ Wo^T
    gemm_kernel<<<dim3(EMBED/128, NTOK/128), 256>>>(ob, Wo, nullptr, out, NTOK, EMBED, EMBED);
}

// round 4
// speedup vs baseline: 1.2892x; 1.2892x over previous
#include <cuda_runtime.h>
#include <math.h>

#define EMBED   2048
#define NHEADS  16
#define NKV     4
#define HDIM    128
#define BATCH   2
#define SEQ     2048
#define NTOK    (BATCH*SEQ)      // 4096
#define KVDIM   1024             // k(512) + v(512)

// Scratch (device globals: allowed; no runtime allocation)
__device__ float g_q [NTOK * EMBED];   // [tok, h*128+d]
__device__ float g_kv[NTOK * KVDIM];   // [tok, (k: kvh*128+d) | 512 + (v: kvh*128+d)]
__device__ float g_o [NTOK * EMBED];   // attention output per token

// ---------------------------------------------------------------------------
// GEMM: C[M,N] = A[M,K] @ W[N,K]^T (+bias).  Both operands K-major (row-major).
// 128x128 block, BK=16, 256 threads, 8x8 per-thread register tile.
// ---------------------------------------------------------------------------
__global__ __launch_bounds__(256) void gemm_kernel(
    const float* __restrict__ A, const float* __restrict__ W,
    const float* __restrict__ bias, float* __restrict__ C,
    int M, int N, int K)
{
    __shared__ float As[16][132];   // [k][m], pad->float4-aligned rows
    __shared__ float Bs[16][132];   // [k][n]

    const int bm  = blockIdx.y * 128;
    const int bn  = blockIdx.x * 128;
    const int tid = threadIdx.x;
    const int tx  = tid & 15, ty = tid >> 4;
    const int row0 = ty * 8, col0 = tx * 8;

    float acc[8][8];
#pragma unroll
    for (int u = 0; u < 8; u++)
#pragma unroll
        for (int v = 0; v < 8; v++) acc[u][v] = 0.f;

    for (int kb = 0; kb < K; kb += 16) {
        // Load A & W tiles (128x16 each = 512 float4; 2 per thread)
#pragma unroll
        for (int p = 0; p < 2; p++) {
            int f  = tid + p * 256;
            int r  = f >> 2;      // 0..127
            int k4 = f & 3;       // 0..3
            float4 av = *(const float4*)(A + (size_t)(bm + r) * K + kb + k4 * 4);
            As[k4*4+0][r] = av.x; As[k4*4+1][r] = av.y;
            As[k4*4+2][r] = av.z; As[k4*4+3][r] = av.w;
            float4 bv = *(const float4*)(W + (size_t)(bn + r) * K + kb + k4 * 4);
            Bs[k4*4+0][r] = bv.x; Bs[k4*4+1][r] = bv.y;
            Bs[k4*4+2][r] = bv.z; Bs[k4*4+3][r] = bv.w;
        }
        __syncthreads();

#pragma unroll
        for (int kk = 0; kk < 16; kk++) {
            float4 a0 = *(const float4*)&As[kk][row0];
            float4 a1 = *(const float4*)&As[kk][row0 + 4];
            float4 b0 = *(const float4*)&Bs[kk][col0];
            float4 b1 = *(const float4*)&Bs[kk][col0 + 4];
            float a[8] = {a0.x,a0.y,a0.z,a0.w,a1.x,a1.y,a1.z,a1.w};
            float b[8] = {b0.x,b0.y,b0.z,b0.w,b1.x,b1.y,b1.z,b1.w};
#pragma unroll
            for (int u = 0; u < 8; u++)
#pragma unroll
                for (int v = 0; v < 8; v++) acc[u][v] += a[u] * b[v];
        }
        __syncthreads();
    }

    float bb[8];
#pragma unroll
    for (int v = 0; v < 8; v++) bb[v] = bias ? bias[bn + col0 + v] : 0.f;

#pragma unroll
    for (int u = 0; u < 8; u++) {
        int r = bm + row0 + u;
        float4 o0, o1;
        o0.x = acc[u][0] + bb[0]; o0.y = acc[u][1] + bb[1];
        o0.z = acc[u][2] + bb[2]; o0.w = acc[u][3] + bb[3];
        o1.x = acc[u][4] + bb[4]; o1.y = acc[u][5] + bb[5];
        o1.z = acc[u][6] + bb[6]; o1.w = acc[u][7] + bb[7];
        *(float4*)(C + (size_t)r * N + bn + col0)     = o0;
        *(float4*)(C + (size_t)r * N + bn + col0 + 4) = o1;
    }
}

// ---------------------------------------------------------------------------
// RoPE (in-place on g_q and k-half of g_kv). One thread per (token, head, i<64)
// ---------------------------------------------------------------------------
__global__ void rope_kernel(float* __restrict__ q, float* __restrict__ kv)
{
    const int QTOT = NTOK * NHEADS * 64;
    const int KTOT = NTOK * NKV * 64;
    int idx = blockIdx.x * blockDim.x + threadIdx.x;
    if (idx >= QTOT + KTOT) return;

    float* p0;
    int i, s;
    if (idx < QTOT) {
        i = idx & 63;
        int h = (idx >> 6) & 15;
        int t = idx >> 10;           // /(64*16)
        s = t & (SEQ - 1);
        p0 = q + (size_t)t * EMBED + h * HDIM + i;
    } else {
        int j = idx - QTOT;
        i = j & 63;
        int kvh = (j >> 6) & 3;
        int t = j >> 8;              // /(64*4)
        s = t & (SEQ - 1);
        p0 = kv + (size_t)t * KVDIM + kvh * HDIM + i;   // k occupies cols [0,512)
    }
    float freq = powf(10000.0f, -(float)(2 * i) * (1.0f / 128.0f));
    float ang  = (float)s * freq;
    float sn, cs;
    sincosf(ang, &sn, &cs);
    float x1 = p0[0], x2 = p0[64];
    p0[0]  = x1 * cs - x2 * sn;
    p0[64] = x2 * cs + x1 * sn;
}

// ---------------------------------------------------------------------------
// Flash attention: per block = (64 q rows, head, batch), online softmax over
// 64-wide kv tiles. 256 threads. Dynamic smem ~118KB.
// ---------------------------------------------------------------------------
#define QS_LD 68   // padded leading dim for transposed Q/K tiles
#define PS_LD 68

__global__ __launch_bounds__(256) void attn_kernel()
{
    extern __shared__ float sm[];
    float* Qs = sm;                      // [128][68] k-major
    float* Ks = Qs + 128 * QS_LD;        // [128][68] k-major
    float* Vs = Ks + 128 * QS_LD;        // [64][128] natural
    float* Ps = Vs + 64 * 128;           // [64][68]
    float* m_s    = Ps + 64 * PS_LD;     // [64]
    float* l_s    = m_s + 64;            // [64]
    float* corr_s = l_s + 64;            // [64]

    const int q0  = blockIdx.x * 64;
    const int h   = blockIdx.y;
    const int b   = blockIdx.z;
    const int kvh = h >> 2;
    const int tid = threadIdx.x;
    const int tx  = tid & 15, ty = tid >> 4;
    const int r0 = ty * 4;     // 4 q-rows per thread
    const int c0 = tx * 4;     // 4 score-cols per thread
    const int d0 = tx * 8;     // 8 output-dims per thread
    const float scale = 0.08838834764831845f;  // 1/sqrt(128)

    // Load Q tile transposed
    for (int e = tid; e < 64 * 128; e += 256) {
        int r = e >> 7, k = e & 127;
        Qs[k * QS_LD + r] = g_q[(size_t)(b * SEQ + q0 + r) * EMBED + h * HDIM + k];
    }
    if (tid < 64) { m_s[tid] = -INFINITY; l_s[tid] = 0.f; }

    float o_acc[4][8];
#pragma unroll
    for (int ri = 0; ri < 4; ri++)
#pragma unroll
        for (int u = 0; u < 8; u++) o_acc[ri][u] = 0.f;

    __syncthreads();

    for (int kt = 0; kt < SEQ / 64; kt++) {
        int kv0 = kt * 64;
        // Load K (transposed) + V tiles
        for (int e = tid; e < 64 * 128; e += 256) {
            int j = e >> 7, k = e & 127;
            size_t row = (size_t)(b * SEQ + kv0 + j) * KVDIM;
            Ks[k * QS_LD + j] = g_kv[row + kvh * HDIM + k];
            Vs[j * 128 + k]   = g_kv[row + 512 + kvh * HDIM + k];
        }
        __syncthreads();

        // S = scale * Q @ K^T   (each thread 4x4)
        float s_acc[4][4];
#pragma unroll
        for (int ri = 0; ri < 4; ri++)
#pragma unroll
            for (int ci = 0; ci < 4; ci++) s_acc[ri][ci] = 0.f;

#pragma unroll 8
        for (int k = 0; k < 128; k++) {
            float4 qa = *(const float4*)&Qs[k * QS_LD + r0];
            float4 kb = *(const float4*)&Ks[k * QS_LD + c0];
            float a[4] = {qa.x, qa.y, qa.z, qa.w};
            float bq[4] = {kb.x, kb.y, kb.z, kb.w};
#pragma unroll
            for (int ri = 0; ri < 4; ri++)
#pragma unroll
                for (int ci = 0; ci < 4; ci++) s_acc[ri][ci] += a[ri] * bq[ci];
        }
#pragma unroll
        for (int ri = 0; ri < 4; ri++) {
            float4 w;
            w.x = s_acc[ri][0] * scale; w.y = s_acc[ri][1] * scale;
            w.z = s_acc[ri][2] * scale; w.w = s_acc[ri][3] * scale;
            *(float4*)&Ps[(r0 + ri) * PS_LD + c0] = w;
        }
        __syncthreads();

        // Online softmax, one thread per row
        if (tid < 64) {
            int r = tid;
            float mold = m_s[r];
            float rmax = -INFINITY;
            for (int j = 0; j < 64; j++) rmax = fmaxf(rmax, Ps[r * PS_LD + j]);
            float mnew = fmaxf(mold, rmax);
            float corr = expf(mold - mnew);   // 0 on first tile (mold=-inf)
            float sum = 0.f;
            for (int j = 0; j < 64; j++) {
                float p = expf(Ps[r * PS_LD + j] - mnew);
                Ps[r * PS_LD + j] = p;
                sum += p;
            }
            l_s[r] = l_s[r] * corr + sum;
            m_s[r] = mnew;
            corr_s[r] = corr;
        }
        __syncthreads();

        // Rescale accumulators, then O += P @ V
        float cr[4];
#pragma unroll
        for (int ri = 0; ri < 4; ri++) {
            cr[ri] = corr_s[r0 + ri];
#pragma unroll
            for (int u = 0; u < 8; u++) o_acc[ri][u] *= cr[ri];
        }
#pragma unroll 4
        for (int j = 0; j < 64; j++) {
            float4 v0 = *(const float4*)&Vs[j * 128 + d0];
            float4 v1 = *(const float4*)&Vs[j * 128 + d0 + 4];
#pragma unroll
            for (int ri = 0; ri < 4; ri++) {
                float p = Ps[(r0 + ri) * PS_LD + j];
                o_acc[ri][0] += p * v0.x; o_acc[ri][1] += p * v0.y;
                o_acc[ri][2] += p * v0.z; o_acc[ri][3] += p * v0.w;
                o_acc[ri][4] += p * v1.x; o_acc[ri][5] += p * v1.y;
                o_acc[ri][6] += p * v1.z; o_acc[ri][7] += p * v1.w;
            }
        }
        __syncthreads();
    }

    // Normalize and write out
#pragma unroll
    for (int ri = 0; ri < 4; ri++) {
        float inv = 1.0f / l_s[r0 + ri];
        float4 o0, o1;
        o0.x = o_acc[ri][0] * inv; o0.y = o_acc[ri][1] * inv;
        o0.z = o_acc[ri][2] * inv; o0.w = o_acc[ri][3] * inv;
        o1.x = o_acc[ri][4] * inv; o1.y = o_acc[ri][5] * inv;
        o1.z = o_acc[ri][6] * inv; o1.w = o_acc[ri][7] * inv;
        size_t base = (size_t)(b * SEQ + q0 + r0 + ri) * EMBED + h * HDIM + d0;
        *(float4*)&g_o[base]     = o0;
        *(float4*)&g_o[base + 4] = o1;
    }
}

// ---------------------------------------------------------------------------
extern "C" void kernel_launch(void* const* d_in, const int* in_sizes, int n_in,
                              void* d_out, int out_size)
{
    const float* x   = (const float*)d_in[0];
    const float* Wq  = (const float*)d_in[1];
    const float* bq  = (const float*)d_in[2];
    const float* Wkv = (const float*)d_in[3];
    const float* bkv = (const float*)d_in[4];
    const float* Wo  = (const float*)d_in[5];
    float* out = (float*)d_out;

    float *qb, *kvb, *ob;
    cudaGetSymbolAddress((void**)&qb,  g_q);
    cudaGetSymbolAddress((void**)&kvb, g_kv);
    cudaGetSymbolAddress((void**)&ob,  g_o);

    const int ATTN_SMEM = (128*QS_LD*2 + 64*128 + 64*PS_LD + 192) * (int)sizeof(float);
    cudaFuncSetAttribute(attn_kernel, cudaFuncAttributeMaxDynamicSharedMemorySize, ATTN_SMEM);

    // 1) q = x @ Wq^T + bq     [4096, 2048]
    gemm_kernel<<<dim3(EMBED/128, NTOK/128), 256>>>(x, Wq, bq, qb, NTOK, EMBED, EMBED);
    // 2) kv = x @ Wkv^T + bkv  [4096, 1024]
    gemm_kernel<<<dim3(KVDIM/128, NTOK/128), 256>>>(x, Wkv, bkv, kvb, NTOK, KVDIM, EMBED);
    // 3) RoPE on q and k
    {
        int total = NTOK*NHEADS*64 + NTOK*NKV*64;
        rope_kernel<<<(total + 255)/256, 256>>>(qb, kvb);
    }
    // 4) flash attention -> g_o
    attn_kernel<<<dim3(SEQ/64, NHEADS, BATCH), 256, ATTN_SMEM>>>();
    // 5) out = o @ Wo^T
    gemm_kernel<<<dim3(EMBED/128, NTOK/128), 256>>>(ob, Wo, nullptr, out, NTOK, EMBED, EMBED);
}

// round 5
// speedup vs baseline: 3.4809x; 2.7000x over previous
#include <cuda_runtime.h>
#include <math.h>
#include <stdint.h>

#define EMBED   2048
#define NHEADS  16
#define NKV     4
#define HDIM    128
#define BATCH   2
#define SEQ     2048
#define NTOK    (BATCH*SEQ)      // 4096
#define KVDIM   1024             // k(512) + v(512)

// Scratch (device globals: allowed; no runtime allocation)
__device__ float g_q [NTOK * EMBED];
__device__ float g_kv[NTOK * KVDIM];
__device__ float g_o [NTOK * EMBED];

// ---------------------------------------------------------------------------
// TF32 helpers
// ---------------------------------------------------------------------------
__device__ __forceinline__ float f2tf(float x) {
    uint32_t u;
    asm("cvt.rna.tf32.f32 %0, %1;" : "=r"(u) : "f"(x));
    return __uint_as_float(u);
}

// D += A@B : m16n8k8 tf32, A row-major frag (4 regs), B col-major frag (2 regs)
__device__ __forceinline__ void mma8(float c[4], const uint32_t a[4], const uint32_t b[2]) {
    asm volatile(
        "mma.sync.aligned.m16n8k8.row.col.f32.tf32.tf32.f32 "
        "{%0,%1,%2,%3},{%4,%5,%6,%7},{%8,%9},{%0,%1,%2,%3};"
        : "+f"(c[0]), "+f"(c[1]), "+f"(c[2]), "+f"(c[3])
        : "r"(a[0]), "r"(a[1]), "r"(a[2]), "r"(a[3]), "r"(b[0]), "r"(b[1]));
}

// ---------------------------------------------------------------------------
// GEMM: C[M,N] = A[M,K] @ W[N,K]^T (+bias), tf32 tensor-core version.
// 128x128 tile, BK=32, 256 threads / 8 warps. Warp = 32x64 sub-tile.
// Double-buffered smem, register-staged global loads.
// ---------------------------------------------------------------------------
#define GLD 36   // smem leading dim: (4m+k) distinct mod 32 -> conflict-free frags

__global__ __launch_bounds__(256) void gemm_tf32(
    const float* __restrict__ A, const float* __restrict__ W,
    const float* __restrict__ bias, float* __restrict__ C,
    int M, int N, int K)
{
    extern __shared__ float sm[];
    float* As = sm;                      // 2 x [128][GLD]
    float* Bs = sm + 2 * 128 * GLD;      // 2 x [128][GLD]

    const int bm   = blockIdx.y * 128;
    const int bn   = blockIdx.x * 128;
    const int tid  = threadIdx.x;
    const int lane = tid & 31;
    const int w    = tid >> 5;
    const int mw   = w & 3;      // row block of 32
    const int nw   = w >> 2;     // col block of 64
    const int lr   = lane >> 2;  // 0..7
    const int lc   = lane & 3;   // 0..3

    float acc[2][8][4];
#pragma unroll
    for (int mi = 0; mi < 2; mi++)
#pragma unroll
        for (int ni = 0; ni < 8; ni++)
#pragma unroll
            for (int c = 0; c < 4; c++) acc[mi][ni][c] = 0.f;

    const int NT = K / 32;
    float4 ra[4], rb[4];

    // stage tile t into registers
    auto stage = [&](int t) {
        int kb = t * 32;
#pragma unroll
        for (int i = 0; i < 4; i++) {
            int slot = tid + i * 256;        // 0..1023
            int r = slot >> 3, c4 = slot & 7;
            ra[i] = *(const float4*)(A + (size_t)(bm + r) * K + kb + c4 * 4);
            rb[i] = *(const float4*)(W + (size_t)(bn + r) * K + kb + c4 * 4);
        }
    };
    // commit registers into smem buffer buf (with tf32 rounding)
    auto commit = [&](int buf) {
        float* Ab = As + buf * 128 * GLD;
        float* Bb = Bs + buf * 128 * GLD;
#pragma unroll
        for (int i = 0; i < 4; i++) {
            int slot = tid + i * 256;
            int r = slot >> 3, c = (slot & 7) * 4;
            float* pa = Ab + r * GLD + c;
            pa[0] = f2tf(ra[i].x); pa[1] = f2tf(ra[i].y);
            pa[2] = f2tf(ra[i].z); pa[3] = f2tf(ra[i].w);
            float* pb = Bb + r * GLD + c;
            pb[0] = f2tf(rb[i].x); pb[1] = f2tf(rb[i].y);
            pb[2] = f2tf(rb[i].z); pb[3] = f2tf(rb[i].w);
        }
    };

    stage(0);
    commit(0);
    __syncthreads();

    for (int t = 0; t < NT; t++) {
        if (t + 1 < NT) stage(t + 1);   // gmem loads in flight during compute

        const float* Ab = As + (t & 1) * 128 * GLD;
        const float* Bb = Bs + (t & 1) * 128 * GLD;
#pragma unroll
        for (int ks = 0; ks < 4; ks++) {
            int k0 = ks * 8;
            uint32_t af[2][4];
#pragma unroll
            for (int mi = 0; mi < 2; mi++) {
                int m  = mw * 32 + mi * 16 + lr;
                int kk = k0 + lc;
                af[mi][0] = __float_as_uint(Ab[m * GLD + kk]);
                af[mi][1] = __float_as_uint(Ab[(m + 8) * GLD + kk]);
                af[mi][2] = __float_as_uint(Ab[m * GLD + kk + 4]);
                af[mi][3] = __float_as_uint(Ab[(m + 8) * GLD + kk + 4]);
            }
#pragma unroll
            for (int ni = 0; ni < 8; ni++) {
                int n  = nw * 64 + ni * 8 + lr;
                int kk = k0 + lc;
                uint32_t bf[2];
                bf[0] = __float_as_uint(Bb[n * GLD + kk]);
                bf[1] = __float_as_uint(Bb[n * GLD + kk + 4]);
                mma8(acc[0][ni], af[0], bf);
                mma8(acc[1][ni], af[1], bf);
            }
        }
        __syncthreads();
        if (t + 1 < NT) {
            commit((t + 1) & 1);
            __syncthreads();
        }
    }

    // Epilogue: bias + store (float2 per c-pair)
#pragma unroll
    for (int mi = 0; mi < 2; mi++) {
        int r = bm + mw * 32 + mi * 16 + lr;
#pragma unroll
        for (int ni = 0; ni < 8; ni++) {
            int cc = bn + nw * 64 + ni * 8 + 2 * lc;
            float b0 = bias ? bias[cc] : 0.f;
            float b1 = bias ? bias[cc + 1] : 0.f;
            float2 o0 = make_float2(acc[mi][ni][0] + b0, acc[mi][ni][1] + b1);
            float2 o1 = make_float2(acc[mi][ni][2] + b0, acc[mi][ni][3] + b1);
            *(float2*)(C + (size_t)r * N + cc)       = o0;
            *(float2*)(C + (size_t)(r + 8) * N + cc) = o1;
        }
    }
}

// ---------------------------------------------------------------------------
// RoPE (in-place on g_q and k-half of g_kv)
// ---------------------------------------------------------------------------
__global__ void rope_kernel(float* __restrict__ q, float* __restrict__ kv)
{
    const int QTOT = NTOK * NHEADS * 64;
    const int KTOT = NTOK * NKV * 64;
    int idx = blockIdx.x * blockDim.x + threadIdx.x;
    if (idx >= QTOT + KTOT) return;

    float* p0;
    int i, s;
    if (idx < QTOT) {
        i = idx & 63;
        int h = (idx >> 6) & 15;
        int t = idx >> 10;
        s = t & (SEQ - 1);
        p0 = q + (size_t)t * EMBED + h * HDIM + i;
    } else {
        int j = idx - QTOT;
        i = j & 63;
        int kvh = (j >> 6) & 3;
        int t = j >> 8;
        s = t & (SEQ - 1);
        p0 = kv + (size_t)t * KVDIM + kvh * HDIM + i;
    }
    float freq = powf(10000.0f, -(float)(2 * i) * (1.0f / 128.0f));
    float ang  = (float)s * freq;
    float sn, cs;
    sincosf(ang, &sn, &cs);
    float x1 = p0[0], x2 = p0[64];
    p0[0]  = x1 * cs - x2 * sn;
    p0[64] = x2 * cs + x1 * sn;
}

// ---------------------------------------------------------------------------
// Flash attention, tf32 MMA for QK^T and PV.
// Block = (64 q rows, head, batch), 8 warps / 256 threads.
// ---------------------------------------------------------------------------
#define LDQ 132   // Qs/Ks/Vs leading dim (conflict-free frag LDS)
#define LDP 68    // Ps leading dim

__global__ __launch_bounds__(256) void attn_kernel()
{
    extern __shared__ float sm[];
    float* Qs = sm;                       // [64][LDQ]  q rows x dim (A operand)
    float* Ks = Qs + 64 * LDQ;            // [64][LDQ]  kv rows x dim (B operand)
    float* Vs = Ks + 64 * LDQ;            // [64][LDQ]  kv rows x dim (B op, k=j,n=d)
    float* Ps = Vs + 64 * LDQ;            // [64][LDP]  scores / probs
    float* corr_s = Ps + 64 * LDP;        // [64]
    float* l_s    = corr_s + 64;          // [64]

    const int q0   = blockIdx.x * 64;
    const int h    = blockIdx.y;
    const int b    = blockIdx.z;
    const int kvh  = h >> 2;
    const int tid  = threadIdx.x;
    const int lane = tid & 31;
    const int w    = tid >> 5;
    const int mw   = w & 3;     // 16-row strip of S/O
    const int nw2  = w >> 2;    // col half
    const int lr   = lane >> 2;
    const int lc   = lane & 3;
    const float scale = 0.08838834764831845f;   // 1/sqrt(128)

    // Load Q tile (rounded to tf32)
#pragma unroll
    for (int i = 0; i < 8; i++) {
        int slot = tid + i * 256;          // 0..2047
        int r = slot >> 5, d = (slot & 31) * 4;
        float4 qv = *(const float4*)(g_q + (size_t)(b * SEQ + q0 + r) * EMBED + h * HDIM + d);
        float* p = Qs + r * LDQ + d;
        p[0] = f2tf(qv.x); p[1] = f2tf(qv.y); p[2] = f2tf(qv.z); p[3] = f2tf(qv.w);
    }

    // Per-warp softmax state: this warp owns rows w*8 .. w*8+7 (replicated per lane)
    float m_i[8], l_i[8];
#pragma unroll
    for (int i = 0; i < 8; i++) { m_i[i] = -INFINITY; l_i[i] = 0.f; }

    float ofr[8][4];   // O accumulators: rows 16*mw, cols 64*nw2 + ni*8
#pragma unroll
    for (int ni = 0; ni < 8; ni++)
#pragma unroll
        for (int c = 0; c < 4; c++) ofr[ni][c] = 0.f;

    __syncthreads();

    for (int kt = 0; kt < SEQ / 64; kt++) {
        int kv0 = kt * 64;
        // Load K, V tiles
#pragma unroll
        for (int i = 0; i < 8; i++) {
            int slot = tid + i * 256;
            int r = slot >> 5, d = (slot & 31) * 4;
            size_t row = (size_t)(b * SEQ + kv0 + r) * KVDIM;
            float4 kv4 = *(const float4*)(g_kv + row + kvh * HDIM + d);
            float4 vv4 = *(const float4*)(g_kv + row + 512 + kvh * HDIM + d);
            float* pk = Ks + r * LDQ + d;
            pk[0] = f2tf(kv4.x); pk[1] = f2tf(kv4.y); pk[2] = f2tf(kv4.z); pk[3] = f2tf(kv4.w);
            float* pv = Vs + r * LDQ + d;
            pv[0] = f2tf(vv4.x); pv[1] = f2tf(vv4.y); pv[2] = f2tf(vv4.z); pv[3] = f2tf(vv4.w);
        }
        __syncthreads();

        // S = Q @ K^T  (warp: 16 rows x 32 cols, 4 n-frags)
        float sfr[4][4];
#pragma unroll
        for (int ni = 0; ni < 4; ni++)
#pragma unroll
            for (int c = 0; c < 4; c++) sfr[ni][c] = 0.f;

#pragma unroll
        for (int ks = 0; ks < 16; ks++) {
            int k0 = ks * 8;
            int m  = mw * 16 + lr;
            int kk = k0 + lc;
            uint32_t af[4];
            af[0] = __float_as_uint(Qs[m * LDQ + kk]);
            af[1] = __float_as_uint(Qs[(m + 8) * LDQ + kk]);
            af[2] = __float_as_uint(Qs[m * LDQ + kk + 4]);
            af[3] = __float_as_uint(Qs[(m + 8) * LDQ + kk + 4]);
#pragma unroll
            for (int ni = 0; ni < 4; ni++) {
                int n = nw2 * 32 + ni * 8 + lr;
                uint32_t bf[2];
                bf[0] = __float_as_uint(Ks[n * LDQ + kk]);
                bf[1] = __float_as_uint(Ks[n * LDQ + kk + 4]);
                mma8(sfr[ni], af, bf);
            }
        }
        // scale + write S fragments to Ps
#pragma unroll
        for (int ni = 0; ni < 4; ni++) {
            int row = mw * 16 + lr;
            int col = nw2 * 32 + ni * 8 + 2 * lc;
            *(float2*)&Ps[row * LDP + col]       = make_float2(sfr[ni][0] * scale, sfr[ni][1] * scale);
            *(float2*)&Ps[(row + 8) * LDP + col] = make_float2(sfr[ni][2] * scale, sfr[ni][3] * scale);
        }
        __syncthreads();

        // Online softmax: warp w handles rows w*8 .. w*8+7, full-warp shuffles
#pragma unroll
        for (int i = 0; i < 8; i++) {
            int r = w * 8 + i;
            float v0 = Ps[r * LDP + lane];
            float v1 = Ps[r * LDP + lane + 32];
            float rm = fmaxf(v0, v1);
#pragma unroll
            for (int o = 16; o > 0; o >>= 1)
                rm = fmaxf(rm, __shfl_xor_sync(0xffffffffu, rm, o));
            float mnew = fmaxf(m_i[i], rm);
            float corr = __expf(m_i[i] - mnew);
            float p0 = __expf(v0 - mnew);
            float p1 = __expf(v1 - mnew);
            Ps[r * LDP + lane]      = f2tf(p0);
            Ps[r * LDP + lane + 32] = f2tf(p1);
            float s = p0 + p1;
#pragma unroll
            for (int o = 16; o > 0; o >>= 1)
                s += __shfl_xor_sync(0xffffffffu, s, o);
            l_i[i] = l_i[i] * corr + s;
            m_i[i] = mnew;
            if (lane == 0) { corr_s[r] = corr; l_s[r] = l_i[i]; }
        }
        __syncthreads();

        // Rescale O accumulators, then O += P @ V
        float cr0 = corr_s[mw * 16 + lr];
        float cr1 = corr_s[mw * 16 + lr + 8];
#pragma unroll
        for (int ni = 0; ni < 8; ni++) {
            ofr[ni][0] *= cr0; ofr[ni][1] *= cr0;
            ofr[ni][2] *= cr1; ofr[ni][3] *= cr1;
        }
#pragma unroll
        for (int ks = 0; ks < 8; ks++) {
            int k0 = ks * 8;
            int m  = mw * 16 + lr;
            int kk = k0 + lc;
            uint32_t af[4];
            af[0] = __float_as_uint(Ps[m * LDP + kk]);
            af[1] = __float_as_uint(Ps[(m + 8) * LDP + kk]);
            af[2] = __float_as_uint(Ps[m * LDP + kk + 4]);
            af[3] = __float_as_uint(Ps[(m + 8) * LDP + kk + 4]);
#pragma unroll
            for (int ni = 0; ni < 8; ni++) {
                int n = nw2 * 64 + ni * 8 + lr;
                uint32_t bf[2];
                bf[0] = __float_as_uint(Vs[kk * LDQ + n]);        // V[k=j][n=d]
                bf[1] = __float_as_uint(Vs[(kk + 4) * LDQ + n]);
                mma8(ofr[ni], af, bf);
            }
        }
        __syncthreads();
    }

    // Normalize and write out
    float inv0 = 1.0f / l_s[mw * 16 + lr];
    float inv1 = 1.0f / l_s[mw * 16 + lr + 8];
    int row = b * SEQ + q0 + mw * 16 + lr;
#pragma unroll
    for (int ni = 0; ni < 8; ni++) {
        int d = nw2 * 64 + ni * 8 + 2 * lc;
        size_t base0 = (size_t)row * EMBED + h * HDIM + d;
        size_t base1 = (size_t)(row + 8) * EMBED + h * HDIM + d;
        *(float2*)(g_o + base0) = make_float2(ofr[ni][0] * inv0, ofr[ni][1] * inv0);
        *(float2*)(g_o + base1) = make_float2(ofr[ni][2] * inv1, ofr[ni][3] * inv1);
    }
}

// ---------------------------------------------------------------------------
extern "C" void kernel_launch(void* const* d_in, const int* in_sizes, int n_in,
                              void* d_out, int out_size)
{
    const float* x   = (const float*)d_in[0];
    const float* Wq  = (const float*)d_in[1];
    const float* bq  = (const float*)d_in[2];
    const float* Wkv = (const float*)d_in[3];
    const float* bkv = (const float*)d_in[4];
    const float* Wo  = (const float*)d_in[5];
    float* out = (float*)d_out;

    float *qb, *kvb, *ob;
    cudaGetSymbolAddress((void**)&qb,  g_q);
    cudaGetSymbolAddress((void**)&kvb, g_kv);
    cudaGetSymbolAddress((void**)&ob,  g_o);

    const int GEMM_SMEM = 4 * 128 * GLD * (int)sizeof(float);   // 73728 B
    const int ATTN_SMEM = (3 * 64 * LDQ + 64 * LDP + 128) * (int)sizeof(float);
    cudaFuncSetAttribute(gemm_tf32, cudaFuncAttributeMaxDynamicSharedMemorySize, GEMM_SMEM);
    cudaFuncSetAttribute(attn_kernel, cudaFuncAttributeMaxDynamicSharedMemorySize, ATTN_SMEM);

    // 1) q = x @ Wq^T + bq     [4096, 2048]
    gemm_tf32<<<dim3(EMBED/128, NTOK/128), 256, GEMM_SMEM>>>(x, Wq, bq, qb, NTOK, EMBED, EMBED);
    // 2) kv = x @ Wkv^T + bkv  [4096, 1024]
    gemm_tf32<<<dim3(KVDIM/128, NTOK/128), 256, GEMM_SMEM>>>(x, Wkv, bkv, kvb, NTOK, KVDIM, EMBED);
    // 3) RoPE on q and k
    {
        int total = NTOK*NHEADS*64 + NTOK*NKV*64;
        rope_kernel<<<(total + 255)/256, 256>>>(qb, kvb);
    }
    // 4) flash attention -> g_o
    attn_kernel<<<dim3(SEQ/64, NHEADS, BATCH), 256, ATTN_SMEM>>>();
    // 5) out = o @ Wo^T
    gemm_tf32<<<dim3(EMBED/128, NTOK/128), 256, GEMM_SMEM>>>(ob, Wo, nullptr, out, NTOK, EMBED, EMBED);
}

// round 7
// speedup vs baseline: 3.8649x; 1.1103x over previous
#include <cuda_runtime.h>
#include <math.h>
#include <stdint.h>

#define EMBED   2048
#define NHEADS  16
#define NKV     4
#define HDIM    128
#define BATCH   2
#define SEQ     2048
#define NTOK    (BATCH*SEQ)      // 4096
#define KVDIM   1024             // k(512) + v(512)

// Scratch (device globals)
__device__ float g_q [NTOK * EMBED];
__device__ float g_kv[NTOK * KVDIM];
__device__ float g_o [NTOK * EMBED];

// ---------------------------------------------------------------------------
// TF32 helpers
// ---------------------------------------------------------------------------
__device__ __forceinline__ float f2tf(float x) {
    uint32_t u;
    asm("cvt.rna.tf32.f32 %0, %1;" : "=r"(u) : "f"(x));
    return __uint_as_float(u);
}

__device__ __forceinline__ void mma8(float c[4], const uint32_t a[4], const uint32_t b[2]) {
    asm volatile(
        "mma.sync.aligned.m16n8k8.row.col.f32.tf32.tf32.f32 "
        "{%0,%1,%2,%3},{%4,%5,%6,%7},{%8,%9},{%0,%1,%2,%3};"
        : "+f"(c[0]), "+f"(c[1]), "+f"(c[2]), "+f"(c[3])
        : "r"(a[0]), "r"(a[1]), "r"(a[2]), "r"(a[3]), "r"(b[0]), "r"(b[1]));
}

// k-pair interleave: within each 8-wide k-oct, element k sits next to k+4.
__device__ __forceinline__ int pidx(int k) {
    return (k & ~7) + ((k & 3) * 2) + ((k >> 2) & 1);
}

// ---------------------------------------------------------------------------
// GEMM: C[M,N] = A[M,K] @ W[N,K]^T (+bias), tf32 MMA, paired smem layout.
// 128x128 tile, BK=32, 256 threads / 8 warps (32x64 per warp). Double-buffered.
// ---------------------------------------------------------------------------
#define GLD 40   // leading dim: 40%32==8 -> 2-way max on LDS.64 (free)

__global__ __launch_bounds__(256) void gemm_tf32(
    const float* __restrict__ A, const float* __restrict__ W,
    const float* __restrict__ bias, float* __restrict__ C,
    int M, int N, int K)
{
    extern __shared__ float sm[];
    float* As = sm;                      // 2 x [128][GLD]
    float* Bs = sm + 2 * 128 * GLD;      // 2 x [128][GLD]

    const int bm   = blockIdx.y * 128;
    const int bn   = blockIdx.x * 128;
    const int tid  = threadIdx.x;
    const int lane = tid & 31;
    const int w    = tid >> 5;
    const int mw   = w & 3;
    const int nw   = w >> 2;
    const int lr   = lane >> 2;
    const int lc   = lane & 3;

    float acc[2][8][4];
#pragma unroll
    for (int mi = 0; mi < 2; mi++)
#pragma unroll
        for (int ni = 0; ni < 8; ni++)
#pragma unroll
            for (int c = 0; c < 4; c++) acc[mi][ni][c] = 0.f;

    const int NT = K / 32;
    float4 ra[4], rb[4];

    auto stage = [&](int t) {
        int kb = t * 32;
#pragma unroll
        for (int i = 0; i < 4; i++) {
            int slot = tid + i * 256;
            int r = slot >> 3, c4 = slot & 7;
            ra[i] = *(const float4*)(A + (size_t)(bm + r) * K + kb + c4 * 4);
            rb[i] = *(const float4*)(W + (size_t)(bn + r) * K + kb + c4 * 4);
        }
    };
    auto commit = [&](int buf) {
        float* Ab = As + buf * 128 * GLD;
        float* Bb = Bs + buf * 128 * GLD;
#pragma unroll
        for (int i = 0; i < 4; i++) {
            int slot = tid + i * 256;
            int r = slot >> 3, c = (slot & 7) * 4;
            float* pa = Ab + r * GLD + (c & ~7) + ((c >> 2) & 1);
            pa[0] = f2tf(ra[i].x); pa[2] = f2tf(ra[i].y);
            pa[4] = f2tf(ra[i].z); pa[6] = f2tf(ra[i].w);
            float* pb = Bb + r * GLD + (c & ~7) + ((c >> 2) & 1);
            pb[0] = f2tf(rb[i].x); pb[2] = f2tf(rb[i].y);
            pb[4] = f2tf(rb[i].z); pb[6] = f2tf(rb[i].w);
        }
    };

    stage(0);
    commit(0);
    __syncthreads();

    for (int t = 0; t < NT; t++) {
        if (t + 1 < NT) stage(t + 1);

        const float* Ab = As + (t & 1) * 128 * GLD;
        const float* Bb = Bs + (t & 1) * 128 * GLD;
#pragma unroll
        for (int ks = 0; ks < 4; ks++) {
            int k0 = ks * 8;
            uint32_t af[2][4];
#pragma unroll
            for (int mi = 0; mi < 2; mi++) {
                int m = mw * 32 + mi * 16 + lr;
                float2 a0 = *(const float2*)&Ab[m * GLD + k0 + 2 * lc];
                float2 a1 = *(const float2*)&Ab[(m + 8) * GLD + k0 + 2 * lc];
                af[mi][0] = __float_as_uint(a0.x);
                af[mi][1] = __float_as_uint(a1.x);
                af[mi][2] = __float_as_uint(a0.y);
                af[mi][3] = __float_as_uint(a1.y);
            }
#pragma unroll
            for (int ni = 0; ni < 8; ni++) {
                int n = nw * 64 + ni * 8 + lr;
                float2 bv = *(const float2*)&Bb[n * GLD + k0 + 2 * lc];
                uint32_t bf[2] = { __float_as_uint(bv.x), __float_as_uint(bv.y) };
                mma8(acc[0][ni], af[0], bf);
                mma8(acc[1][ni], af[1], bf);
            }
        }
        __syncthreads();
        if (t + 1 < NT) {
            commit((t + 1) & 1);
            __syncthreads();
        }
    }

#pragma unroll
    for (int mi = 0; mi < 2; mi++) {
        int r = bm + mw * 32 + mi * 16 + lr;
#pragma unroll
        for (int ni = 0; ni < 8; ni++) {
            int cc = bn + nw * 64 + ni * 8 + 2 * lc;
            float b0 = bias ? bias[cc] : 0.f;
            float b1 = bias ? bias[cc + 1] : 0.f;
            *(float2*)(C + (size_t)r * N + cc)       = make_float2(acc[mi][ni][0] + b0, acc[mi][ni][1] + b1);
            *(float2*)(C + (size_t)(r + 8) * N + cc) = make_float2(acc[mi][ni][2] + b0, acc[mi][ni][3] + b1);
        }
    }
}

// ---------------------------------------------------------------------------
// RoPE (in-place on g_q and k-half of g_kv)
// ---------------------------------------------------------------------------
__global__ void rope_kernel(float* __restrict__ q, float* __restrict__ kv)
{
    const int QTOT = NTOK * NHEADS * 64;
    const int KTOT = NTOK * NKV * 64;
    int idx = blockIdx.x * blockDim.x + threadIdx.x;
    if (idx >= QTOT + KTOT) return;

    float* p0;
    int i, s;
    if (idx < QTOT) {
        i = idx & 63;
        int h = (idx >> 6) & 15;
        int t = idx >> 10;
        s = t & (SEQ - 1);
        p0 = q + (size_t)t * EMBED + h * HDIM + i;
    } else {
        int j = idx - QTOT;
        i = j & 63;
        int kvh = (j >> 6) & 3;
        int t = j >> 8;
        s = t & (SEQ - 1);
        p0 = kv + (size_t)t * KVDIM + kvh * HDIM + i;
    }
    float freq = powf(10000.0f, -(float)(2 * i) * (1.0f / 128.0f));
    float ang  = (float)s * freq;
    float sn, cs;
    sincosf(ang, &sn, &cs);
    float x1 = p0[0], x2 = p0[64];
    p0[0]  = x1 * cs - x2 * sn;
    p0[64] = x2 * cs + x1 * sn;
}

// ---------------------------------------------------------------------------
// Flash attention: 128 q-rows per CTA, 8 warps = 8 row-strips of 16 rows.
// Each warp computes its full 16x64 S tile and full 16x128 O tile, so the
// online softmax is entirely warp-local (quad shuffles only) and P smem is
// warp-private: 2 barriers per kv-tile.
// ---------------------------------------------------------------------------
#define LDK 136   // Q/K/V leading dim (paired for Q/K; V natural)
#define LDV 136
#define LDP 72

__global__ __launch_bounds__(256, 1) void attn_kernel()
{
    extern __shared__ float sm[];
    float* Qs = sm;                       // [128][LDK] paired
    float* Ks = Qs + 128 * LDK;           // [64][LDK]  paired
    float* Vs = Ks + 64 * LDK;            // [64][LDV]  natural [j][d]
    float* Ps = Vs + 64 * LDV;            // [128][LDP] paired (k = j), warp-private rows

    const int q0   = blockIdx.x * 128;
    const int h    = blockIdx.y;
    const int b    = blockIdx.z;
    const int kvh  = h >> 2;
    const int tid  = threadIdx.x;
    const int lane = tid & 31;
    const int w    = tid >> 5;           // row strip: rows [w*16, w*16+16)
    const int lr   = lane >> 2;
    const int lc   = lane & 3;
    const float scale = 0.08838834764831845f;   // 1/sqrt(128), folded into Q

    // Load Q tile (scaled, tf32, paired)
#pragma unroll
    for (int i = 0; i < 16; i++) {
        int slot = tid + i * 256;
        int r = slot >> 5, d = (slot & 31) * 4;
        float4 qv = *(const float4*)(g_q + (size_t)(b * SEQ + q0 + r) * EMBED + h * HDIM + d);
        float* p = Qs + r * LDK + (d & ~7) + ((d >> 2) & 1);
        p[0] = f2tf(qv.x * scale); p[2] = f2tf(qv.y * scale);
        p[4] = f2tf(qv.z * scale); p[6] = f2tf(qv.w * scale);
    }

    const int r0 = w * 16 + lr;
    const int r1 = r0 + 8;
    float m0 = -INFINITY, m1 = -INFINITY, l0 = 0.f, l1 = 0.f;
    float o_acc[16][4];
#pragma unroll
    for (int ni = 0; ni < 16; ni++)
#pragma unroll
        for (int c = 0; c < 4; c++) o_acc[ni][c] = 0.f;

    for (int kt = 0; kt < SEQ / 64; kt++) {
        int kv0 = kt * 64;
        __syncthreads();   // previous tile's K/V reads done (orders Q on kt=0)

        // Load K (paired) + V (natural) tiles
#pragma unroll
        for (int i = 0; i < 8; i++) {
            int slot = tid + i * 256;
            int r = slot >> 5, d = (slot & 31) * 4;
            size_t row = (size_t)(b * SEQ + kv0 + r) * KVDIM;
            float4 kv4 = *(const float4*)(g_kv + row + kvh * HDIM + d);
            float4 vv4 = *(const float4*)(g_kv + row + 512 + kvh * HDIM + d);
            float* pk = Ks + r * LDK + (d & ~7) + ((d >> 2) & 1);
            pk[0] = f2tf(kv4.x); pk[2] = f2tf(kv4.y);
            pk[4] = f2tf(kv4.z); pk[6] = f2tf(kv4.w);
            float4 vt;
            vt.x = f2tf(vv4.x); vt.y = f2tf(vv4.y);
            vt.z = f2tf(vv4.z); vt.w = f2tf(vv4.w);
            *(float4*)&Vs[r * LDV + d] = vt;
        }
        __syncthreads();

        // S = Q @ K^T : warp computes rows [w*16,+16) x all 64 cols
        float sfr[8][4];
#pragma unroll
        for (int ni = 0; ni < 8; ni++)
#pragma unroll
            for (int c = 0; c < 4; c++) sfr[ni][c] = 0.f;

#pragma unroll
        for (int ks = 0; ks < 16; ks++) {
            int k0 = ks * 8;
            float2 a0 = *(const float2*)&Qs[r0 * LDK + k0 + 2 * lc];
            float2 a1 = *(const float2*)&Qs[r1 * LDK + k0 + 2 * lc];
            uint32_t af[4] = { __float_as_uint(a0.x), __float_as_uint(a1.x),
                               __float_as_uint(a0.y), __float_as_uint(a1.y) };
#pragma unroll
            for (int ni = 0; ni < 8; ni++) {
                int n = ni * 8 + lr;
                float2 bv = *(const float2*)&Ks[n * LDK + k0 + 2 * lc];
                uint32_t bf[2] = { __float_as_uint(bv.x), __float_as_uint(bv.y) };
                mma8(sfr[ni], af, bf);
            }
        }

        // Warp-local online softmax (rows owned entirely by this warp)
        float mx0 = -INFINITY, mx1 = -INFINITY;
#pragma unroll
        for (int ni = 0; ni < 8; ni++) {
            mx0 = fmaxf(mx0, fmaxf(sfr[ni][0], sfr[ni][1]));
            mx1 = fmaxf(mx1, fmaxf(sfr[ni][2], sfr[ni][3]));
        }
        mx0 = fmaxf(mx0, __shfl_xor_sync(0xffffffffu, mx0, 1));
        mx0 = fmaxf(mx0, __shfl_xor_sync(0xffffffffu, mx0, 2));
        mx1 = fmaxf(mx1, __shfl_xor_sync(0xffffffffu, mx1, 1));
        mx1 = fmaxf(mx1, __shfl_xor_sync(0xffffffffu, mx1, 2));

        float mn0 = fmaxf(m0, mx0);
        float mn1 = fmaxf(m1, mx1);
        float corr0 = __expf(m0 - mn0);
        float corr1 = __expf(m1 - mn1);
        m0 = mn0; m1 = mn1;

        float s0 = 0.f, s1 = 0.f;
#pragma unroll
        for (int ni = 0; ni < 8; ni++) {
            int c0i = ni * 8 + 2 * lc;
            float p00 = __expf(sfr[ni][0] - mn0);
            float p01 = __expf(sfr[ni][1] - mn0);
            float p10 = __expf(sfr[ni][2] - mn1);
            float p11 = __expf(sfr[ni][3] - mn1);
            s0 += p00 + p01; s1 += p10 + p11;
            Ps[r0 * LDP + pidx(c0i)]     = f2tf(p00);
            Ps[r0 * LDP + pidx(c0i + 1)] = f2tf(p01);
            Ps[r1 * LDP + pidx(c0i)]     = f2tf(p10);
            Ps[r1 * LDP + pidx(c0i + 1)] = f2tf(p11);
        }
        s0 += __shfl_xor_sync(0xffffffffu, s0, 1);
        s0 += __shfl_xor_sync(0xffffffffu, s0, 2);
        s1 += __shfl_xor_sync(0xffffffffu, s1, 1);
        s1 += __shfl_xor_sync(0xffffffffu, s1, 2);
        l0 = l0 * corr0 + s0;
        l1 = l1 * corr1 + s1;

        // Rescale accumulators, O += P @ V (warp: 16 rows x all 128 dims).
        // Ps rows are warp-private; no barrier needed before reading them.
#pragma unroll
        for (int ni = 0; ni < 16; ni++) {
            o_acc[ni][0] *= corr0; o_acc[ni][1] *= corr0;
            o_acc[ni][2] *= corr1; o_acc[ni][3] *= corr1;
        }
#pragma unroll
        for (int ks = 0; ks < 8; ks++) {
            int k0 = ks * 8;
            float2 a0 = *(const float2*)&Ps[r0 * LDP + k0 + 2 * lc];
            float2 a1 = *(const float2*)&Ps[r1 * LDP + k0 + 2 * lc];
            uint32_t af[4] = { __float_as_uint(a0.x), __float_as_uint(a1.x),
                               __float_as_uint(a0.y), __float_as_uint(a1.y) };
#pragma unroll
            for (int ni = 0; ni < 16; ni++) {
                int n = ni * 8 + lr;
                uint32_t bf[2] = { __float_as_uint(Vs[(k0 + lc) * LDV + n]),
                                   __float_as_uint(Vs[(k0 + lc + 4) * LDV + n]) };
                mma8(o_acc[ni], af, bf);
            }
        }
    }

    // Normalize + write out
    float inv0 = 1.0f / l0;
    float inv1 = 1.0f / l1;
    int row = b * SEQ + q0 + r0;
#pragma unroll
    for (int ni = 0; ni < 16; ni++) {
        int d = ni * 8 + 2 * lc;
        size_t base0 = (size_t)row * EMBED + h * HDIM + d;
        size_t base1 = (size_t)(row + 8) * EMBED + h * HDIM + d;
        *(float2*)(g_o + base0) = make_float2(o_acc[ni][0] * inv0, o_acc[ni][1] * inv0);
        *(float2*)(g_o + base1) = make_float2(o_acc[ni][2] * inv1, o_acc[ni][3] * inv1);
    }
}

// ---------------------------------------------------------------------------
extern "C" void kernel_launch(void* const* d_in, const int* in_sizes, int n_in,
                              void* d_out, int out_size)
{
    const float* x   = (const float*)d_in[0];
    const float* Wq  = (const float*)d_in[1];
    const float* bq  = (const float*)d_in[2];
    const float* Wkv = (const float*)d_in[3];
    const float* bkv = (const float*)d_in[4];
    const float* Wo  = (const float*)d_in[5];
    float* out = (float*)d_out;

    float *qb, *kvb, *ob;
    cudaGetSymbolAddress((void**)&qb,  g_q);
    cudaGetSymbolAddress((void**)&kvb, g_kv);
    cudaGetSymbolAddress((void**)&ob,  g_o);

    const int GEMM_SMEM = 4 * 128 * GLD * (int)sizeof(float);   // 81920 B
    const int ATTN_SMEM = (128 * LDK + 64 * LDK + 64 * LDV + 128 * LDP) * (int)sizeof(float); // 176128 B
    cudaFuncSetAttribute(gemm_tf32,   cudaFuncAttributeMaxDynamicSharedMemorySize, GEMM_SMEM);
    cudaFuncSetAttribute(attn_kernel, cudaFuncAttributeMaxDynamicSharedMemorySize, ATTN_SMEM);

    // 1) q = x @ Wq^T + bq
    gemm_tf32<<<dim3(EMBED/128, NTOK/128), 256, GEMM_SMEM>>>(x, Wq, bq, qb, NTOK, EMBED, EMBED);
    // 2) kv = x @ Wkv^T + bkv
    gemm_tf32<<<dim3(KVDIM/128, NTOK/128), 256, GEMM_SMEM>>>(x, Wkv, bkv, kvb, NTOK, KVDIM, EMBED);
    // 3) RoPE
    {
        int total = NTOK*NHEADS*64 + NTOK*NKV*64;
        rope_kernel<<<(total + 255)/256, 256>>>(qb, kvb);
    }
    // 4) flash attention (128 q-rows per CTA)
    attn_kernel<<<dim3(SEQ/128, NHEADS, BATCH), 256, ATTN_SMEM>>>();
    // 5) out = o @ Wo^T
    gemm_tf32<<<dim3(EMBED/128, NTOK/128), 256, GEMM_SMEM>>>(ob, Wo, nullptr, out, NTOK, EMBED, EMBED);
}

// round 9
// speedup vs baseline: 10.8792x; 2.8149x over previous
#include <cuda_runtime.h>
#include <cuda_fp16.h>
#include <math.h>
#include <stdint.h>

#define EMBED   2048
#define NHEADS  16
#define NKV     4
#define HDIM    128
#define BATCH   2
#define SEQ     2048
#define NTOK    (BATCH*SEQ)      // 4096
#define KVDIM   1024             // k(512) + v(512)

// fp32 scratch
__device__ float  g_q [NTOK * EMBED];
__device__ float  g_kv[NTOK * KVDIM];
// fp16 scratch
__device__ __half g_xh  [NTOK * EMBED];
__device__ __half g_wqh [EMBED * EMBED];
__device__ __half g_wkvh[KVDIM * EMBED];
__device__ __half g_woh [EMBED * EMBED];
__device__ __half g_qh  [NTOK * EMBED];   // [b][h][s][d], pre-scaled
__device__ __half g_kh  [NTOK * 512];     // [b][kvh][s][d]
__device__ __half g_vh  [NTOK * 512];     // [b][kvh][s][d]
__device__ __half g_oh  [NTOK * EMBED];   // [tok][h*128+d]

// ---------------------------------------------------------------------------
// PTX helpers (baseline sm_80+ features only — no 'a'-suffix instructions)
// ---------------------------------------------------------------------------
__device__ __forceinline__ uint32_t smem_to_u32(const void* p) {
    uint32_t a;
    asm("{ .reg .u64 t; cvta.to.shared.u64 t, %1; cvt.u32.u64 %0, t; }" : "=r"(a) : "l"(p));
    return a;
}

__device__ __forceinline__ void mma16(float c[4], const uint32_t a[4], const uint32_t b[2]) {
    asm volatile(
        "mma.sync.aligned.m16n8k16.row.col.f32.f16.f16.f32 "
        "{%0,%1,%2,%3},{%4,%5,%6,%7},{%8,%9},{%0,%1,%2,%3};"
        : "+f"(c[0]), "+f"(c[1]), "+f"(c[2]), "+f"(c[3])
        : "r"(a[0]), "r"(a[1]), "r"(a[2]), "r"(a[3]), "r"(b[0]), "r"(b[1]));
}

__device__ __forceinline__ void ldsm4(uint32_t r[4], uint32_t addr) {
    asm volatile("ldmatrix.sync.aligned.m8n8.x4.shared.b16 {%0,%1,%2,%3}, [%4];"
        : "=r"(r[0]), "=r"(r[1]), "=r"(r[2]), "=r"(r[3]) : "r"(addr));
}

__device__ __forceinline__ void ldsm4t(uint32_t r[4], uint32_t addr) {
    asm volatile("ldmatrix.sync.aligned.m8n8.x4.trans.shared.b16 {%0,%1,%2,%3}, [%4];"
        : "=r"(r[0]), "=r"(r[1]), "=r"(r[2]), "=r"(r[3]) : "r"(addr));
}

__device__ __forceinline__ void cp16(uint32_t dst, const void* src) {
    asm volatile("cp.async.cg.shared.global [%0], [%1], 16;" :: "r"(dst), "l"(src));
}
#define CP_COMMIT() asm volatile("cp.async.commit_group;" ::: "memory")
#define CP_WAIT0()  asm volatile("cp.async.wait_group 0;" ::: "memory")
#define CP_WAIT1()  asm volatile("cp.async.wait_group 1;" ::: "memory")

// ---------------------------------------------------------------------------
// fp32 -> fp16 bulk convert (vectorized by 4)
// ---------------------------------------------------------------------------
__global__ void to_half(const float4* __restrict__ src, uint2* __restrict__ dst, int n4)
{
    int i = blockIdx.x * blockDim.x + threadIdx.x;
    if (i >= n4) return;
    float4 v = src[i];
    __half2 h0 = __floats2half2_rn(v.x, v.y);
    __half2 h1 = __floats2half2_rn(v.z, v.w);
    uint2 u;
    u.x = *(uint32_t*)&h0;
    u.y = *(uint32_t*)&h1;
    dst[i] = u;
}

// ---------------------------------------------------------------------------
// GEMM: C[M,N](fp32) = A[M,K](fp16) @ W[N,K]^T(fp16) + bias
// CTA 128x128, BK=64, 8 warps (32x64 each), cp.async double buffer, ldmatrix.
// smem row = 64 halves (128B) + 16B pad = 144B  (144 % 128 == 16 -> ldmatrix
// conflict-free). Buffer block = A(18432) + B(18432) = 36864 B, x2 = 73728 B.
// ---------------------------------------------------------------------------
__global__ __launch_bounds__(256, 2) void gemm_h(
    const __half* __restrict__ A, const __half* __restrict__ W,
    const float* __restrict__ bias, float* __restrict__ C,
    int M, int N, int K)
{
    extern __shared__ char smc[];
    const uint32_t sb = smem_to_u32(smc);

    const int bm   = blockIdx.y * 128;
    const int bn   = blockIdx.x * 128;
    const int tid  = threadIdx.x;
    const int lane = tid & 31;
    const int w    = tid >> 5;
    const int mw   = w & 3;
    const int nw   = w >> 2;
    const int lr   = lane >> 2;
    const int lc   = lane & 3;

    float acc[2][8][4];
#pragma unroll
    for (int mi = 0; mi < 2; mi++)
#pragma unroll
        for (int ni = 0; ni < 8; ni++)
#pragma unroll
            for (int c = 0; c < 4; c++) acc[mi][ni][c] = 0.f;

    const int NT = K / 64;

    auto issue = [&](int t) {
        const int buf = t & 1;
        const int kb  = t * 64;
        uint32_t abuf = sb + buf * 36864;
        uint32_t bbuf = abuf + 18432;
#pragma unroll
        for (int i = 0; i < 4; i++) {
            int slot = tid + i * 256;          // 0..1023
            int r = slot >> 3, c = slot & 7;   // row, 16B chunk
            cp16(abuf + r * 144 + c * 16, A + (size_t)(bm + r) * K + kb + c * 8);
            cp16(bbuf + r * 144 + c * 16, W + (size_t)(bn + r) * K + kb + c * 8);
        }
        CP_COMMIT();
    };

    // ldmatrix lane bases
    const uint32_t a_base = sb + (mw * 32 + (lane & 15)) * 144 + (lane >> 4) * 16;
    const uint32_t b_base = sb + 18432
        + (nw * 64 + ((lane >> 4) << 3) + (lane & 7)) * 144 + ((lane >> 3) & 1) * 16;

    issue(0);

    for (int t = 0; t < NT; t++) {
        if (t + 1 < NT) { issue(t + 1); CP_WAIT1(); } else { CP_WAIT0(); }
        __syncthreads();

        const uint32_t boff = (t & 1) * 36864;
#pragma unroll
        for (int ks = 0; ks < 4; ks++) {
            uint32_t af0[4], af1[4];
            ldsm4(af0, a_base + boff + ks * 32);
            ldsm4(af1, a_base + boff + 2304 + ks * 32);   // +16 rows
#pragma unroll
            for (int np = 0; np < 4; np++) {
                uint32_t bf[4];
                ldsm4(bf, b_base + boff + np * 2304 + ks * 32);
                mma16(acc[0][np * 2],     af0, bf);
                mma16(acc[0][np * 2 + 1], af0, bf + 2);
                mma16(acc[1][np * 2],     af1, bf);
                mma16(acc[1][np * 2 + 1], af1, bf + 2);
            }
        }
        __syncthreads();   // all reads of this buffer done before re-fill
    }

    // Epilogue
#pragma unroll
    for (int mi = 0; mi < 2; mi++) {
        int r = bm + mw * 32 + mi * 16 + lr;
#pragma unroll
        for (int ni = 0; ni < 8; ni++) {
            int cc = bn + nw * 64 + ni * 8 + 2 * lc;
            float b0 = bias ? bias[cc] : 0.f;
            float b1 = bias ? bias[cc + 1] : 0.f;
            *(float2*)(C + (size_t)r * N + cc)       = make_float2(acc[mi][ni][0] + b0, acc[mi][ni][1] + b1);
            *(float2*)(C + (size_t)(r + 8) * N + cc) = make_float2(acc[mi][ni][2] + b0, acc[mi][ni][3] + b1);
        }
    }
}

// ---------------------------------------------------------------------------
// RoPE + fp16 repack: g_q -> g_qh (scaled, [b][h][s][d]); k-half of g_kv ->
// g_kh; v-half -> g_vh (plain convert).
// ---------------------------------------------------------------------------
__global__ void rope_h()
{
    const int QTOT = NTOK * NHEADS * 64;   // rotation pairs
    const int KTOT = NTOK * NKV * 64;
    const int VTOT = NTOK * NKV * 128;     // plain elements
    const float scale = 0.08838834764831845f;  // 1/sqrt(128)

    int idx = blockIdx.x * blockDim.x + threadIdx.x;
    if (idx < QTOT) {
        int i = idx & 63;
        int h = (idx >> 6) & 15;
        int t = idx >> 10;
        int s = t & (SEQ - 1), b = t >> 11;
        float x1 = g_q[(size_t)t * EMBED + h * HDIM + i];
        float x2 = g_q[(size_t)t * EMBED + h * HDIM + i + 64];
        float freq = powf(10000.0f, -(float)(2 * i) * (1.0f / 128.0f));
        float sn, cs; sincosf((float)s * freq, &sn, &cs);
        size_t dst = ((size_t)(b * NHEADS + h) * SEQ + s) * HDIM + i;
        g_qh[dst]      = __float2half_rn((x1 * cs - x2 * sn) * scale);
        g_qh[dst + 64] = __float2half_rn((x2 * cs + x1 * sn) * scale);
    } else if (idx < QTOT + KTOT) {
        int j = idx - QTOT;
        int i = j & 63;
        int kvh = (j >> 6) & 3;
        int t = j >> 8;
        int s = t & (SEQ - 1), b = t >> 11;
        float x1 = g_kv[(size_t)t * KVDIM + kvh * HDIM + i];
        float x2 = g_kv[(size_t)t * KVDIM + kvh * HDIM + i + 64];
        float freq = powf(10000.0f, -(float)(2 * i) * (1.0f / 128.0f));
        float sn, cs; sincosf((float)s * freq, &sn, &cs);
        size_t dst = ((size_t)(b * NKV + kvh) * SEQ + s) * HDIM + i;
        g_kh[dst]      = __float2half_rn(x1 * cs - x2 * sn);
        g_kh[dst + 64] = __float2half_rn(x2 * cs + x1 * sn);
    } else if (idx < QTOT + KTOT + VTOT) {
        int j = idx - QTOT - KTOT;
        int d = j & 127;
        int rest = j >> 7;
        int kvh = rest & 3;
        int t = rest >> 2;
        int s = t & (SEQ - 1), b = t >> 11;
        g_vh[((size_t)(b * NKV + kvh) * SEQ + s) * HDIM + d] =
            __float2half_rn(g_kv[(size_t)t * KVDIM + 512 + kvh * HDIM + d]);
    }
}

// ---------------------------------------------------------------------------
// Flash attention fp16: 128 q-rows/CTA, 8 warps = 8 row-strips of 16.
// cp.async double-buffered K/V; ldmatrix for Q/K/P; ldmatrix.trans for V
// (no transpose pass). Warp-local online softmax. Writes g_oh fp16.
// smem: Qs[128][272B] | Ks 2x[64][272B] | Vs 2x[64][272B] | Ps[128][144B]
// ---------------------------------------------------------------------------
#define AT_QS 0
#define AT_KS 34816
#define AT_VS 69632
#define AT_PS 104448
#define AT_SMEM 122880

__global__ __launch_bounds__(256, 1) void attn_h()
{
    extern __shared__ char smc[];
    const uint32_t sb = smem_to_u32(smc);

    const int q0   = blockIdx.x * 128;
    const int h    = blockIdx.y;
    const int b    = blockIdx.z;
    const int kvh  = h >> 2;
    const int tid  = threadIdx.x;
    const int lane = tid & 31;
    const int w    = tid >> 5;
    const int lr   = lane >> 2;
    const int lc   = lane & 3;

    const __half* qsrc = g_qh + ((size_t)(b * NHEADS + h) * SEQ + q0) * HDIM;
    const __half* ksrc = g_kh + (size_t)(b * NKV + kvh) * SEQ * HDIM;
    const __half* vsrc = g_vh + (size_t)(b * NKV + kvh) * SEQ * HDIM;

    // Group 0: Q tile + KV tile 0
#pragma unroll
    for (int i = 0; i < 8; i++) {
        int slot = tid + i * 256;            // 0..2047
        int r = slot >> 4, c = slot & 15;
        cp16(sb + AT_QS + r * 272 + c * 16, qsrc + (size_t)r * HDIM + c * 8);
    }
#pragma unroll
    for (int i = 0; i < 4; i++) {
        int slot = tid + i * 256;            // 0..1023
        int r = slot >> 4, c = slot & 15;
        cp16(sb + AT_KS + r * 272 + c * 16, ksrc + (size_t)r * HDIM + c * 8);
        cp16(sb + AT_VS + r * 272 + c * 16, vsrc + (size_t)r * HDIM + c * 8);
    }
    CP_COMMIT();

    // ldmatrix lane bases
    const uint32_t q_base = sb + AT_QS + (w * 16 + (lane & 15)) * 272 + (lane >> 4) * 16;
    const uint32_t k_base = sb + AT_KS
        + (((lane >> 4) << 3) + (lane & 7)) * 272 + ((lane >> 3) & 1) * 16;
    const uint32_t v_base = sb + AT_VS + (lane & 15) * 272 + (lane >> 4) * 16;
    const uint32_t p_base = sb + AT_PS + (w * 16 + (lane & 15)) * 144 + (lane >> 4) * 16;

    const int r0 = w * 16 + lr;
    const int r1 = r0 + 8;
    float m0 = -INFINITY, m1 = -INFINITY, l0 = 0.f, l1 = 0.f;
    float o_acc[16][4];
#pragma unroll
    for (int ni = 0; ni < 16; ni++)
#pragma unroll
        for (int c = 0; c < 4; c++) o_acc[ni][c] = 0.f;

    const int NT = SEQ / 64;   // 32
    for (int kt = 0; kt < NT; kt++) {
        if (kt + 1 < NT) {
            const int buf = (kt + 1) & 1;
            const int kv0 = (kt + 1) * 64;
#pragma unroll
            for (int i = 0; i < 4; i++) {
                int slot = tid + i * 256;
                int r = slot >> 4, c = slot & 15;
                cp16(sb + AT_KS + buf * 17408 + r * 272 + c * 16,
                     ksrc + (size_t)(kv0 + r) * HDIM + c * 8);
                cp16(sb + AT_VS + buf * 17408 + r * 272 + c * 16,
                     vsrc + (size_t)(kv0 + r) * HDIM + c * 8);
            }
            CP_COMMIT();
            CP_WAIT1();
        } else {
            CP_WAIT0();
        }
        __syncthreads();

        const uint32_t kb = (kt & 1) * 17408;

        // S = Q @ K^T : warp rows [w*16,+16) x 64 kv cols
        float sfr[8][4];
#pragma unroll
        for (int ni = 0; ni < 8; ni++)
#pragma unroll
            for (int c = 0; c < 4; c++) sfr[ni][c] = 0.f;

#pragma unroll
        for (int ks = 0; ks < 8; ks++) {
            uint32_t af[4];
            ldsm4(af, q_base + ks * 32);
#pragma unroll
            for (int np = 0; np < 4; np++) {
                uint32_t bf[4];
                ldsm4(bf, k_base + kb + np * 4352 + ks * 32);
                mma16(sfr[np * 2],     af, bf);
                mma16(sfr[np * 2 + 1], af, bf + 2);
            }
        }

        // Warp-local online softmax
        float mx0 = -INFINITY, mx1 = -INFINITY;
#pragma unroll
        for (int ni = 0; ni < 8; ni++) {
            mx0 = fmaxf(mx0, fmaxf(sfr[ni][0], sfr[ni][1]));
            mx1 = fmaxf(mx1, fmaxf(sfr[ni][2], sfr[ni][3]));
        }
        mx0 = fmaxf(mx0, __shfl_xor_sync(0xffffffffu, mx0, 1));
        mx0 = fmaxf(mx0, __shfl_xor_sync(0xffffffffu, mx0, 2));
        mx1 = fmaxf(mx1, __shfl_xor_sync(0xffffffffu, mx1, 1));
        mx1 = fmaxf(mx1, __shfl_xor_sync(0xffffffffu, mx1, 2));

        float mn0 = fmaxf(m0, mx0);
        float mn1 = fmaxf(m1, mx1);
        float corr0 = __expf(m0 - mn0);
        float corr1 = __expf(m1 - mn1);
        m0 = mn0; m1 = mn1;

        float s0 = 0.f, s1 = 0.f;
#pragma unroll
        for (int ni = 0; ni < 8; ni++) {
            int cc = ni * 8 + 2 * lc;
            float p00 = __expf(sfr[ni][0] - mn0);
            float p01 = __expf(sfr[ni][1] - mn0);
            float p10 = __expf(sfr[ni][2] - mn1);
            float p11 = __expf(sfr[ni][3] - mn1);
            s0 += p00 + p01; s1 += p10 + p11;
            __half2 h0 = __floats2half2_rn(p00, p01);
            __half2 h1 = __floats2half2_rn(p10, p11);
            *(__half2*)(smc + AT_PS + r0 * 144 + cc * 2) = h0;
            *(__half2*)(smc + AT_PS + r1 * 144 + cc * 2) = h1;
        }
        s0 += __shfl_xor_sync(0xffffffffu, s0, 1);
        s0 += __shfl_xor_sync(0xffffffffu, s0, 2);
        s1 += __shfl_xor_sync(0xffffffffu, s1, 1);
        s1 += __shfl_xor_sync(0xffffffffu, s1, 2);
        l0 = l0 * corr0 + s0;
        l1 = l1 * corr1 + s1;
        __syncwarp();   // P rows are warp-private; make stores visible to warp

        // Rescale + O += P @ V
#pragma unroll
        for (int ni = 0; ni < 16; ni++) {
            o_acc[ni][0] *= corr0; o_acc[ni][1] *= corr0;
            o_acc[ni][2] *= corr1; o_acc[ni][3] *= corr1;
        }
#pragma unroll
        for (int ks = 0; ks < 4; ks++) {
            uint32_t af[4];
            ldsm4(af, p_base + ks * 32);
#pragma unroll
            for (int np = 0; np < 8; np++) {
                uint32_t bf[4];
                ldsm4t(bf, v_base + kb + ks * 4352 + np * 32);
                mma16(o_acc[np * 2],     af, bf);
                mma16(o_acc[np * 2 + 1], af, bf + 2);
            }
        }
        __syncthreads();   // done reading this K/V buffer
    }

    // Normalize + write g_oh (fp16, token-major for the Wo GEMM)
    float inv0 = 1.0f / l0;
    float inv1 = 1.0f / l1;
    int row = b * SEQ + q0 + r0;
#pragma unroll
    for (int ni = 0; ni < 16; ni++) {
        int d = ni * 8 + 2 * lc;
        __half2 h0 = __floats2half2_rn(o_acc[ni][0] * inv0, o_acc[ni][1] * inv0);
        __half2 h1 = __floats2half2_rn(o_acc[ni][2] * inv1, o_acc[ni][3] * inv1);
        *(__half2*)(g_oh + (size_t)row * EMBED + h * HDIM + d)       = h0;
        *(__half2*)(g_oh + (size_t)(row + 8) * EMBED + h * HDIM + d) = h1;
    }
}

// ---------------------------------------------------------------------------
extern "C" void kernel_launch(void* const* d_in, const int* in_sizes, int n_in,
                              void* d_out, int out_size)
{
    const float* x   = (const float*)d_in[0];
    const float* Wq  = (const float*)d_in[1];
    const float* bq  = (const float*)d_in[2];
    const float* Wkv = (const float*)d_in[3];
    const float* bkv = (const float*)d_in[4];
    const float* Wo  = (const float*)d_in[5];
    float* out = (float*)d_out;

    float *qb, *kvb;
    __half *xh, *wqh, *wkvh, *woh, *oh;
    cudaGetSymbolAddress((void**)&qb,   g_q);
    cudaGetSymbolAddress((void**)&kvb,  g_kv);
    cudaGetSymbolAddress((void**)&xh,   g_xh);
    cudaGetSymbolAddress((void**)&wqh,  g_wqh);
    cudaGetSymbolAddress((void**)&wkvh, g_wkvh);
    cudaGetSymbolAddress((void**)&woh,  g_woh);
    cudaGetSymbolAddress((void**)&oh,   g_oh);

    const int GEMM_SMEM = 73728;
    cudaFuncSetAttribute(gemm_h, cudaFuncAttributeMaxDynamicSharedMemorySize, GEMM_SMEM);
    cudaFuncSetAttribute(attn_h, cudaFuncAttributeMaxDynamicSharedMemorySize, AT_SMEM);

    // 0) fp32 -> fp16 conversions of x and weights
    {
        int n4;
        n4 = NTOK * EMBED / 4;
        to_half<<<(n4 + 255) / 256, 256>>>((const float4*)x,   (uint2*)xh,   n4);
        n4 = EMBED * EMBED / 4;
        to_half<<<(n4 + 255) / 256, 256>>>((const float4*)Wq,  (uint2*)wqh,  n4);
        n4 = KVDIM * EMBED / 4;
        to_half<<<(n4 + 255) / 256, 256>>>((const float4*)Wkv, (uint2*)wkvh, n4);
        n4 = EMBED * EMBED / 4;
        to_half<<<(n4 + 255) / 256, 256>>>((const float4*)Wo,  (uint2*)woh,  n4);
    }

    // 1) q = x @ Wq^T + bq   (fp32 out for RoPE)
    gemm_h<<<dim3(EMBED/128, NTOK/128), 256, GEMM_SMEM>>>(xh, wqh, bq, qb, NTOK, EMBED, EMBED);
    // 2) kv = x @ Wkv^T + bkv
    gemm_h<<<dim3(KVDIM/128, NTOK/128), 256, GEMM_SMEM>>>(xh, wkvh, bkv, kvb, NTOK, KVDIM, EMBED);
    // 3) RoPE + fp16 repack (q scaled, k, v)
    {
        int total = NTOK*NHEADS*64 + NTOK*NKV*64 + NTOK*NKV*128;
        rope_h<<<(total + 255) / 256, 256>>>();
    }
    // 4) flash attention -> g_oh (fp16)
    attn_h<<<dim3(SEQ/128, NHEADS, BATCH), 256, AT_SMEM>>>();
    // 5) out = o @ Wo^T
    gemm_h<<<dim3(EMBED/128, NTOK/128), 256, GEMM_SMEM>>>(oh, woh, nullptr, out, NTOK, EMBED, EMBED);
}

// round 10
// speedup vs baseline: 11.3726x; 1.0454x over previous
#include <cuda_runtime.h>
#include <cuda_fp16.h>
#include <math.h>
#include <stdint.h>

#define EMBED   2048
#define NHEADS  16
#define NKV     4
#define HDIM    128
#define BATCH   2
#define SEQ     2048
#define NTOK    (BATCH*SEQ)      // 4096
#define KVDIM   1024             // k(512) + v(512)

// fp16 scratch
__device__ __half g_xh  [NTOK * EMBED];
__device__ __half g_wqh [EMBED * EMBED];
__device__ __half g_wkvh[KVDIM * EMBED];
__device__ __half g_woh [EMBED * EMBED];
__device__ __half g_q16 [NTOK * EMBED];   // pre-rope q (fp16, token-major)
__device__ __half g_kv16[NTOK * KVDIM];   // pre-rope kv (fp16, token-major)
__device__ __half g_qh  [NTOK * EMBED];   // [b][h][s][d], rope'd + scaled
__device__ __half g_kh  [NTOK * 512];     // [b][kvh][s][d], rope'd
__device__ __half g_vh  [NTOK * 512];     // [b][kvh][s][d]
__device__ __half g_oh  [NTOK * EMBED];   // attention out (fp16, token-major)

// ---------------------------------------------------------------------------
// PTX helpers (baseline sm_80+ features only)
// ---------------------------------------------------------------------------
__device__ __forceinline__ uint32_t smem_to_u32(const void* p) {
    uint32_t a;
    asm("{ .reg .u64 t; cvta.to.shared.u64 t, %1; cvt.u32.u64 %0, t; }" : "=r"(a) : "l"(p));
    return a;
}

__device__ __forceinline__ void mma16(float c[4], const uint32_t a[4], const uint32_t b[2]) {
    asm volatile(
        "mma.sync.aligned.m16n8k16.row.col.f32.f16.f16.f32 "
        "{%0,%1,%2,%3},{%4,%5,%6,%7},{%8,%9},{%0,%1,%2,%3};"
        : "+f"(c[0]), "+f"(c[1]), "+f"(c[2]), "+f"(c[3])
        : "r"(a[0]), "r"(a[1]), "r"(a[2]), "r"(a[3]), "r"(b[0]), "r"(b[1]));
}

__device__ __forceinline__ void ldsm4(uint32_t r[4], uint32_t addr) {
    asm volatile("ldmatrix.sync.aligned.m8n8.x4.shared.b16 {%0,%1,%2,%3}, [%4];"
        : "=r"(r[0]), "=r"(r[1]), "=r"(r[2]), "=r"(r[3]) : "r"(addr));
}

__device__ __forceinline__ void ldsm4t(uint32_t r[4], uint32_t addr) {
    asm volatile("ldmatrix.sync.aligned.m8n8.x4.trans.shared.b16 {%0,%1,%2,%3}, [%4];"
        : "=r"(r[0]), "=r"(r[1]), "=r"(r[2]), "=r"(r[3]) : "r"(addr));
}

__device__ __forceinline__ void cp16(uint32_t dst, const void* src) {
    asm volatile("cp.async.cg.shared.global [%0], [%1], 16;" :: "r"(dst), "l"(src));
}
#define CP_COMMIT() asm volatile("cp.async.commit_group;" ::: "memory")
#define CP_WAIT0()  asm volatile("cp.async.wait_group 0;" ::: "memory")
#define CP_WAIT1()  asm volatile("cp.async.wait_group 1;" ::: "memory")
#define CP_WAIT2()  asm volatile("cp.async.wait_group 2;" ::: "memory")

// ---------------------------------------------------------------------------
// Fused fp32 -> fp16 conversion of x, Wq, Wkv, Wo (one launch)
// ---------------------------------------------------------------------------
__global__ void to_half_all(const float4* __restrict__ x,  const float4* __restrict__ wq,
                            const float4* __restrict__ wkv, const float4* __restrict__ wo)
{
    const int n_x   = NTOK * EMBED / 4;
    const int n_wq  = EMBED * EMBED / 4;
    const int n_wkv = KVDIM * EMBED / 4;
    const int n_wo  = EMBED * EMBED / 4;
    int i = blockIdx.x * blockDim.x + threadIdx.x;

    const float4* src;
    uint2* dst;
    int j;
    if (i < n_x)                         { src = x;   dst = (uint2*)g_xh;   j = i; }
    else if (i < n_x + n_wq)             { src = wq;  dst = (uint2*)g_wqh;  j = i - n_x; }
    else if (i < n_x + n_wq + n_wkv)     { src = wkv; dst = (uint2*)g_wkvh; j = i - n_x - n_wq; }
    else if (i < n_x + n_wq + n_wkv + n_wo) { src = wo; dst = (uint2*)g_woh; j = i - n_x - n_wq - n_wkv; }
    else return;

    float4 v = src[j];
    __half2 h0 = __floats2half2_rn(v.x, v.y);
    __half2 h1 = __floats2half2_rn(v.z, v.w);
    uint2 u;
    u.x = *(uint32_t*)&h0;
    u.y = *(uint32_t*)&h1;
    dst[j] = u;
}

// ---------------------------------------------------------------------------
// GEMM: C[M,N] = A[M,K](fp16) @ W[N,K]^T(fp16) + bias.  HOUT: fp16 vs fp32 C.
// CTA 128x128, BK=64, 8 warps (32x64 each), 3-stage cp.async pipeline,
// ldmatrix fragments. smem row = 128B data + 16B pad = 144B.
// Stage = A(18432)+B(18432) = 36864 B; x3 = 110592 B.
// ---------------------------------------------------------------------------
template <bool HOUT>
__global__ __launch_bounds__(256, 2) void gemm_h(
    const __half* __restrict__ A, const __half* __restrict__ W,
    const float* __restrict__ bias, void* __restrict__ Cout,
    int M, int N, int K)
{
    extern __shared__ char smc[];
    const uint32_t sb = smem_to_u32(smc);

    const int bm   = blockIdx.y * 128;
    const int bn   = blockIdx.x * 128;
    const int tid  = threadIdx.x;
    const int lane = tid & 31;
    const int w    = tid >> 5;
    const int mw   = w & 3;
    const int nw   = w >> 2;
    const int lr   = lane >> 2;
    const int lc   = lane & 3;

    float acc[2][8][4];
#pragma unroll
    for (int mi = 0; mi < 2; mi++)
#pragma unroll
        for (int ni = 0; ni < 8; ni++)
#pragma unroll
            for (int c = 0; c < 4; c++) acc[mi][ni][c] = 0.f;

    const int NT = K / 64;

    auto issue = [&](int t) {
        const int buf = t % 3;
        const int kb  = t * 64;
        uint32_t abuf = sb + buf * 36864;
        uint32_t bbuf = abuf + 18432;
#pragma unroll
        for (int i = 0; i < 4; i++) {
            int slot = tid + i * 256;
            int r = slot >> 3, c = slot & 7;
            cp16(abuf + r * 144 + c * 16, A + (size_t)(bm + r) * K + kb + c * 8);
            cp16(bbuf + r * 144 + c * 16, W + (size_t)(bn + r) * K + kb + c * 8);
        }
        CP_COMMIT();
    };

    const uint32_t a_base = sb + (mw * 32 + (lane & 15)) * 144 + (lane >> 4) * 16;
    const uint32_t b_base = sb + 18432
        + (nw * 64 + ((lane >> 4) << 3) + (lane & 7)) * 144 + ((lane >> 3) & 1) * 16;

    issue(0);
    issue(1);

    for (int t = 0; t < NT; t++) {
        if (t + 2 < NT) { issue(t + 2); CP_WAIT2(); }
        else if (t + 1 < NT) { CP_WAIT1(); }
        else { CP_WAIT0(); }
        __syncthreads();

        const uint32_t boff = (t % 3) * 36864;
#pragma unroll
        for (int ks = 0; ks < 4; ks++) {
            uint32_t af0[4], af1[4];
            ldsm4(af0, a_base + boff + ks * 32);
            ldsm4(af1, a_base + boff + 2304 + ks * 32);   // +16 rows
#pragma unroll
            for (int np = 0; np < 4; np++) {
                uint32_t bf[4];
                ldsm4(bf, b_base + boff + np * 2304 + ks * 32);
                mma16(acc[0][np * 2],     af0, bf);
                mma16(acc[0][np * 2 + 1], af0, bf + 2);
                mma16(acc[1][np * 2],     af1, bf);
                mma16(acc[1][np * 2 + 1], af1, bf + 2);
            }
        }
        __syncthreads();   // reads of this buffer done before it is re-filled
    }

    // Epilogue
#pragma unroll
    for (int mi = 0; mi < 2; mi++) {
        int r = bm + mw * 32 + mi * 16 + lr;
#pragma unroll
        for (int ni = 0; ni < 8; ni++) {
            int cc = bn + nw * 64 + ni * 8 + 2 * lc;
            float b0 = bias ? bias[cc] : 0.f;
            float b1 = bias ? bias[cc + 1] : 0.f;
            float v00 = acc[mi][ni][0] + b0, v01 = acc[mi][ni][1] + b1;
            float v10 = acc[mi][ni][2] + b0, v11 = acc[mi][ni][3] + b1;
            if (HOUT) {
                __half* C = (__half*)Cout;
                __half2 h0 = __floats2half2_rn(v00, v01);
                __half2 h1 = __floats2half2_rn(v10, v11);
                *(__half2*)(C + (size_t)r * N + cc)       = h0;
                *(__half2*)(C + (size_t)(r + 8) * N + cc) = h1;
            } else {
                float* C = (float*)Cout;
                *(float2*)(C + (size_t)r * N + cc)       = make_float2(v00, v01);
                *(float2*)(C + (size_t)(r + 8) * N + cc) = make_float2(v10, v11);
            }
        }
    }
}

// ---------------------------------------------------------------------------
// RoPE + repack (fp16 in, fp16 out): g_q16 -> g_qh (scaled, [b][h][s][d]);
// k-half of g_kv16 -> g_kh; v-half -> g_vh (pure half2 relayout).
// ---------------------------------------------------------------------------
__global__ void rope_h()
{
    const int QTOT = NTOK * NHEADS * 64;   // rotation pairs
    const int KTOT = NTOK * NKV * 64;
    const int VTOT = NTOK * NKV * 64;      // half2 copies
    const float scale = 0.08838834764831845f;  // 1/sqrt(128)

    int idx = blockIdx.x * blockDim.x + threadIdx.x;
    if (idx < QTOT) {
        int i = idx & 63;
        int h = (idx >> 6) & 15;
        int t = idx >> 10;
        int s = t & (SEQ - 1), b = t >> 11;
        float x1 = __half2float(g_q16[(size_t)t * EMBED + h * HDIM + i]);
        float x2 = __half2float(g_q16[(size_t)t * EMBED + h * HDIM + i + 64]);
        float freq = powf(10000.0f, -(float)(2 * i) * (1.0f / 128.0f));
        float sn, cs; sincosf((float)s * freq, &sn, &cs);
        size_t dst = ((size_t)(b * NHEADS + h) * SEQ + s) * HDIM + i;
        g_qh[dst]      = __float2half_rn((x1 * cs - x2 * sn) * scale);
        g_qh[dst + 64] = __float2half_rn((x2 * cs + x1 * sn) * scale);
    } else if (idx < QTOT + KTOT) {
        int j = idx - QTOT;
        int i = j & 63;
        int kvh = (j >> 6) & 3;
        int t = j >> 8;
        int s = t & (SEQ - 1), b = t >> 11;
        float x1 = __half2float(g_kv16[(size_t)t * KVDIM + kvh * HDIM + i]);
        float x2 = __half2float(g_kv16[(size_t)t * KVDIM + kvh * HDIM + i + 64]);
        float freq = powf(10000.0f, -(float)(2 * i) * (1.0f / 128.0f));
        float sn, cs; sincosf((float)s * freq, &sn, &cs);
        size_t dst = ((size_t)(b * NKV + kvh) * SEQ + s) * HDIM + i;
        g_kh[dst]      = __float2half_rn(x1 * cs - x2 * sn);
        g_kh[dst + 64] = __float2half_rn(x2 * cs + x1 * sn);
    } else if (idx < QTOT + KTOT + VTOT) {
        int j = idx - QTOT - KTOT;
        int d2 = j & 63;              // half2 index within head dim
        int rest = j >> 6;
        int kvh = rest & 3;
        int t = rest >> 2;
        int s = t & (SEQ - 1), b = t >> 11;
        const __half2* src = (const __half2*)(g_kv16 + (size_t)t * KVDIM + 512 + kvh * HDIM);
        __half2* dst = (__half2*)(g_vh + ((size_t)(b * NKV + kvh) * SEQ + s) * HDIM);
        dst[d2] = src[d2];
    }
}

// ---------------------------------------------------------------------------
// Flash attention fp16: 128 q-rows/CTA, 8 warps = 8 row-strips of 16.
// cp.async double-buffered K/V; ldmatrix Q/K, ldmatrix.trans V.
// P stays in REGISTERS: S accumulator fragments re-pack directly into the
// A-operand fragments of the PV mma (FlashAttention-2 layout identity).
// smem: Qs[128][272B] | Ks 2x[64][272B] | Vs 2x[64][272B]  = 104448 B
// ---------------------------------------------------------------------------
#define AT_QS 0
#define AT_KS 34816
#define AT_VS 69632
#define AT_SMEM 104448

__global__ __launch_bounds__(256, 1) void attn_h()
{
    extern __shared__ char smc[];
    const uint32_t sb = smem_to_u32(smc);

    const int q0   = blockIdx.x * 128;
    const int h    = blockIdx.y;
    const int b    = blockIdx.z;
    const int kvh  = h >> 2;
    const int tid  = threadIdx.x;
    const int lane = tid & 31;
    const int w    = tid >> 5;
    const int lr   = lane >> 2;
    const int lc   = lane & 3;

    const __half* qsrc = g_qh + ((size_t)(b * NHEADS + h) * SEQ + q0) * HDIM;
    const __half* ksrc = g_kh + (size_t)(b * NKV + kvh) * SEQ * HDIM;
    const __half* vsrc = g_vh + (size_t)(b * NKV + kvh) * SEQ * HDIM;

    // Group 0: Q tile + KV tile 0
#pragma unroll
    for (int i = 0; i < 8; i++) {
        int slot = tid + i * 256;
        int r = slot >> 4, c = slot & 15;
        cp16(sb + AT_QS + r * 272 + c * 16, qsrc + (size_t)r * HDIM + c * 8);
    }
#pragma unroll
    for (int i = 0; i < 4; i++) {
        int slot = tid + i * 256;
        int r = slot >> 4, c = slot & 15;
        cp16(sb + AT_KS + r * 272 + c * 16, ksrc + (size_t)r * HDIM + c * 8);
        cp16(sb + AT_VS + r * 272 + c * 16, vsrc + (size_t)r * HDIM + c * 8);
    }
    CP_COMMIT();

    const uint32_t q_base = sb + AT_QS + (w * 16 + (lane & 15)) * 272 + (lane >> 4) * 16;
    const uint32_t k_base = sb + AT_KS
        + (((lane >> 4) << 3) + (lane & 7)) * 272 + ((lane >> 3) & 1) * 16;
    const uint32_t v_base = sb + AT_VS + (lane & 15) * 272 + (lane >> 4) * 16;

    float m0 = -INFINITY, m1 = -INFINITY, l0 = 0.f, l1 = 0.f;
    float o_acc[16][4];
#pragma unroll
    for (int ni = 0; ni < 16; ni++)
#pragma unroll
        for (int c = 0; c < 4; c++) o_acc[ni][c] = 0.f;

    const int NT = SEQ / 64;   // 32
    for (int kt = 0; kt < NT; kt++) {
        if (kt + 1 < NT) {
            const int buf = (kt + 1) & 1;
            const int kv0 = (kt + 1) * 64;
#pragma unroll
            for (int i = 0; i < 4; i++) {
                int slot = tid + i * 256;
                int r = slot >> 4, c = slot & 15;
                cp16(sb + AT_KS + buf * 17408 + r * 272 + c * 16,
                     ksrc + (size_t)(kv0 + r) * HDIM + c * 8);
                cp16(sb + AT_VS + buf * 17408 + r * 272 + c * 16,
                     vsrc + (size_t)(kv0 + r) * HDIM + c * 8);
            }
            CP_COMMIT();
            CP_WAIT1();
        } else {
            CP_WAIT0();
        }
        __syncthreads();

        const uint32_t kb = (kt & 1) * 17408;

        // S = Q @ K^T : warp rows [w*16,+16) x 64 kv cols
        float sfr[8][4];
#pragma unroll
        for (int ni = 0; ni < 8; ni++)
#pragma unroll
            for (int c = 0; c < 4; c++) sfr[ni][c] = 0.f;

#pragma unroll
        for (int ks = 0; ks < 8; ks++) {
            uint32_t af[4];
            ldsm4(af, q_base + ks * 32);
#pragma unroll
            for (int np = 0; np < 4; np++) {
                uint32_t bf[4];
                ldsm4(bf, k_base + kb + np * 4352 + ks * 32);
                mma16(sfr[np * 2],     af, bf);
                mma16(sfr[np * 2 + 1], af, bf + 2);
            }
        }

        // Warp-local online softmax
        float mx0 = -INFINITY, mx1 = -INFINITY;
#pragma unroll
        for (int ni = 0; ni < 8; ni++) {
            mx0 = fmaxf(mx0, fmaxf(sfr[ni][0], sfr[ni][1]));
            mx1 = fmaxf(mx1, fmaxf(sfr[ni][2], sfr[ni][3]));
        }
        mx0 = fmaxf(mx0, __shfl_xor_sync(0xffffffffu, mx0, 1));
        mx0 = fmaxf(mx0, __shfl_xor_sync(0xffffffffu, mx0, 2));
        mx1 = fmaxf(mx1, __shfl_xor_sync(0xffffffffu, mx1, 1));
        mx1 = fmaxf(mx1, __shfl_xor_sync(0xffffffffu, mx1, 2));

        float mn0 = fmaxf(m0, mx0);
        float mn1 = fmaxf(m1, mx1);
        float corr0 = __expf(m0 - mn0);
        float corr1 = __expf(m1 - mn1);
        m0 = mn0; m1 = mn1;

        // exp + pack P directly into PV A-operand fragments (no smem):
        // pf[ks][0,1] = rows lr/lr+8, k = ks*16 + 2lc(+1)      (from sfr[2ks])
        // pf[ks][2,3] = rows lr/lr+8, k = ks*16 + 8 + 2lc(+1)  (from sfr[2ks+1])
        uint32_t pf[4][4];
        float s0 = 0.f, s1 = 0.f;
#pragma unroll
        for (int ni = 0; ni < 8; ni++) {
            float p00 = __expf(sfr[ni][0] - mn0);
            float p01 = __expf(sfr[ni][1] - mn0);
            float p10 = __expf(sfr[ni][2] - mn1);
            float p11 = __expf(sfr[ni][3] - mn1);
            s0 += p00 + p01; s1 += p10 + p11;
            __half2 h0 = __floats2half2_rn(p00, p01);
            __half2 h1 = __floats2half2_rn(p10, p11);
            pf[ni >> 1][((ni & 1) << 1)]     = *(uint32_t*)&h0;
            pf[ni >> 1][((ni & 1) << 1) + 1] = *(uint32_t*)&h1;
        }
        s0 += __shfl_xor_sync(0xffffffffu, s0, 1);
        s0 += __shfl_xor_sync(0xffffffffu, s0, 2);
        s1 += __shfl_xor_sync(0xffffffffu, s1, 1);
        s1 += __shfl_xor_sync(0xffffffffu, s1, 2);
        l0 = l0 * corr0 + s0;
        l1 = l1 * corr1 + s1;

        // Rescale + O += P @ V (P from registers, V via ldmatrix.trans)
#pragma unroll
        for (int ni = 0; ni < 16; ni++) {
            o_acc[ni][0] *= corr0; o_acc[ni][1] *= corr0;
            o_acc[ni][2] *= corr1; o_acc[ni][3] *= corr1;
        }
#pragma unroll
        for (int ks = 0; ks < 4; ks++) {
#pragma unroll
            for (int np = 0; np < 8; np++) {
                uint32_t bf[4];
                ldsm4t(bf, v_base + kb + ks * 4352 + np * 32);
                mma16(o_acc[np * 2],     pf[ks], bf);
                mma16(o_acc[np * 2 + 1], pf[ks], bf + 2);
            }
        }
        __syncthreads();   // done reading this K/V buffer
    }

    // Normalize + write g_oh (fp16, token-major for the Wo GEMM)
    float inv0 = 1.0f / l0;
    float inv1 = 1.0f / l1;
    int row = b * SEQ + q0 + w * 16 + lr;
#pragma unroll
    for (int ni = 0; ni < 16; ni++) {
        int d = ni * 8 + 2 * lc;
        __half2 h0 = __floats2half2_rn(o_acc[ni][0] * inv0, o_acc[ni][1] * inv0);
        __half2 h1 = __floats2half2_rn(o_acc[ni][2] * inv1, o_acc[ni][3] * inv1);
        *(__half2*)(g_oh + (size_t)row * EMBED + h * HDIM + d)       = h0;
        *(__half2*)(g_oh + (size_t)(row + 8) * EMBED + h * HDIM + d) = h1;
    }
}

// ---------------------------------------------------------------------------
extern "C" void kernel_launch(void* const* d_in, const int* in_sizes, int n_in,
                              void* d_out, int out_size)
{
    const float* x   = (const float*)d_in[0];
    const float* Wq  = (const float*)d_in[1];
    const float* bq  = (const float*)d_in[2];
    const float* Wkv = (const float*)d_in[3];
    const float* bkv = (const float*)d_in[4];
    const float* Wo  = (const float*)d_in[5];
    float* out = (float*)d_out;

    __half *xh, *wqh, *wkvh, *woh, *q16, *kv16, *oh;
    cudaGetSymbolAddress((void**)&xh,   g_xh);
    cudaGetSymbolAddress((void**)&wqh,  g_wqh);
    cudaGetSymbolAddress((void**)&wkvh, g_wkvh);
    cudaGetSymbolAddress((void**)&woh,  g_woh);
    cudaGetSymbolAddress((void**)&q16,  g_q16);
    cudaGetSymbolAddress((void**)&kv16, g_kv16);
    cudaGetSymbolAddress((void**)&oh,   g_oh);

    const int GEMM_SMEM = 110592;   // 3 stages x 36864
    cudaFuncSetAttribute(gemm_h<true>,  cudaFuncAttributeMaxDynamicSharedMemorySize, GEMM_SMEM);
    cudaFuncSetAttribute(gemm_h<false>, cudaFuncAttributeMaxDynamicSharedMemorySize, GEMM_SMEM);
    cudaFuncSetAttribute(attn_h, cudaFuncAttributeMaxDynamicSharedMemorySize, AT_SMEM);

    // 0) fp32 -> fp16 conversions (single fused launch)
    {
        int n4 = (NTOK * EMBED + 2 * EMBED * EMBED + KVDIM * EMBED) / 4;
        to_half_all<<<(n4 + 255) / 256, 256>>>((const float4*)x, (const float4*)Wq,
                                               (const float4*)Wkv, (const float4*)Wo);
    }
    // 1) q = x @ Wq^T + bq  (fp16 out)
    gemm_h<true><<<dim3(EMBED/128, NTOK/128), 256, GEMM_SMEM>>>(xh, wqh, bq, q16, NTOK, EMBED, EMBED);
    // 2) kv = x @ Wkv^T + bkv  (fp16 out)
    gemm_h<true><<<dim3(KVDIM/128, NTOK/128), 256, GEMM_SMEM>>>(xh, wkvh, bkv, kv16, NTOK, KVDIM, EMBED);
    // 3) RoPE + repack
    {
        int total = NTOK*NHEADS*64 + NTOK*NKV*64 + NTOK*NKV*64;
        rope_h<<<(total + 255) / 256, 256>>>();
    }
    // 4) flash attention -> g_oh
    attn_h<<<dim3(SEQ/128, NHEADS, BATCH), 256, AT_SMEM>>>();
    // 5) out = o @ Wo^T  (fp32 out)
    gemm_h<false><<<dim3(EMBED/128, NTOK/128), 256, GEMM_SMEM>>>(oh, woh, nullptr, out, NTOK, EMBED, EMBED);
}

// round 11
// speedup vs baseline: 11.7375x; 1.0321x over previous
#include <cuda_runtime.h>
#include <cuda_fp16.h>
#include <math.h>
#include <stdint.h>

#define EMBED   2048
#define NHEADS  16
#define NKV     4
#define HDIM    128
#define BATCH   2
#define SEQ     2048
#define NTOK    (BATCH*SEQ)      // 4096
#define KVDIM   1024             // k(512) + v(512)
#define QKVN    (EMBED + KVDIM)  // 3072 fused projection width

// fp16 scratch
__device__ __half g_xh   [NTOK * EMBED];
__device__ __half g_wh   [QKVN * EMBED];    // Wq rows 0..2047, Wkv rows 2048..3071
__device__ __half g_woh  [EMBED * EMBED];
__device__ __half g_qkv16[NTOK * QKVN];     // fused projection out (pre-rope)
__device__ __half g_qh   [NTOK * EMBED];    // [b][h][s][d], rope'd + scaled
__device__ __half g_kh   [NTOK * 512];      // [b][kvh][s][d], rope'd
__device__ __half g_vh   [NTOK * 512];      // [b][kvh][s][d]
__device__ __half g_oh   [NTOK * EMBED];    // attention out (token-major)
// aux
__device__ float2 g_rope_tab[SEQ * 64];     // (cos, sin) per (s, i)
__device__ float  g_bqkv[QKVN];             // stacked bias

// ---------------------------------------------------------------------------
// PTX helpers (baseline sm_80+ features only)
// ---------------------------------------------------------------------------
__device__ __forceinline__ uint32_t smem_to_u32(const void* p) {
    uint32_t a;
    asm("{ .reg .u64 t; cvta.to.shared.u64 t, %1; cvt.u32.u64 %0, t; }" : "=r"(a) : "l"(p));
    return a;
}

__device__ __forceinline__ void mma16(float c[4], const uint32_t a[4], const uint32_t b[2]) {
    asm volatile(
        "mma.sync.aligned.m16n8k16.row.col.f32.f16.f16.f32 "
        "{%0,%1,%2,%3},{%4,%5,%6,%7},{%8,%9},{%0,%1,%2,%3};"
        : "+f"(c[0]), "+f"(c[1]), "+f"(c[2]), "+f"(c[3])
        : "r"(a[0]), "r"(a[1]), "r"(a[2]), "r"(a[3]), "r"(b[0]), "r"(b[1]));
}

__device__ __forceinline__ void ldsm4(uint32_t r[4], uint32_t addr) {
    asm volatile("ldmatrix.sync.aligned.m8n8.x4.shared.b16 {%0,%1,%2,%3}, [%4];"
        : "=r"(r[0]), "=r"(r[1]), "=r"(r[2]), "=r"(r[3]) : "r"(addr));
}

__device__ __forceinline__ void ldsm4t(uint32_t r[4], uint32_t addr) {
    asm volatile("ldmatrix.sync.aligned.m8n8.x4.trans.shared.b16 {%0,%1,%2,%3}, [%4];"
        : "=r"(r[0]), "=r"(r[1]), "=r"(r[2]), "=r"(r[3]) : "r"(addr));
}

__device__ __forceinline__ void cp16(uint32_t dst, const void* src) {
    asm volatile("cp.async.cg.shared.global [%0], [%1], 16;" :: "r"(dst), "l"(src));
}
#define CP_COMMIT() asm volatile("cp.async.commit_group;" ::: "memory")
#define CP_WAIT0()  asm volatile("cp.async.wait_group 0;" ::: "memory")
#define CP_WAIT1()  asm volatile("cp.async.wait_group 1;" ::: "memory")

// ---------------------------------------------------------------------------
// Fused prep: fp32->fp16 of x, Wq|Wkv (packed), Wo; RoPE table; stacked bias.
// ---------------------------------------------------------------------------
__global__ void prep_all(const float4* __restrict__ x,  const float4* __restrict__ wq,
                         const float4* __restrict__ wkv, const float4* __restrict__ wo,
                         const float* __restrict__ bq,  const float* __restrict__ bkv)
{
    const int n_x   = NTOK * EMBED / 4;
    const int n_wq  = EMBED * EMBED / 4;
    const int n_wkv = KVDIM * EMBED / 4;
    const int n_wo  = EMBED * EMBED / 4;
    const int n_tab = SEQ * 64;
    int i = blockIdx.x * blockDim.x + threadIdx.x;

    int base = 0;
    if (i < (base += n_x)) {
        int j = i;
        float4 v = x[j];
        __half2 h0 = __floats2half2_rn(v.x, v.y), h1 = __floats2half2_rn(v.z, v.w);
        ((uint2*)g_xh)[j] = make_uint2(*(uint32_t*)&h0, *(uint32_t*)&h1);
    } else if (i < (base += n_wq)) {
        int j = i - (base - n_wq);
        float4 v = wq[j];
        __half2 h0 = __floats2half2_rn(v.x, v.y), h1 = __floats2half2_rn(v.z, v.w);
        ((uint2*)g_wh)[j] = make_uint2(*(uint32_t*)&h0, *(uint32_t*)&h1);
    } else if (i < (base += n_wkv)) {
        int j = i - (base - n_wkv);
        float4 v = wkv[j];
        __half2 h0 = __floats2half2_rn(v.x, v.y), h1 = __floats2half2_rn(v.z, v.w);
        ((uint2*)(g_wh + (size_t)EMBED * EMBED))[j] = make_uint2(*(uint32_t*)&h0, *(uint32_t*)&h1);
    } else if (i < (base += n_wo)) {
        int j = i - (base - n_wo);
        float4 v = wo[j];
        __half2 h0 = __floats2half2_rn(v.x, v.y), h1 = __floats2half2_rn(v.z, v.w);
        ((uint2*)g_woh)[j] = make_uint2(*(uint32_t*)&h0, *(uint32_t*)&h1);
    } else if (i < (base += n_tab)) {
        int j = i - (base - n_tab);
        int s = j >> 6, d = j & 63;
        float freq = powf(10000.0f, -(float)d * (1.0f / 64.0f));
        float sn, cs; sincosf((float)s * freq, &sn, &cs);
        g_rope_tab[j] = make_float2(cs, sn);
    } else if (i < (base += QKVN)) {
        int j = i - (base - QKVN);
        g_bqkv[j] = (j < EMBED) ? bq[j] : bkv[j - EMBED];
    }
}

// ---------------------------------------------------------------------------
// GEMM: C[M,N] = A[M,K](fp16) @ W[N,K]^T(fp16) + bias.  HOUT: fp16 vs fp32 C.
// CTA 128x128, BK=64, 8 warps, 3-stage cp.async, single sync per k-tile.
// ---------------------------------------------------------------------------
template <bool HOUT>
__global__ __launch_bounds__(256, 2) void gemm_h(
    const __half* __restrict__ A, const __half* __restrict__ W,
    const float* __restrict__ bias, void* __restrict__ Cout,
    int M, int N, int K)
{
    extern __shared__ char smc[];
    const uint32_t sb = smem_to_u32(smc);

    const int bm   = blockIdx.y * 128;
    const int bn   = blockIdx.x * 128;
    const int tid  = threadIdx.x;
    const int lane = tid & 31;
    const int w    = tid >> 5;
    const int mw   = w & 3;
    const int nw   = w >> 2;
    const int lr   = lane >> 2;
    const int lc   = lane & 3;

    float acc[2][8][4];
#pragma unroll
    for (int mi = 0; mi < 2; mi++)
#pragma unroll
        for (int ni = 0; ni < 8; ni++)
#pragma unroll
            for (int c = 0; c < 4; c++) acc[mi][ni][c] = 0.f;

    const int NT = K / 64;

    auto issue = [&](int t) {
        const int buf = t % 3;
        const int kb  = t * 64;
        uint32_t abuf = sb + buf * 36864;
        uint32_t bbuf = abuf + 18432;
#pragma unroll
        for (int i = 0; i < 4; i++) {
            int slot = tid + i * 256;
            int r = slot >> 3, c = slot & 7;
            cp16(abuf + r * 144 + c * 16, A + (size_t)(bm + r) * K + kb + c * 8);
            cp16(bbuf + r * 144 + c * 16, W + (size_t)(bn + r) * K + kb + c * 8);
        }
        CP_COMMIT();
    };

    const uint32_t a_base = sb + (mw * 32 + (lane & 15)) * 144 + (lane >> 4) * 16;
    const uint32_t b_base = sb + 18432
        + (nw * 64 + ((lane >> 4) << 3) + (lane & 7)) * 144 + ((lane >> 3) & 1) * 16;

    issue(0);
    issue(1);

    for (int t = 0; t < NT; t++) {
        if (t + 1 < NT) { CP_WAIT1(); } else { CP_WAIT0(); }
        __syncthreads();               // buf t ready; all warps past compute(t-1)
        if (t + 2 < NT) issue(t + 2);  // overwrites buf (t-1)%3 — safe post-sync

        const uint32_t boff = (t % 3) * 36864;
#pragma unroll
        for (int ks = 0; ks < 4; ks++) {
            uint32_t af0[4], af1[4];
            ldsm4(af0, a_base + boff + ks * 32);
            ldsm4(af1, a_base + boff + 2304 + ks * 32);
#pragma unroll
            for (int np = 0; np < 4; np++) {
                uint32_t bf[4];
                ldsm4(bf, b_base + boff + np * 2304 + ks * 32);
                mma16(acc[0][np * 2],     af0, bf);
                mma16(acc[0][np * 2 + 1], af0, bf + 2);
                mma16(acc[1][np * 2],     af1, bf);
                mma16(acc[1][np * 2 + 1], af1, bf + 2);
            }
        }
    }

    // Epilogue
#pragma unroll
    for (int mi = 0; mi < 2; mi++) {
        int r = bm + mw * 32 + mi * 16 + lr;
#pragma unroll
        for (int ni = 0; ni < 8; ni++) {
            int cc = bn + nw * 64 + ni * 8 + 2 * lc;
            float b0 = bias ? bias[cc] : 0.f;
            float b1 = bias ? bias[cc + 1] : 0.f;
            float v00 = acc[mi][ni][0] + b0, v01 = acc[mi][ni][1] + b1;
            float v10 = acc[mi][ni][2] + b0, v11 = acc[mi][ni][3] + b1;
            if (HOUT) {
                __half* C = (__half*)Cout;
                __half2 h0 = __floats2half2_rn(v00, v01);
                __half2 h1 = __floats2half2_rn(v10, v11);
                *(__half2*)(C + (size_t)r * N + cc)       = h0;
                *(__half2*)(C + (size_t)(r + 8) * N + cc) = h1;
            } else {
                float* C = (float*)Cout;
                *(float2*)(C + (size_t)r * N + cc)       = make_float2(v00, v01);
                *(float2*)(C + (size_t)(r + 8) * N + cc) = make_float2(v10, v11);
            }
        }
    }
}

// ---------------------------------------------------------------------------
// RoPE + repack from fused projection buffer (table-based, memory-bound).
// q cols [0,2048) -> g_qh (scaled); k cols [2048,2560) -> g_kh; v -> g_vh.
// ---------------------------------------------------------------------------
__global__ void rope_h()
{
    const int QTOT = NTOK * NHEADS * 64;   // rotation pairs
    const int KTOT = NTOK * NKV * 64;
    const int VTOT = NTOK * NKV * 64;      // half2 copies
    const float scale = 0.08838834764831845f;

    int idx = blockIdx.x * blockDim.x + threadIdx.x;
    if (idx < QTOT) {
        int i = idx & 63;
        int h = (idx >> 6) & 15;
        int t = idx >> 10;
        int s = t & (SEQ - 1), b = t >> 11;
        const __half* src = g_qkv16 + (size_t)t * QKVN + h * HDIM + i;
        float x1 = __half2float(src[0]);
        float x2 = __half2float(src[64]);
        float2 cssn = g_rope_tab[s * 64 + i];
        size_t dst = ((size_t)(b * NHEADS + h) * SEQ + s) * HDIM + i;
        g_qh[dst]      = __float2half_rn((x1 * cssn.x - x2 * cssn.y) * scale);
        g_qh[dst + 64] = __float2half_rn((x2 * cssn.x + x1 * cssn.y) * scale);
    } else if (idx < QTOT + KTOT) {
        int j = idx - QTOT;
        int i = j & 63;
        int kvh = (j >> 6) & 3;
        int t = j >> 8;
        int s = t & (SEQ - 1), b = t >> 11;
        const __half* src = g_qkv16 + (size_t)t * QKVN + EMBED + kvh * HDIM + i;
        float x1 = __half2float(src[0]);
        float x2 = __half2float(src[64]);
        float2 cssn = g_rope_tab[s * 64 + i];
        size_t dst = ((size_t)(b * NKV + kvh) * SEQ + s) * HDIM + i;
        g_kh[dst]      = __float2half_rn(x1 * cssn.x - x2 * cssn.y);
        g_kh[dst + 64] = __float2half_rn(x2 * cssn.x + x1 * cssn.y);
    } else if (idx < QTOT + KTOT + VTOT) {
        int j = idx - QTOT - KTOT;
        int d2 = j & 63;
        int rest = j >> 6;
        int kvh = rest & 3;
        int t = rest >> 2;
        int s = t & (SEQ - 1), b = t >> 11;
        const __half2* src = (const __half2*)(g_qkv16 + (size_t)t * QKVN + EMBED + 512 + kvh * HDIM);
        __half2* dst = (__half2*)(g_vh + ((size_t)(b * NKV + kvh) * SEQ + s) * HDIM);
        dst[d2] = src[d2];
    }
}

// ---------------------------------------------------------------------------
// Flash attention fp16: 128 q-rows/CTA, 8 warp row-strips, register-P,
// 3-stage K/V cp.async pipeline, single sync per kv-tile.
// smem: Qs[128][272B] | Ks 3x[64][272B] | Vs 3x[64][272B] = 139264 B
// ---------------------------------------------------------------------------
#define AT_QS 0
#define AT_KS 34816
#define AT_VS 87040
#define AT_SMEM 139264

__global__ __launch_bounds__(256, 1) void attn_h()
{
    extern __shared__ char smc[];
    const uint32_t sb = smem_to_u32(smc);

    const int q0   = blockIdx.x * 128;
    const int h    = blockIdx.y;
    const int b    = blockIdx.z;
    const int kvh  = h >> 2;
    const int tid  = threadIdx.x;
    const int lane = tid & 31;
    const int w    = tid >> 5;
    const int lr   = lane >> 2;
    const int lc   = lane & 3;

    const __half* qsrc = g_qh + ((size_t)(b * NHEADS + h) * SEQ + q0) * HDIM;
    const __half* ksrc = g_kh + (size_t)(b * NKV + kvh) * SEQ * HDIM;
    const __half* vsrc = g_vh + (size_t)(b * NKV + kvh) * SEQ * HDIM;

    auto issue_kv = [&](int kt) {
        const int buf = kt % 3;
        const int kv0 = kt * 64;
#pragma unroll
        for (int i = 0; i < 4; i++) {
            int slot = tid + i * 256;
            int r = slot >> 4, c = slot & 15;
            cp16(sb + AT_KS + buf * 17408 + r * 272 + c * 16,
                 ksrc + (size_t)(kv0 + r) * HDIM + c * 8);
            cp16(sb + AT_VS + buf * 17408 + r * 272 + c * 16,
                 vsrc + (size_t)(kv0 + r) * HDIM + c * 8);
        }
        CP_COMMIT();
    };

    // Group 0: Q + KV0; group 1: KV1
#pragma unroll
    for (int i = 0; i < 8; i++) {
        int slot = tid + i * 256;
        int r = slot >> 4, c = slot & 15;
        cp16(sb + AT_QS + r * 272 + c * 16, qsrc + (size_t)r * HDIM + c * 8);
    }
#pragma unroll
    for (int i = 0; i < 4; i++) {
        int slot = tid + i * 256;
        int r = slot >> 4, c = slot & 15;
        cp16(sb + AT_KS + r * 272 + c * 16, ksrc + (size_t)r * HDIM + c * 8);
        cp16(sb + AT_VS + r * 272 + c * 16, vsrc + (size_t)r * HDIM + c * 8);
    }
    CP_COMMIT();
    issue_kv(1);

    const uint32_t q_base = sb + AT_QS + (w * 16 + (lane & 15)) * 272 + (lane >> 4) * 16;
    const uint32_t k_base = sb + AT_KS
        + (((lane >> 4) << 3) + (lane & 7)) * 272 + ((lane >> 3) & 1) * 16;
    const uint32_t v_base = sb + AT_VS + (lane & 15) * 272 + (lane >> 4) * 16;

    float m0 = -INFINITY, m1 = -INFINITY, l0 = 0.f, l1 = 0.f;
    float o_acc[16][4];
#pragma unroll
    for (int ni = 0; ni < 16; ni++)
#pragma unroll
        for (int c = 0; c < 4; c++) o_acc[ni][c] = 0.f;

    const int NT = SEQ / 64;   // 32
    for (int kt = 0; kt < NT; kt++) {
        if (kt + 1 < NT) { CP_WAIT1(); } else { CP_WAIT0(); }
        __syncthreads();                 // buf kt ready; all warps past kt-1
        if (kt + 2 < NT) issue_kv(kt + 2);

        const uint32_t kb = (kt % 3) * 17408;

        // S = Q @ K^T
        float sfr[8][4];
#pragma unroll
        for (int ni = 0; ni < 8; ni++)
#pragma unroll
            for (int c = 0; c < 4; c++) sfr[ni][c] = 0.f;

#pragma unroll
        for (int ks = 0; ks < 8; ks++) {
            uint32_t af[4];
            ldsm4(af, q_base + ks * 32);
#pragma unroll
            for (int np = 0; np < 4; np++) {
                uint32_t bf[4];
                ldsm4(bf, k_base + kb + np * 4352 + ks * 32);
                mma16(sfr[np * 2],     af, bf);
                mma16(sfr[np * 2 + 1], af, bf + 2);
            }
        }

        // Warp-local online softmax
        float mx0 = -INFINITY, mx1 = -INFINITY;
#pragma unroll
        for (int ni = 0; ni < 8; ni++) {
            mx0 = fmaxf(mx0, fmaxf(sfr[ni][0], sfr[ni][1]));
            mx1 = fmaxf(mx1, fmaxf(sfr[ni][2], sfr[ni][3]));
        }
        mx0 = fmaxf(mx0, __shfl_xor_sync(0xffffffffu, mx0, 1));
        mx0 = fmaxf(mx0, __shfl_xor_sync(0xffffffffu, mx0, 2));
        mx1 = fmaxf(mx1, __shfl_xor_sync(0xffffffffu, mx1, 1));
        mx1 = fmaxf(mx1, __shfl_xor_sync(0xffffffffu, mx1, 2));

        float mn0 = fmaxf(m0, mx0);
        float mn1 = fmaxf(m1, mx1);
        float corr0 = __expf(m0 - mn0);
        float corr1 = __expf(m1 - mn1);
        m0 = mn0; m1 = mn1;

        // exp + pack P into PV A-fragments (registers only)
        uint32_t pf[4][4];
        float s0 = 0.f, s1 = 0.f;
#pragma unroll
        for (int ni = 0; ni < 8; ni++) {
            float p00 = __expf(sfr[ni][0] - mn0);
            float p01 = __expf(sfr[ni][1] - mn0);
            float p10 = __expf(sfr[ni][2] - mn1);
            float p11 = __expf(sfr[ni][3] - mn1);
            s0 += p00 + p01; s1 += p10 + p11;
            __half2 h0 = __floats2half2_rn(p00, p01);
            __half2 h1 = __floats2half2_rn(p10, p11);
            pf[ni >> 1][((ni & 1) << 1)]     = *(uint32_t*)&h0;
            pf[ni >> 1][((ni & 1) << 1) + 1] = *(uint32_t*)&h1;
        }
        s0 += __shfl_xor_sync(0xffffffffu, s0, 1);
        s0 += __shfl_xor_sync(0xffffffffu, s0, 2);
        s1 += __shfl_xor_sync(0xffffffffu, s1, 1);
        s1 += __shfl_xor_sync(0xffffffffu, s1, 2);
        l0 = l0 * corr0 + s0;
        l1 = l1 * corr1 + s1;

        // Rescale + O += P @ V
#pragma unroll
        for (int ni = 0; ni < 16; ni++) {
            o_acc[ni][0] *= corr0; o_acc[ni][1] *= corr0;
            o_acc[ni][2] *= corr1; o_acc[ni][3] *= corr1;
        }
#pragma unroll
        for (int ks = 0; ks < 4; ks++) {
#pragma unroll
            for (int np = 0; np < 8; np++) {
                uint32_t bf[4];
                ldsm4t(bf, v_base + kb + ks * 4352 + np * 32);
                mma16(o_acc[np * 2],     pf[ks], bf);
                mma16(o_acc[np * 2 + 1], pf[ks], bf + 2);
            }
        }
    }

    // Normalize + write g_oh (fp16, token-major)
    float inv0 = 1.0f / l0;
    float inv1 = 1.0f / l1;
    int row = b * SEQ + q0 + w * 16 + lr;
#pragma unroll
    for (int ni = 0; ni < 16; ni++) {
        int d = ni * 8 + 2 * lc;
        __half2 h0 = __floats2half2_rn(o_acc[ni][0] * inv0, o_acc[ni][1] * inv0);
        __half2 h1 = __floats2half2_rn(o_acc[ni][2] * inv1, o_acc[ni][3] * inv1);
        *(__half2*)(g_oh + (size_t)row * EMBED + h * HDIM + d)       = h0;
        *(__half2*)(g_oh + (size_t)(row + 8) * EMBED + h * HDIM + d) = h1;
    }
}

// ---------------------------------------------------------------------------
extern "C" void kernel_launch(void* const* d_in, const int* in_sizes, int n_in,
                              void* d_out, int out_size)
{
    const float* x   = (const float*)d_in[0];
    const float* Wq  = (const float*)d_in[1];
    const float* bq  = (const float*)d_in[2];
    const float* Wkv = (const float*)d_in[3];
    const float* bkv = (const float*)d_in[4];
    const float* Wo  = (const float*)d_in[5];
    float* out = (float*)d_out;

    __half *xh, *wh, *woh, *qkv16, *oh;
    float* bqkv;
    cudaGetSymbolAddress((void**)&xh,    g_xh);
    cudaGetSymbolAddress((void**)&wh,    g_wh);
    cudaGetSymbolAddress((void**)&woh,   g_woh);
    cudaGetSymbolAddress((void**)&qkv16, g_qkv16);
    cudaGetSymbolAddress((void**)&oh,    g_oh);
    cudaGetSymbolAddress((void**)&bqkv,  g_bqkv);

    const int GEMM_SMEM = 110592;
    cudaFuncSetAttribute(gemm_h<true>,  cudaFuncAttributeMaxDynamicSharedMemorySize, GEMM_SMEM);
    cudaFuncSetAttribute(gemm_h<false>, cudaFuncAttributeMaxDynamicSharedMemorySize, GEMM_SMEM);
    cudaFuncSetAttribute(attn_h, cudaFuncAttributeMaxDynamicSharedMemorySize, AT_SMEM);

    // 0) conversions + rope table + stacked bias (single launch)
    {
        int total = (NTOK * EMBED + 2 * EMBED * EMBED + KVDIM * EMBED) / 4
                  + SEQ * 64 + QKVN;
        prep_all<<<(total + 255) / 256, 256>>>((const float4*)x, (const float4*)Wq,
                                               (const float4*)Wkv, (const float4*)Wo,
                                               bq, bkv);
    }
    // 1) fused qkv = x @ [Wq;Wkv]^T + [bq;bkv]  (fp16 out)
    gemm_h<true><<<dim3(QKVN/128, NTOK/128), 256, GEMM_SMEM>>>(xh, wh, bqkv, qkv16, NTOK, QKVN, EMBED);
    // 2) RoPE + repack (table-based)
    {
        int total = NTOK*NHEADS*64 + NTOK*NKV*64 + NTOK*NKV*64;
        rope_h<<<(total + 255) / 256, 256>>>();
    }
    // 3) flash attention -> g_oh
    attn_h<<<dim3(SEQ/128, NHEADS, BATCH), 256, AT_SMEM>>>();
    // 4) out = o @ Wo^T  (fp32 out)
    gemm_h<false><<<dim3(EMBED/128, NTOK/128), 256, GEMM_SMEM>>>(oh, woh, nullptr, out, NTOK, EMBED, EMBED);
}

// round 12
// speedup vs baseline: 12.3131x; 1.0490x over previous
#include <cuda_runtime.h>
#include <cuda_fp16.h>
#include <math.h>
#include <stdint.h>

#define EMBED   2048
#define NHEADS  16
#define NKV     4
#define HDIM    128
#define BATCH   2
#define SEQ     2048
#define NTOK    (BATCH*SEQ)      // 4096
#define KVDIM   1024             // k(512) + v(512)
#define QKVN    (EMBED + KVDIM)  // 3072 fused projection width

// fp16 scratch
__device__ __half g_xh   [NTOK * EMBED];
__device__ __half g_wh   [QKVN * EMBED];    // Wq rows 0..2047, Wkv rows 2048..3071
__device__ __half g_woh  [EMBED * EMBED];
__device__ __half g_qkv16[NTOK * QKVN];     // fused projection out (pre-rope)
__device__ __half g_qh   [NTOK * EMBED];    // [b][h][s][d], rope'd + scaled
__device__ __half g_kh   [NTOK * 512];      // [b][kvh][s][d], rope'd
__device__ __half g_vh   [NTOK * 512];      // [b][kvh][s][d]
__device__ __half g_oh   [NTOK * EMBED];    // attention out (token-major)
// aux
__device__ float2 g_rope_tab[SEQ * 64];     // (cos, sin) per (s, i)
__device__ float  g_bqkv[QKVN];             // stacked bias

// ---------------------------------------------------------------------------
// PTX helpers (baseline sm_80+ features only)
// ---------------------------------------------------------------------------
__device__ __forceinline__ uint32_t smem_to_u32(const void* p) {
    uint32_t a;
    asm("{ .reg .u64 t; cvta.to.shared.u64 t, %1; cvt.u32.u64 %0, t; }" : "=r"(a) : "l"(p));
    return a;
}

__device__ __forceinline__ void mma16(float c[4], const uint32_t a[4], const uint32_t b[2]) {
    asm volatile(
        "mma.sync.aligned.m16n8k16.row.col.f32.f16.f16.f32 "
        "{%0,%1,%2,%3},{%4,%5,%6,%7},{%8,%9},{%0,%1,%2,%3};"
        : "+f"(c[0]), "+f"(c[1]), "+f"(c[2]), "+f"(c[3])
        : "r"(a[0]), "r"(a[1]), "r"(a[2]), "r"(a[3]), "r"(b[0]), "r"(b[1]));
}

__device__ __forceinline__ void ldsm4(uint32_t r[4], uint32_t addr) {
    asm volatile("ldmatrix.sync.aligned.m8n8.x4.shared.b16 {%0,%1,%2,%3}, [%4];"
        : "=r"(r[0]), "=r"(r[1]), "=r"(r[2]), "=r"(r[3]) : "r"(addr));
}

__device__ __forceinline__ void ldsm4t(uint32_t r[4], uint32_t addr) {
    asm volatile("ldmatrix.sync.aligned.m8n8.x4.trans.shared.b16 {%0,%1,%2,%3}, [%4];"
        : "=r"(r[0]), "=r"(r[1]), "=r"(r[2]), "=r"(r[3]) : "r"(addr));
}

__device__ __forceinline__ void cp16(uint32_t dst, const void* src) {
    asm volatile("cp.async.cg.shared.global [%0], [%1], 16;" :: "r"(dst), "l"(src));
}
#define CP_COMMIT() asm volatile("cp.async.commit_group;" ::: "memory")
#define CP_WAIT0()  asm volatile("cp.async.wait_group 0;" ::: "memory")
#define CP_WAIT1()  asm volatile("cp.async.wait_group 1;" ::: "memory")

// ---------------------------------------------------------------------------
// Fused prep: fp32->fp16 of x, Wq|Wkv (packed), Wo; RoPE table; stacked bias.
// ---------------------------------------------------------------------------
__global__ void prep_all(const float4* __restrict__ x,  const float4* __restrict__ wq,
                         const float4* __restrict__ wkv, const float4* __restrict__ wo,
                         const float* __restrict__ bq,  const float* __restrict__ bkv)
{
    const int n_x   = NTOK * EMBED / 4;
    const int n_wq  = EMBED * EMBED / 4;
    const int n_wkv = KVDIM * EMBED / 4;
    const int n_wo  = EMBED * EMBED / 4;
    const int n_tab = SEQ * 64;
    int i = blockIdx.x * blockDim.x + threadIdx.x;

    int base = 0;
    if (i < (base += n_x)) {
        int j = i;
        float4 v = x[j];
        __half2 h0 = __floats2half2_rn(v.x, v.y), h1 = __floats2half2_rn(v.z, v.w);
        ((uint2*)g_xh)[j] = make_uint2(*(uint32_t*)&h0, *(uint32_t*)&h1);
    } else if (i < (base += n_wq)) {
        int j = i - (base - n_wq);
        float4 v = wq[j];
        __half2 h0 = __floats2half2_rn(v.x, v.y), h1 = __floats2half2_rn(v.z, v.w);
        ((uint2*)g_wh)[j] = make_uint2(*(uint32_t*)&h0, *(uint32_t*)&h1);
    } else if (i < (base += n_wkv)) {
        int j = i - (base - n_wkv);
        float4 v = wkv[j];
        __half2 h0 = __floats2half2_rn(v.x, v.y), h1 = __floats2half2_rn(v.z, v.w);
        ((uint2*)(g_wh + (size_t)EMBED * EMBED))[j] = make_uint2(*(uint32_t*)&h0, *(uint32_t*)&h1);
    } else if (i < (base += n_wo)) {
        int j = i - (base - n_wo);
        float4 v = wo[j];
        __half2 h0 = __floats2half2_rn(v.x, v.y), h1 = __floats2half2_rn(v.z, v.w);
        ((uint2*)g_woh)[j] = make_uint2(*(uint32_t*)&h0, *(uint32_t*)&h1);
    } else if (i < (base += n_tab)) {
        int j = i - (base - n_tab);
        int s = j >> 6, d = j & 63;
        float freq = powf(10000.0f, -(float)d * (1.0f / 64.0f));
        float sn, cs; sincosf((float)s * freq, &sn, &cs);
        g_rope_tab[j] = make_float2(cs, sn);
    } else if (i < (base += QKVN)) {
        int j = i - (base - QKVN);
        g_bqkv[j] = (j < EMBED) ? bq[j] : bkv[j - EMBED];
    }
}

// ---------------------------------------------------------------------------
// GEMM: C[M,N] = A[M,K](fp16) @ W[N,K]^T(fp16) + bias.  HOUT: fp16 vs fp32 C.
// CTA 128x128, BK=64, 8 warps, 3-stage cp.async, single sync per k-tile.
// ---------------------------------------------------------------------------
template <bool HOUT>
__global__ __launch_bounds__(256, 2) void gemm_h(
    const __half* __restrict__ A, const __half* __restrict__ W,
    const float* __restrict__ bias, void* __restrict__ Cout,
    int M, int N, int K)
{
    extern __shared__ char smc[];
    const uint32_t sb = smem_to_u32(smc);

    const int bm   = blockIdx.y * 128;
    const int bn   = blockIdx.x * 128;
    const int tid  = threadIdx.x;
    const int lane = tid & 31;
    const int w    = tid >> 5;
    const int mw   = w & 3;
    const int nw   = w >> 2;
    const int lr   = lane >> 2;
    const int lc   = lane & 3;

    float acc[2][8][4];
#pragma unroll
    for (int mi = 0; mi < 2; mi++)
#pragma unroll
        for (int ni = 0; ni < 8; ni++)
#pragma unroll
            for (int c = 0; c < 4; c++) acc[mi][ni][c] = 0.f;

    const int NT = K / 64;

    auto issue = [&](int t) {
        const int buf = t % 3;
        const int kb  = t * 64;
        uint32_t abuf = sb + buf * 36864;
        uint32_t bbuf = abuf + 18432;
#pragma unroll
        for (int i = 0; i < 4; i++) {
            int slot = tid + i * 256;
            int r = slot >> 3, c = slot & 7;
            cp16(abuf + r * 144 + c * 16, A + (size_t)(bm + r) * K + kb + c * 8);
            cp16(bbuf + r * 144 + c * 16, W + (size_t)(bn + r) * K + kb + c * 8);
        }
        CP_COMMIT();
    };

    const uint32_t a_base = sb + (mw * 32 + (lane & 15)) * 144 + (lane >> 4) * 16;
    const uint32_t b_base = sb + 18432
        + (nw * 64 + ((lane >> 4) << 3) + (lane & 7)) * 144 + ((lane >> 3) & 1) * 16;

    issue(0);
    issue(1);

    for (int t = 0; t < NT; t++) {
        if (t + 1 < NT) { CP_WAIT1(); } else { CP_WAIT0(); }
        __syncthreads();               // buf t ready; all warps past compute(t-1)
        if (t + 2 < NT) issue(t + 2);  // overwrites buf (t-1)%3 — safe post-sync

        const uint32_t boff = (t % 3) * 36864;
#pragma unroll
        for (int ks = 0; ks < 4; ks++) {
            uint32_t af0[4], af1[4];
            ldsm4(af0, a_base + boff + ks * 32);
            ldsm4(af1, a_base + boff + 2304 + ks * 32);
#pragma unroll
            for (int np = 0; np < 4; np++) {
                uint32_t bf[4];
                ldsm4(bf, b_base + boff + np * 2304 + ks * 32);
                mma16(acc[0][np * 2],     af0, bf);
                mma16(acc[0][np * 2 + 1], af0, bf + 2);
                mma16(acc[1][np * 2],     af1, bf);
                mma16(acc[1][np * 2 + 1], af1, bf + 2);
            }
        }
    }

    // Epilogue
#pragma unroll
    for (int mi = 0; mi < 2; mi++) {
        int r = bm + mw * 32 + mi * 16 + lr;
#pragma unroll
        for (int ni = 0; ni < 8; ni++) {
            int cc = bn + nw * 64 + ni * 8 + 2 * lc;
            float b0 = bias ? bias[cc] : 0.f;
            float b1 = bias ? bias[cc + 1] : 0.f;
            float v00 = acc[mi][ni][0] + b0, v01 = acc[mi][ni][1] + b1;
            float v10 = acc[mi][ni][2] + b0, v11 = acc[mi][ni][3] + b1;
            if (HOUT) {
                __half* C = (__half*)Cout;
                __half2 h0 = __floats2half2_rn(v00, v01);
                __half2 h1 = __floats2half2_rn(v10, v11);
                *(__half2*)(C + (size_t)r * N + cc)       = h0;
                *(__half2*)(C + (size_t)(r + 8) * N + cc) = h1;
            } else {
                float* C = (float*)Cout;
                *(float2*)(C + (size_t)r * N + cc)       = make_float2(v00, v01);
                *(float2*)(C + (size_t)(r + 8) * N + cc) = make_float2(v10, v11);
            }
        }
    }
}

// ---------------------------------------------------------------------------
// RoPE + repack from fused projection buffer (table-based, memory-bound).
// ---------------------------------------------------------------------------
__global__ void rope_h()
{
    const int QTOT = NTOK * NHEADS * 64;   // rotation pairs
    const int KTOT = NTOK * NKV * 64;
    const int VTOT = NTOK * NKV * 64;      // half2 copies
    const float scale = 0.08838834764831845f;

    int idx = blockIdx.x * blockDim.x + threadIdx.x;
    if (idx < QTOT) {
        int i = idx & 63;
        int h = (idx >> 6) & 15;
        int t = idx >> 10;
        int s = t & (SEQ - 1), b = t >> 11;
        const __half* src = g_qkv16 + (size_t)t * QKVN + h * HDIM + i;
        float x1 = __half2float(src[0]);
        float x2 = __half2float(src[64]);
        float2 cssn = g_rope_tab[s * 64 + i];
        size_t dst = ((size_t)(b * NHEADS + h) * SEQ + s) * HDIM + i;
        g_qh[dst]      = __float2half_rn((x1 * cssn.x - x2 * cssn.y) * scale);
        g_qh[dst + 64] = __float2half_rn((x2 * cssn.x + x1 * cssn.y) * scale);
    } else if (idx < QTOT + KTOT) {
        int j = idx - QTOT;
        int i = j & 63;
        int kvh = (j >> 6) & 3;
        int t = j >> 8;
        int s = t & (SEQ - 1), b = t >> 11;
        const __half* src = g_qkv16 + (size_t)t * QKVN + EMBED + kvh * HDIM + i;
        float x1 = __half2float(src[0]);
        float x2 = __half2float(src[64]);
        float2 cssn = g_rope_tab[s * 64 + i];
        size_t dst = ((size_t)(b * NKV + kvh) * SEQ + s) * HDIM + i;
        g_kh[dst]      = __float2half_rn(x1 * cssn.x - x2 * cssn.y);
        g_kh[dst + 64] = __float2half_rn(x2 * cssn.x + x1 * cssn.y);
    } else if (idx < QTOT + KTOT + VTOT) {
        int j = idx - QTOT - KTOT;
        int d2 = j & 63;
        int rest = j >> 6;
        int kvh = rest & 3;
        int t = rest >> 2;
        int s = t & (SEQ - 1), b = t >> 11;
        const __half2* src = (const __half2*)(g_qkv16 + (size_t)t * QKVN + EMBED + 512 + kvh * HDIM);
        __half2* dst = (__half2*)(g_vh + ((size_t)(b * NKV + kvh) * SEQ + s) * HDIM);
        dst[d2] = src[d2];
    }
}

// ---------------------------------------------------------------------------
// Flash attention fp16: 128 q-rows/CTA, 8 warp row-strips, register-P.
// 2-stage K/V cp.async pipeline (smem 104448 B -> 2 CTAs/SM), regs capped
// at 128 via launch_bounds for 2-CTA occupancy. Single sync per kv-tile:
//   wait0 -> sync -> issue(kt+1) -> compute(kt)
// smem: Qs[128][272B] | Ks 2x[64][272B] | Vs 2x[64][272B] = 104448 B
// ---------------------------------------------------------------------------
#define AT_QS 0
#define AT_KS 34816
#define AT_VS 69632
#define AT_SMEM 104448

__global__ __launch_bounds__(256, 2) void attn_h()
{
    extern __shared__ char smc[];
    const uint32_t sb = smem_to_u32(smc);

    const int q0   = blockIdx.x * 128;
    const int h    = blockIdx.y;
    const int b    = blockIdx.z;
    const int kvh  = h >> 2;
    const int tid  = threadIdx.x;
    const int lane = tid & 31;
    const int w    = tid >> 5;
    const int lr   = lane >> 2;
    const int lc   = lane & 3;

    const __half* qsrc = g_qh + ((size_t)(b * NHEADS + h) * SEQ + q0) * HDIM;
    const __half* ksrc = g_kh + (size_t)(b * NKV + kvh) * SEQ * HDIM;
    const __half* vsrc = g_vh + (size_t)(b * NKV + kvh) * SEQ * HDIM;

    auto issue_kv = [&](int kt) {
        const int buf = kt & 1;
        const int kv0 = kt * 64;
#pragma unroll
        for (int i = 0; i < 4; i++) {
            int slot = tid + i * 256;
            int r = slot >> 4, c = slot & 15;
            cp16(sb + AT_KS + buf * 17408 + r * 272 + c * 16,
                 ksrc + (size_t)(kv0 + r) * HDIM + c * 8);
            cp16(sb + AT_VS + buf * 17408 + r * 272 + c * 16,
                 vsrc + (size_t)(kv0 + r) * HDIM + c * 8);
        }
        CP_COMMIT();
    };

    // Prologue: Q + KV tile 0 in one group
#pragma unroll
    for (int i = 0; i < 8; i++) {
        int slot = tid + i * 256;
        int r = slot >> 4, c = slot & 15;
        cp16(sb + AT_QS + r * 272 + c * 16, qsrc + (size_t)r * HDIM + c * 8);
    }
#pragma unroll
    for (int i = 0; i < 4; i++) {
        int slot = tid + i * 256;
        int r = slot >> 4, c = slot & 15;
        cp16(sb + AT_KS + r * 272 + c * 16, ksrc + (size_t)r * HDIM + c * 8);
        cp16(sb + AT_VS + r * 272 + c * 16, vsrc + (size_t)r * HDIM + c * 8);
    }
    CP_COMMIT();

    const uint32_t q_base = sb + AT_QS + (w * 16 + (lane & 15)) * 272 + (lane >> 4) * 16;
    const uint32_t k_base = sb + AT_KS
        + (((lane >> 4) << 3) + (lane & 7)) * 272 + ((lane >> 3) & 1) * 16;
    const uint32_t v_base = sb + AT_VS + (lane & 15) * 272 + (lane >> 4) * 16;

    float m0 = -INFINITY, m1 = -INFINITY, l0 = 0.f, l1 = 0.f;
    float o_acc[16][4];
#pragma unroll
    for (int ni = 0; ni < 16; ni++)
#pragma unroll
        for (int c = 0; c < 4; c++) o_acc[ni][c] = 0.f;

    const int NT = SEQ / 64;   // 32
    for (int kt = 0; kt < NT; kt++) {
        CP_WAIT0();
        __syncthreads();                   // buf kt ready; all warps past kt-1
        if (kt + 1 < NT) issue_kv(kt + 1); // fills buf (kt+1)&1, read-done via sync

        const uint32_t kb = (kt & 1) * 17408;

        // S = Q @ K^T
        float sfr[8][4];
#pragma unroll
        for (int ni = 0; ni < 8; ni++)
#pragma unroll
            for (int c = 0; c < 4; c++) sfr[ni][c] = 0.f;

#pragma unroll
        for (int ks = 0; ks < 8; ks++) {
            uint32_t af[4];
            ldsm4(af, q_base + ks * 32);
#pragma unroll
            for (int np = 0; np < 4; np++) {
                uint32_t bf[4];
                ldsm4(bf, k_base + kb + np * 4352 + ks * 32);
                mma16(sfr[np * 2],     af, bf);
                mma16(sfr[np * 2 + 1], af, bf + 2);
            }
        }

        // Warp-local online softmax
        float mx0 = -INFINITY, mx1 = -INFINITY;
#pragma unroll
        for (int ni = 0; ni < 8; ni++) {
            mx0 = fmaxf(mx0, fmaxf(sfr[ni][0], sfr[ni][1]));
            mx1 = fmaxf(mx1, fmaxf(sfr[ni][2], sfr[ni][3]));
        }
        mx0 = fmaxf(mx0, __shfl_xor_sync(0xffffffffu, mx0, 1));
        mx0 = fmaxf(mx0, __shfl_xor_sync(0xffffffffu, mx0, 2));
        mx1 = fmaxf(mx1, __shfl_xor_sync(0xffffffffu, mx1, 1));
        mx1 = fmaxf(mx1, __shfl_xor_sync(0xffffffffu, mx1, 2));

        float mn0 = fmaxf(m0, mx0);
        float mn1 = fmaxf(m1, mx1);
        float corr0 = __expf(m0 - mn0);
        float corr1 = __expf(m1 - mn1);
        m0 = mn0; m1 = mn1;

        // exp + pack P into PV A-fragments (registers only)
        uint32_t pf[4][4];
        float s0 = 0.f, s1 = 0.f;
#pragma unroll
        for (int ni = 0; ni < 8; ni++) {
            float p00 = __expf(sfr[ni][0] - mn0);
            float p01 = __expf(sfr[ni][1] - mn0);
            float p10 = __expf(sfr[ni][2] - mn1);
            float p11 = __expf(sfr[ni][3] - mn1);
            s0 += p00 + p01; s1 += p10 + p11;
            __half2 h0 = __floats2half2_rn(p00, p01);
            __half2 h1 = __floats2half2_rn(p10, p11);
            pf[ni >> 1][((ni & 1) << 1)]     = *(uint32_t*)&h0;
            pf[ni >> 1][((ni & 1) << 1) + 1] = *(uint32_t*)&h1;
        }
        s0 += __shfl_xor_sync(0xffffffffu, s0, 1);
        s0 += __shfl_xor_sync(0xffffffffu, s0, 2);
        s1 += __shfl_xor_sync(0xffffffffu, s1, 1);
        s1 += __shfl_xor_sync(0xffffffffu, s1, 2);
        l0 = l0 * corr0 + s0;
        l1 = l1 * corr1 + s1;

        // Rescale + O += P @ V
#pragma unroll
        for (int ni = 0; ni < 16; ni++) {
            o_acc[ni][0] *= corr0; o_acc[ni][1] *= corr0;
            o_acc[ni][2] *= corr1; o_acc[ni][3] *= corr1;
        }
#pragma unroll
        for (int ks = 0; ks < 4; ks++) {
#pragma unroll
            for (int np = 0; np < 8; np++) {
                uint32_t bf[4];
                ldsm4t(bf, v_base + kb + ks * 4352 + np * 32);
                mma16(o_acc[np * 2],     pf[ks], bf);
                mma16(o_acc[np * 2 + 1], pf[ks], bf + 2);
            }
        }
    }

    // Normalize + write g_oh (fp16, token-major)
    float inv0 = 1.0f / l0;
    float inv1 = 1.0f / l1;
    int row = b * SEQ + q0 + w * 16 + lr;
#pragma unroll
    for (int ni = 0; ni < 16; ni++) {
        int d = ni * 8 + 2 * lc;
        __half2 h0 = __floats2half2_rn(o_acc[ni][0] * inv0, o_acc[ni][1] * inv0);
        __half2 h1 = __floats2half2_rn(o_acc[ni][2] * inv1, o_acc[ni][3] * inv1);
        *(__half2*)(g_oh + (size_t)row * EMBED + h * HDIM + d)       = h0;
        *(__half2*)(g_oh + (size_t)(row + 8) * EMBED + h * HDIM + d) = h1;
    }
}

// ---------------------------------------------------------------------------
extern "C" void kernel_launch(void* const* d_in, const int* in_sizes, int n_in,
                              void* d_out, int out_size)
{
    const float* x   = (const float*)d_in[0];
    const float* Wq  = (const float*)d_in[1];
    const float* bq  = (const float*)d_in[2];
    const float* Wkv = (const float*)d_in[3];
    const float* bkv = (const float*)d_in[4];
    const float* Wo  = (const float*)d_in[5];
    float* out = (float*)d_out;

    __half *xh, *wh, *woh, *qkv16, *oh;
    float* bqkv;
    cudaGetSymbolAddress((void**)&xh,    g_xh);
    cudaGetSymbolAddress((void**)&wh,    g_wh);
    cudaGetSymbolAddress((void**)&woh,   g_woh);
    cudaGetSymbolAddress((void**)&qkv16, g_qkv16);
    cudaGetSymbolAddress((void**)&oh,    g_oh);
    cudaGetSymbolAddress((void**)&bqkv,  g_bqkv);

    const int GEMM_SMEM = 110592;
    cudaFuncSetAttribute(gemm_h<true>,  cudaFuncAttributeMaxDynamicSharedMemorySize, GEMM_SMEM);
    cudaFuncSetAttribute(gemm_h<false>, cudaFuncAttributeMaxDynamicSharedMemorySize, GEMM_SMEM);
    cudaFuncSetAttribute(attn_h, cudaFuncAttributeMaxDynamicSharedMemorySize, AT_SMEM);

    // 0) conversions + rope table + stacked bias (single launch)
    {
        int total = (NTOK * EMBED + 2 * EMBED * EMBED + KVDIM * EMBED) / 4
                  + SEQ * 64 + QKVN;
        prep_all<<<(total + 255) / 256, 256>>>((const float4*)x, (const float4*)Wq,
                                               (const float4*)Wkv, (const float4*)Wo,
                                               bq, bkv);
    }
    // 1) fused qkv = x @ [Wq;Wkv]^T + [bq;bkv]  (fp16 out)
    gemm_h<true><<<dim3(QKVN/128, NTOK/128), 256, GEMM_SMEM>>>(xh, wh, bqkv, qkv16, NTOK, QKVN, EMBED);
    // 2) RoPE + repack (table-based)
    {
        int total = NTOK*NHEADS*64 + NTOK*NKV*64 + NTOK*NKV*64;
        rope_h<<<(total + 255) / 256, 256>>>();
    }
    // 3) flash attention -> g_oh  (2 CTAs/SM)
    attn_h<<<dim3(SEQ/128, NHEADS, BATCH), 256, AT_SMEM>>>();
    // 4) out = o @ Wo^T  (fp32 out)
    gemm_h<false><<<dim3(EMBED/128, NTOK/128), 256, GEMM_SMEM>>>(oh, woh, nullptr, out, NTOK, EMBED, EMBED);
}

// round 13
// speedup vs baseline: 12.9354x; 1.0505x over previous
#include <cuda_runtime.h>
#include <cuda_fp16.h>
#include <math.h>
#include <stdint.h>

#define EMBED   2048
#define NHEADS  16
#define NKV     4
#define HDIM    128
#define BATCH   2
#define SEQ     2048
#define NTOK    (BATCH*SEQ)      // 4096
#define KVDIM   1024             // k(512) + v(512)
#define QKVN    (EMBED + KVDIM)  // 3072 fused projection width

// fp16 scratch
__device__ __half g_xh   [NTOK * EMBED];
__device__ __half g_wh   [QKVN * EMBED];    // Wq rows 0..2047, Wkv rows 2048..3071
__device__ __half g_woh  [EMBED * EMBED];
__device__ __half g_qkv16[NTOK * QKVN];     // fused projection out (pre-rope)
__device__ __half g_qh   [NTOK * EMBED];    // [b][h][s][d], rope'd + scaled
__device__ __half g_kh   [NTOK * 512];      // [b][kvh][s][d], rope'd
__device__ __half g_vh   [NTOK * 512];      // [b][kvh][s][d]
__device__ __half g_oh   [NTOK * EMBED];    // attention out (token-major)
// aux
__device__ float2 g_rope_tab[SEQ * 64];     // (cos, sin) per (s, i)
__device__ float  g_bqkv[QKVN];             // stacked bias

// ---------------------------------------------------------------------------
// PTX helpers (baseline sm_80+ features only)
// ---------------------------------------------------------------------------
__device__ __forceinline__ uint32_t smem_to_u32(const void* p) {
    uint32_t a;
    asm("{ .reg .u64 t; cvta.to.shared.u64 t, %1; cvt.u32.u64 %0, t; }" : "=r"(a) : "l"(p));
    return a;
}

__device__ __forceinline__ void mma16(float c[4], const uint32_t a[4], const uint32_t b[2]) {
    asm volatile(
        "mma.sync.aligned.m16n8k16.row.col.f32.f16.f16.f32 "
        "{%0,%1,%2,%3},{%4,%5,%6,%7},{%8,%9},{%0,%1,%2,%3};"
        : "+f"(c[0]), "+f"(c[1]), "+f"(c[2]), "+f"(c[3])
        : "r"(a[0]), "r"(a[1]), "r"(a[2]), "r"(a[3]), "r"(b[0]), "r"(b[1]));
}

__device__ __forceinline__ void ldsm4(uint32_t r[4], uint32_t addr) {
    asm volatile("ldmatrix.sync.aligned.m8n8.x4.shared.b16 {%0,%1,%2,%3}, [%4];"
        : "=r"(r[0]), "=r"(r[1]), "=r"(r[2]), "=r"(r[3]) : "r"(addr));
}

__device__ __forceinline__ void ldsm4t(uint32_t r[4], uint32_t addr) {
    asm volatile("ldmatrix.sync.aligned.m8n8.x4.trans.shared.b16 {%0,%1,%2,%3}, [%4];"
        : "=r"(r[0]), "=r"(r[1]), "=r"(r[2]), "=r"(r[3]) : "r"(addr));
}

__device__ __forceinline__ void cp16(uint32_t dst, const void* src) {
    asm volatile("cp.async.cg.shared.global [%0], [%1], 16;" :: "r"(dst), "l"(src));
}
#define CP_COMMIT() asm volatile("cp.async.commit_group;" ::: "memory")
#define CP_WAIT0()  asm volatile("cp.async.wait_group 0;" ::: "memory")
#define CP_WAIT1()  asm volatile("cp.async.wait_group 1;" ::: "memory")

// ---------------------------------------------------------------------------
// Fused prep: fp32->fp16 of x, Wq|Wkv (packed), Wo; RoPE table; stacked bias.
// ---------------------------------------------------------------------------
__global__ void prep_all(const float4* __restrict__ x,  const float4* __restrict__ wq,
                         const float4* __restrict__ wkv, const float4* __restrict__ wo,
                         const float* __restrict__ bq,  const float* __restrict__ bkv)
{
    const int n_x   = NTOK * EMBED / 4;
    const int n_wq  = EMBED * EMBED / 4;
    const int n_wkv = KVDIM * EMBED / 4;
    const int n_wo  = EMBED * EMBED / 4;
    const int n_tab = SEQ * 64;
    int i = blockIdx.x * blockDim.x + threadIdx.x;

    int base = 0;
    if (i < (base += n_x)) {
        int j = i;
        float4 v = x[j];
        __half2 h0 = __floats2half2_rn(v.x, v.y), h1 = __floats2half2_rn(v.z, v.w);
        ((uint2*)g_xh)[j] = make_uint2(*(uint32_t*)&h0, *(uint32_t*)&h1);
    } else if (i < (base += n_wq)) {
        int j = i - (base - n_wq);
        float4 v = wq[j];
        __half2 h0 = __floats2half2_rn(v.x, v.y), h1 = __floats2half2_rn(v.z, v.w);
        ((uint2*)g_wh)[j] = make_uint2(*(uint32_t*)&h0, *(uint32_t*)&h1);
    } else if (i < (base += n_wkv)) {
        int j = i - (base - n_wkv);
        float4 v = wkv[j];
        __half2 h0 = __floats2half2_rn(v.x, v.y), h1 = __floats2half2_rn(v.z, v.w);
        ((uint2*)(g_wh + (size_t)EMBED * EMBED))[j] = make_uint2(*(uint32_t*)&h0, *(uint32_t*)&h1);
    } else if (i < (base += n_wo)) {
        int j = i - (base - n_wo);
        float4 v = wo[j];
        __half2 h0 = __floats2half2_rn(v.x, v.y), h1 = __floats2half2_rn(v.z, v.w);
        ((uint2*)g_woh)[j] = make_uint2(*(uint32_t*)&h0, *(uint32_t*)&h1);
    } else if (i < (base += n_tab)) {
        int j = i - (base - n_tab);
        int s = j >> 6, d = j & 63;
        float freq = powf(10000.0f, -(float)d * (1.0f / 64.0f));
        float sn, cs; sincosf((float)s * freq, &sn, &cs);
        g_rope_tab[j] = make_float2(cs, sn);
    } else if (i < (base += QKVN)) {
        int j = i - (base - QKVN);
        g_bqkv[j] = (j < EMBED) ? bq[j] : bkv[j - EMBED];
    }
}

// ---------------------------------------------------------------------------
// GEMM: C[M,N] = A[M,K](fp16) @ W[N,K]^T(fp16) + bias.  HOUT: fp16 vs fp32 C.
// CTA 128x128, BK=64, 8 warps, 3-stage cp.async, single sync per k-tile.
// (unchanged from R12)
// ---------------------------------------------------------------------------
template <bool HOUT>
__global__ __launch_bounds__(256, 2) void gemm_h(
    const __half* __restrict__ A, const __half* __restrict__ W,
    const float* __restrict__ bias, void* __restrict__ Cout,
    int M, int N, int K)
{
    extern __shared__ char smc[];
    const uint32_t sb = smem_to_u32(smc);

    const int bm   = blockIdx.y * 128;
    const int bn   = blockIdx.x * 128;
    const int tid  = threadIdx.x;
    const int lane = tid & 31;
    const int w    = tid >> 5;
    const int mw   = w & 3;
    const int nw   = w >> 2;
    const int lr   = lane >> 2;
    const int lc   = lane & 3;

    float acc[2][8][4];
#pragma unroll
    for (int mi = 0; mi < 2; mi++)
#pragma unroll
        for (int ni = 0; ni < 8; ni++)
#pragma unroll
            for (int c = 0; c < 4; c++) acc[mi][ni][c] = 0.f;

    const int NT = K / 64;

    auto issue = [&](int t) {
        const int buf = t % 3;
        const int kb  = t * 64;
        uint32_t abuf = sb + buf * 36864;
        uint32_t bbuf = abuf + 18432;
#pragma unroll
        for (int i = 0; i < 4; i++) {
            int slot = tid + i * 256;
            int r = slot >> 3, c = slot & 7;
            cp16(abuf + r * 144 + c * 16, A + (size_t)(bm + r) * K + kb + c * 8);
            cp16(bbuf + r * 144 + c * 16, W + (size_t)(bn + r) * K + kb + c * 8);
        }
        CP_COMMIT();
    };

    const uint32_t a_base = sb + (mw * 32 + (lane & 15)) * 144 + (lane >> 4) * 16;
    const uint32_t b_base = sb + 18432
        + (nw * 64 + ((lane >> 4) << 3) + (lane & 7)) * 144 + ((lane >> 3) & 1) * 16;

    issue(0);
    issue(1);

    for (int t = 0; t < NT; t++) {
        if (t + 1 < NT) { CP_WAIT1(); } else { CP_WAIT0(); }
        __syncthreads();
        if (t + 2 < NT) issue(t + 2);

        const uint32_t boff = (t % 3) * 36864;
#pragma unroll
        for (int ks = 0; ks < 4; ks++) {
            uint32_t af0[4], af1[4];
            ldsm4(af0, a_base + boff + ks * 32);
            ldsm4(af1, a_base + boff + 2304 + ks * 32);
#pragma unroll
            for (int np = 0; np < 4; np++) {
                uint32_t bf[4];
                ldsm4(bf, b_base + boff + np * 2304 + ks * 32);
                mma16(acc[0][np * 2],     af0, bf);
                mma16(acc[0][np * 2 + 1], af0, bf + 2);
                mma16(acc[1][np * 2],     af1, bf);
                mma16(acc[1][np * 2 + 1], af1, bf + 2);
            }
        }
    }

    // Epilogue
#pragma unroll
    for (int mi = 0; mi < 2; mi++) {
        int r = bm + mw * 32 + mi * 16 + lr;
#pragma unroll
        for (int ni = 0; ni < 8; ni++) {
            int cc = bn + nw * 64 + ni * 8 + 2 * lc;
            float b0 = bias ? bias[cc] : 0.f;
            float b1 = bias ? bias[cc + 1] : 0.f;
            float v00 = acc[mi][ni][0] + b0, v01 = acc[mi][ni][1] + b1;
            float v10 = acc[mi][ni][2] + b0, v11 = acc[mi][ni][3] + b1;
            if (HOUT) {
                __half* C = (__half*)Cout;
                __half2 h0 = __floats2half2_rn(v00, v01);
                __half2 h1 = __floats2half2_rn(v10, v11);
                *(__half2*)(C + (size_t)r * N + cc)       = h0;
                *(__half2*)(C + (size_t)(r + 8) * N + cc) = h1;
            } else {
                float* C = (float*)Cout;
                *(float2*)(C + (size_t)r * N + cc)       = make_float2(v00, v01);
                *(float2*)(C + (size_t)(r + 8) * N + cc) = make_float2(v10, v11);
            }
        }
    }
}

// ---------------------------------------------------------------------------
// RoPE + repack from fused projection buffer (table-based, memory-bound).
// ---------------------------------------------------------------------------
__global__ void rope_h()
{
    const int QTOT = NTOK * NHEADS * 64;   // rotation pairs
    const int KTOT = NTOK * NKV * 64;
    const int VTOT = NTOK * NKV * 64;      // half2 copies
    const float scale = 0.08838834764831845f;

    int idx = blockIdx.x * blockDim.x + threadIdx.x;
    if (idx < QTOT) {
        int i = idx & 63;
        int h = (idx >> 6) & 15;
        int t = idx >> 10;
        int s = t & (SEQ - 1), b = t >> 11;
        const __half* src = g_qkv16 + (size_t)t * QKVN + h * HDIM + i;
        float x1 = __half2float(src[0]);
        float x2 = __half2float(src[64]);
        float2 cssn = g_rope_tab[s * 64 + i];
        size_t dst = ((size_t)(b * NHEADS + h) * SEQ + s) * HDIM + i;
        g_qh[dst]      = __float2half_rn((x1 * cssn.x - x2 * cssn.y) * scale);
        g_qh[dst + 64] = __float2half_rn((x2 * cssn.x + x1 * cssn.y) * scale);
    } else if (idx < QTOT + KTOT) {
        int j = idx - QTOT;
        int i = j & 63;
        int kvh = (j >> 6) & 3;
        int t = j >> 8;
        int s = t & (SEQ - 1), b = t >> 11;
        const __half* src = g_qkv16 + (size_t)t * QKVN + EMBED + kvh * HDIM + i;
        float x1 = __half2float(src[0]);
        float x2 = __half2float(src[64]);
        float2 cssn = g_rope_tab[s * 64 + i];
        size_t dst = ((size_t)(b * NKV + kvh) * SEQ + s) * HDIM + i;
        g_kh[dst]      = __float2half_rn(x1 * cssn.x - x2 * cssn.y);
        g_kh[dst + 64] = __float2half_rn(x2 * cssn.x + x1 * cssn.y);
    } else if (idx < QTOT + KTOT + VTOT) {
        int j = idx - QTOT - KTOT;
        int d2 = j & 63;
        int rest = j >> 6;
        int kvh = rest & 3;
        int t = rest >> 2;
        int s = t & (SEQ - 1), b = t >> 11;
        const __half2* src = (const __half2*)(g_qkv16 + (size_t)t * QKVN + EMBED + 512 + kvh * HDIM);
        __half2* dst = (__half2*)(g_vh + ((size_t)(b * NKV + kvh) * SEQ + s) * HDIM);
        dst[d2] = src[d2];
    }
}

// ---------------------------------------------------------------------------
// Flash attention fp16: 128 q-rows/CTA, **4 warps x 32 q-rows each**.
// Each warp computes its full 32x64 S tile and 32x128 O tile -> K/V fragments
// loaded 4x per CTA instead of 8x (smem traffic x0.6). Softmax warp-local.
// P packed in-place into S fragment registers (half2 overwrite).
// 2-stage K/V cp.async, 128 threads, 2 CTAs/SM (smem 104448 B).
// ---------------------------------------------------------------------------
#define AT_QS 0
#define AT_KS 34816
#define AT_VS 69632
#define AT_SMEM 104448

__global__ __launch_bounds__(128, 2) void attn_h()
{
    extern __shared__ char smc[];
    const uint32_t sb = smem_to_u32(smc);

    const int q0   = blockIdx.x * 128;
    const int h    = blockIdx.y;
    const int b    = blockIdx.z;
    const int kvh  = h >> 2;
    const int tid  = threadIdx.x;     // 0..127
    const int lane = tid & 31;
    const int w    = tid >> 5;        // 0..3, rows [w*32, w*32+32)
    const int lr   = lane >> 2;
    const int lc   = lane & 3;

    const __half* qsrc = g_qh + ((size_t)(b * NHEADS + h) * SEQ + q0) * HDIM;
    const __half* ksrc = g_kh + (size_t)(b * NKV + kvh) * SEQ * HDIM;
    const __half* vsrc = g_vh + (size_t)(b * NKV + kvh) * SEQ * HDIM;

    auto issue_kv = [&](int kt) {
        const int buf = kt & 1;
        const int kv0 = kt * 64;
#pragma unroll
        for (int i = 0; i < 8; i++) {
            int slot = tid + i * 128;        // 0..1023
            int r = slot >> 4, c = slot & 15;
            cp16(sb + AT_KS + buf * 17408 + r * 272 + c * 16,
                 ksrc + (size_t)(kv0 + r) * HDIM + c * 8);
            cp16(sb + AT_VS + buf * 17408 + r * 272 + c * 16,
                 vsrc + (size_t)(kv0 + r) * HDIM + c * 8);
        }
        CP_COMMIT();
    };

    // Prologue: Q + KV tile 0 in one group
#pragma unroll
    for (int i = 0; i < 16; i++) {
        int slot = tid + i * 128;            // 0..2047
        int r = slot >> 4, c = slot & 15;
        cp16(sb + AT_QS + r * 272 + c * 16, qsrc + (size_t)r * HDIM + c * 8);
    }
#pragma unroll
    for (int i = 0; i < 8; i++) {
        int slot = tid + i * 128;
        int r = slot >> 4, c = slot & 15;
        cp16(sb + AT_KS + r * 272 + c * 16, ksrc + (size_t)r * HDIM + c * 8);
        cp16(sb + AT_VS + r * 272 + c * 16, vsrc + (size_t)r * HDIM + c * 8);
    }
    CP_COMMIT();

    // ldmatrix lane bases
    const uint32_t q_base = sb + AT_QS + (w * 32 + (lane & 15)) * 272 + (lane >> 4) * 16;
    const uint32_t k_base = sb + AT_KS
        + (((lane >> 4) << 3) + (lane & 7)) * 272 + ((lane >> 3) & 1) * 16;
    const uint32_t v_base = sb + AT_VS + (lane & 15) * 272 + (lane >> 4) * 16;

    // Softmax state per (mi, row-half): rows w*32 + mi*16 + {lr, lr+8}
    float m00 = -INFINITY, m01 = -INFINITY, m10 = -INFINITY, m11 = -INFINITY;
    float l00 = 0.f, l01 = 0.f, l10 = 0.f, l11 = 0.f;

    float o_acc[2][16][4];
#pragma unroll
    for (int mi = 0; mi < 2; mi++)
#pragma unroll
        for (int ni = 0; ni < 16; ni++)
#pragma unroll
            for (int c = 0; c < 4; c++) o_acc[mi][ni][c] = 0.f;

    const int NT = SEQ / 64;   // 32
    for (int kt = 0; kt < NT; kt++) {
        CP_WAIT0();
        __syncthreads();                   // buf kt ready; all warps past kt-1
        if (kt + 1 < NT) issue_kv(kt + 1);

        const uint32_t kb = (kt & 1) * 17408;

        // S = Q @ K^T : warp rows [w*32,+32) x all 64 kv cols
        float sfr[2][8][4];
#pragma unroll
        for (int mi = 0; mi < 2; mi++)
#pragma unroll
            for (int ni = 0; ni < 8; ni++)
#pragma unroll
                for (int c = 0; c < 4; c++) sfr[mi][ni][c] = 0.f;

#pragma unroll
        for (int ks = 0; ks < 8; ks++) {
            uint32_t af0[4], af1[4];
            ldsm4(af0, q_base + ks * 32);
            ldsm4(af1, q_base + 4352 + ks * 32);   // +16 rows
#pragma unroll
            for (int np = 0; np < 4; np++) {
                uint32_t bf[4];
                ldsm4(bf, k_base + kb + np * 4352 + ks * 32);
                mma16(sfr[0][np * 2],     af0, bf);
                mma16(sfr[0][np * 2 + 1], af0, bf + 2);
                mma16(sfr[1][np * 2],     af1, bf);
                mma16(sfr[1][np * 2 + 1], af1, bf + 2);
            }
        }

        // Warp-local online softmax for 4 row-groups; pack P in-place.
        float corr00, corr01, corr10, corr11;
#pragma unroll
        for (int mi = 0; mi < 2; mi++) {
            float mx0 = -INFINITY, mx1 = -INFINITY;
#pragma unroll
            for (int ni = 0; ni < 8; ni++) {
                mx0 = fmaxf(mx0, fmaxf(sfr[mi][ni][0], sfr[mi][ni][1]));
                mx1 = fmaxf(mx1, fmaxf(sfr[mi][ni][2], sfr[mi][ni][3]));
            }
            mx0 = fmaxf(mx0, __shfl_xor_sync(0xffffffffu, mx0, 1));
            mx0 = fmaxf(mx0, __shfl_xor_sync(0xffffffffu, mx0, 2));
            mx1 = fmaxf(mx1, __shfl_xor_sync(0xffffffffu, mx1, 1));
            mx1 = fmaxf(mx1, __shfl_xor_sync(0xffffffffu, mx1, 2));

            float mold0 = mi ? m10 : m00;
            float mold1 = mi ? m11 : m01;
            float mn0 = fmaxf(mold0, mx0);
            float mn1 = fmaxf(mold1, mx1);
            float c0 = __expf(mold0 - mn0);
            float c1 = __expf(mold1 - mn1);

            float s0 = 0.f, s1 = 0.f;
#pragma unroll
            for (int ni = 0; ni < 8; ni++) {
                float p00 = __expf(sfr[mi][ni][0] - mn0);
                float p01 = __expf(sfr[mi][ni][1] - mn0);
                float p10 = __expf(sfr[mi][ni][2] - mn1);
                float p11 = __expf(sfr[mi][ni][3] - mn1);
                s0 += p00 + p01; s1 += p10 + p11;
                __half2 h0 = __floats2half2_rn(p00, p01);
                __half2 h1 = __floats2half2_rn(p10, p11);
                uint32_t* sp = (uint32_t*)&sfr[mi][ni][0];
                sp[0] = *(uint32_t*)&h0;   // row lr   (k pair)
                sp[1] = *(uint32_t*)&h1;   // row lr+8 (k pair)
            }
            s0 += __shfl_xor_sync(0xffffffffu, s0, 1);
            s0 += __shfl_xor_sync(0xffffffffu, s0, 2);
            s1 += __shfl_xor_sync(0xffffffffu, s1, 1);
            s1 += __shfl_xor_sync(0xffffffffu, s1, 2);

            if (mi == 0) {
                l00 = l00 * c0 + s0; l01 = l01 * c1 + s1;
                m00 = mn0; m01 = mn1; corr00 = c0; corr01 = c1;
            } else {
                l10 = l10 * c0 + s0; l11 = l11 * c1 + s1;
                m10 = mn0; m11 = mn1; corr10 = c0; corr11 = c1;
            }
        }

        // Rescale O accumulators
#pragma unroll
        for (int ni = 0; ni < 16; ni++) {
            o_acc[0][ni][0] *= corr00; o_acc[0][ni][1] *= corr00;
            o_acc[0][ni][2] *= corr01; o_acc[0][ni][3] *= corr01;
            o_acc[1][ni][0] *= corr10; o_acc[1][ni][1] *= corr10;
            o_acc[1][ni][2] *= corr11; o_acc[1][ni][3] *= corr11;
        }

        // O += P @ V : P fragments read from sfr registers (in-place packed)
#pragma unroll
        for (int kk = 0; kk < 4; kk++) {
            uint32_t pa0[4] = { *(uint32_t*)&sfr[0][kk*2][0], *(uint32_t*)&sfr[0][kk*2][1],
                                *(uint32_t*)&sfr[0][kk*2+1][0], *(uint32_t*)&sfr[0][kk*2+1][1] };
            uint32_t pa1[4] = { *(uint32_t*)&sfr[1][kk*2][0], *(uint32_t*)&sfr[1][kk*2][1],
                                *(uint32_t*)&sfr[1][kk*2+1][0], *(uint32_t*)&sfr[1][kk*2+1][1] };
#pragma unroll
            for (int np = 0; np < 8; np++) {
                uint32_t bf[4];
                ldsm4t(bf, v_base + kb + kk * 4352 + np * 32);
                mma16(o_acc[0][np * 2],     pa0, bf);
                mma16(o_acc[0][np * 2 + 1], pa0, bf + 2);
                mma16(o_acc[1][np * 2],     pa1, bf);
                mma16(o_acc[1][np * 2 + 1], pa1, bf + 2);
            }
        }
    }

    // Normalize + write g_oh (fp16, token-major)
    float inv00 = 1.0f / l00, inv01 = 1.0f / l01;
    float inv10 = 1.0f / l10, inv11 = 1.0f / l11;
#pragma unroll
    for (int mi = 0; mi < 2; mi++) {
        float i0 = mi ? inv10 : inv00;
        float i1 = mi ? inv11 : inv01;
        int row = b * SEQ + q0 + w * 32 + mi * 16 + lr;
#pragma unroll
        for (int ni = 0; ni < 16; ni++) {
            int d = ni * 8 + 2 * lc;
            __half2 h0 = __floats2half2_rn(o_acc[mi][ni][0] * i0, o_acc[mi][ni][1] * i0);
            __half2 h1 = __floats2half2_rn(o_acc[mi][ni][2] * i1, o_acc[mi][ni][3] * i1);
            *(__half2*)(g_oh + (size_t)row * EMBED + h * HDIM + d)       = h0;
            *(__half2*)(g_oh + (size_t)(row + 8) * EMBED + h * HDIM + d) = h1;
        }
    }
}

// ---------------------------------------------------------------------------
extern "C" void kernel_launch(void* const* d_in, const int* in_sizes, int n_in,
                              void* d_out, int out_size)
{
    const float* x   = (const float*)d_in[0];
    const float* Wq  = (const float*)d_in[1];
    const float* bq  = (const float*)d_in[2];
    const float* Wkv = (const float*)d_in[3];
    const float* bkv = (const float*)d_in[4];
    const float* Wo  = (const float*)d_in[5];
    float* out = (float*)d_out;

    __half *xh, *wh, *woh, *qkv16, *oh;
    float* bqkv;
    cudaGetSymbolAddress((void**)&xh,    g_xh);
    cudaGetSymbolAddress((void**)&wh,    g_wh);
    cudaGetSymbolAddress((void**)&woh,   g_woh);
    cudaGetSymbolAddress((void**)&qkv16, g_qkv16);
    cudaGetSymbolAddress((void**)&oh,    g_oh);
    cudaGetSymbolAddress((void**)&bqkv,  g_bqkv);

    const int GEMM_SMEM = 110592;
    cudaFuncSetAttribute(gemm_h<true>,  cudaFuncAttributeMaxDynamicSharedMemorySize, GEMM_SMEM);
    cudaFuncSetAttribute(gemm_h<false>, cudaFuncAttributeMaxDynamicSharedMemorySize, GEMM_SMEM);
    cudaFuncSetAttribute(attn_h, cudaFuncAttributeMaxDynamicSharedMemorySize, AT_SMEM);

    // 0) conversions + rope table + stacked bias (single launch)
    {
        int total = (NTOK * EMBED + 2 * EMBED * EMBED + KVDIM * EMBED) / 4
                  + SEQ * 64 + QKVN;
        prep_all<<<(total + 255) / 256, 256>>>((const float4*)x, (const float4*)Wq,
                                               (const float4*)Wkv, (const float4*)Wo,
                                               bq, bkv);
    }
    // 1) fused qkv = x @ [Wq;Wkv]^T + [bq;bkv]  (fp16 out)
    gemm_h<true><<<dim3(QKVN/128, NTOK/128), 256, GEMM_SMEM>>>(xh, wh, bqkv, qkv16, NTOK, QKVN, EMBED);
    // 2) RoPE + repack (table-based)
    {
        int total = NTOK*NHEADS*64 + NTOK*NKV*64 + NTOK*NKV*64;
        rope_h<<<(total + 255) / 256, 256>>>();
    }
    // 3) flash attention -> g_oh  (128 threads, 2 CTAs/SM)
    attn_h<<<dim3(SEQ/128, NHEADS, BATCH), 128, AT_SMEM>>>();
    // 4) out = o @ Wo^T  (fp32 out)
    gemm_h<false><<<dim3(EMBED/128, NTOK/128), 256, GEMM_SMEM>>>(oh, woh, nullptr, out, NTOK, EMBED, EMBED);
}

// round 15
// speedup vs baseline: 13.0970x; 1.0125x over previous
#include <cuda_runtime.h>
#include <cuda_fp16.h>
#include <math.h>
#include <stdint.h>

#define EMBED   2048
#define NHEADS  16
#define NKV     4
#define HDIM    128
#define BATCH   2
#define SEQ     2048
#define NTOK    (BATCH*SEQ)      // 4096
#define KVDIM   1024             // k(512) + v(512)
#define QKVN    (EMBED + KVDIM)  // 3072 fused projection width

// fp16 scratch
__device__ __half g_xh   [NTOK * EMBED];
__device__ __half g_wh   [QKVN * EMBED];    // Wq rows 0..2047, Wkv rows 2048..3071
__device__ __half g_woh  [EMBED * EMBED];
__device__ __half g_qkv16[NTOK * QKVN];     // fused projection out (pre-rope)
__device__ __half g_qh   [NTOK * EMBED];    // [b][h][s][d], rope'd + scaled*log2e
__device__ __half g_kh   [NTOK * 512];      // [b][kvh][s][d], rope'd
__device__ __half g_vh   [NTOK * 512];      // [b][kvh][s][d]
__device__ __half g_oh   [NTOK * EMBED];    // attention out (token-major)
// aux
__device__ float2 g_rope_tab[SEQ * 64];     // (cos, sin) per (s, i)
__device__ float  g_bqkv[QKVN];             // stacked bias

// ---------------------------------------------------------------------------
// PTX helpers (baseline sm_80+ features only)
// ---------------------------------------------------------------------------
__device__ __forceinline__ uint32_t smem_to_u32(const void* p) {
    uint32_t a;
    asm("{ .reg .u64 t; cvta.to.shared.u64 t, %1; cvt.u32.u64 %0, t; }" : "=r"(a) : "l"(p));
    return a;
}

__device__ __forceinline__ void mma16(float c[4], const uint32_t a[4], const uint32_t b[2]) {
    asm volatile(
        "mma.sync.aligned.m16n8k16.row.col.f32.f16.f16.f32 "
        "{%0,%1,%2,%3},{%4,%5,%6,%7},{%8,%9},{%0,%1,%2,%3};"
        : "+f"(c[0]), "+f"(c[1]), "+f"(c[2]), "+f"(c[3])
        : "r"(a[0]), "r"(a[1]), "r"(a[2]), "r"(a[3]), "r"(b[0]), "r"(b[1]));
}

__device__ __forceinline__ void ldsm4(uint32_t r[4], uint32_t addr) {
    asm volatile("ldmatrix.sync.aligned.m8n8.x4.shared.b16 {%0,%1,%2,%3}, [%4];"
        : "=r"(r[0]), "=r"(r[1]), "=r"(r[2]), "=r"(r[3]) : "r"(addr));
}

__device__ __forceinline__ void ldsm4t(uint32_t r[4], uint32_t addr) {
    asm volatile("ldmatrix.sync.aligned.m8n8.x4.trans.shared.b16 {%0,%1,%2,%3}, [%4];"
        : "=r"(r[0]), "=r"(r[1]), "=r"(r[2]), "=r"(r[3]) : "r"(addr));
}

__device__ __forceinline__ void cp16(uint32_t dst, const void* src) {
    asm volatile("cp.async.cg.shared.global [%0], [%1], 16;" :: "r"(dst), "l"(src));
}
#define CP_COMMIT() asm volatile("cp.async.commit_group;" ::: "memory")
#define CP_WAIT0()  asm volatile("cp.async.wait_group 0;" ::: "memory")
#define CP_WAIT1()  asm volatile("cp.async.wait_group 1;" ::: "memory")

__device__ __forceinline__ float ex2f(float x) {
    float r; asm("ex2.approx.f32 %0, %1;" : "=f"(r) : "f"(x)); return r;
}
__device__ __forceinline__ uint32_t h2exp2u(uint32_t x) {
    uint32_t r; asm("ex2.approx.f16x2 %0, %1;" : "=r"(r) : "r"(x)); return r;
}
__device__ __forceinline__ uint32_t pack_h2(float a, float b) {
    __half2 h = __floats2half2_rn(a, b);
    return *(uint32_t*)&h;
}

// ---------------------------------------------------------------------------
// Fused prep: fp32->fp16 of x, Wq|Wkv (packed), Wo; RoPE table; stacked bias.
// ---------------------------------------------------------------------------
__global__ void prep_all(const float4* __restrict__ x,  const float4* __restrict__ wq,
                         const float4* __restrict__ wkv, const float4* __restrict__ wo,
                         const float* __restrict__ bq,  const float* __restrict__ bkv)
{
    const int n_x   = NTOK * EMBED / 4;
    const int n_wq  = EMBED * EMBED / 4;
    const int n_wkv = KVDIM * EMBED / 4;
    const int n_wo  = EMBED * EMBED / 4;
    const int n_tab = SEQ * 64;
    int i = blockIdx.x * blockDim.x + threadIdx.x;

    int base = 0;
    if (i < (base += n_x)) {
        int j = i;
        float4 v = x[j];
        __half2 h0 = __floats2half2_rn(v.x, v.y), h1 = __floats2half2_rn(v.z, v.w);
        ((uint2*)g_xh)[j] = make_uint2(*(uint32_t*)&h0, *(uint32_t*)&h1);
    } else if (i < (base += n_wq)) {
        int j = i - (base - n_wq);
        float4 v = wq[j];
        __half2 h0 = __floats2half2_rn(v.x, v.y), h1 = __floats2half2_rn(v.z, v.w);
        ((uint2*)g_wh)[j] = make_uint2(*(uint32_t*)&h0, *(uint32_t*)&h1);
    } else if (i < (base += n_wkv)) {
        int j = i - (base - n_wkv);
        float4 v = wkv[j];
        __half2 h0 = __floats2half2_rn(v.x, v.y), h1 = __floats2half2_rn(v.z, v.w);
        ((uint2*)(g_wh + (size_t)EMBED * EMBED))[j] = make_uint2(*(uint32_t*)&h0, *(uint32_t*)&h1);
    } else if (i < (base += n_wo)) {
        int j = i - (base - n_wo);
        float4 v = wo[j];
        __half2 h0 = __floats2half2_rn(v.x, v.y), h1 = __floats2half2_rn(v.z, v.w);
        ((uint2*)g_woh)[j] = make_uint2(*(uint32_t*)&h0, *(uint32_t*)&h1);
    } else if (i < (base += n_tab)) {
        int j = i - (base - n_tab);
        int s = j >> 6, d = j & 63;
        float freq = powf(10000.0f, -(float)d * (1.0f / 64.0f));
        float sn, cs; sincosf((float)s * freq, &sn, &cs);
        g_rope_tab[j] = make_float2(cs, sn);
    } else if (i < (base += QKVN)) {
        int j = i - (base - QKVN);
        g_bqkv[j] = (j < EMBED) ? bq[j] : bkv[j - EMBED];
    }
}

// ---------------------------------------------------------------------------
// GEMM: C[M,N] = A[M,K](fp16) @ W[N,K]^T(fp16) + bias.  HOUT: fp16 vs fp32 C.
// CTA 128x128, BK=64, 8 warps, 3-stage cp.async, single sync per k-tile.
// ---------------------------------------------------------------------------
template <bool HOUT>
__global__ __launch_bounds__(256, 2) void gemm_h(
    const __half* __restrict__ A, const __half* __restrict__ W,
    const float* __restrict__ bias, void* __restrict__ Cout,
    int M, int N, int K)
{
    extern __shared__ char smc[];
    const uint32_t sb = smem_to_u32(smc);

    const int bm   = blockIdx.y * 128;
    const int bn   = blockIdx.x * 128;
    const int tid  = threadIdx.x;
    const int lane = tid & 31;
    const int w    = tid >> 5;
    const int mw   = w & 3;
    const int nw   = w >> 2;
    const int lr   = lane >> 2;
    const int lc   = lane & 3;

    float acc[2][8][4];
#pragma unroll
    for (int mi = 0; mi < 2; mi++)
#pragma unroll
        for (int ni = 0; ni < 8; ni++)
#pragma unroll
            for (int c = 0; c < 4; c++) acc[mi][ni][c] = 0.f;

    const int NT = K / 64;

    auto issue = [&](int t) {
        const int buf = t % 3;
        const int kb  = t * 64;
        uint32_t abuf = sb + buf * 36864;
        uint32_t bbuf = abuf + 18432;
#pragma unroll
        for (int i = 0; i < 4; i++) {
            int slot = tid + i * 256;
            int r = slot >> 3, c = slot & 7;
            cp16(abuf + r * 144 + c * 16, A + (size_t)(bm + r) * K + kb + c * 8);
            cp16(bbuf + r * 144 + c * 16, W + (size_t)(bn + r) * K + kb + c * 8);
        }
        CP_COMMIT();
    };

    const uint32_t a_base = sb + (mw * 32 + (lane & 15)) * 144 + (lane >> 4) * 16;
    const uint32_t b_base = sb + 18432
        + (nw * 64 + ((lane >> 4) << 3) + (lane & 7)) * 144 + ((lane >> 3) & 1) * 16;

    issue(0);
    issue(1);

    for (int t = 0; t < NT; t++) {
        if (t + 1 < NT) { CP_WAIT1(); } else { CP_WAIT0(); }
        __syncthreads();
        if (t + 2 < NT) issue(t + 2);

        const uint32_t boff = (t % 3) * 36864;
#pragma unroll
        for (int ks = 0; ks < 4; ks++) {
            uint32_t af0[4], af1[4];
            ldsm4(af0, a_base + boff + ks * 32);
            ldsm4(af1, a_base + boff + 2304 + ks * 32);
#pragma unroll
            for (int np = 0; np < 4; np++) {
                uint32_t bf[4];
                ldsm4(bf, b_base + boff + np * 2304 + ks * 32);
                mma16(acc[0][np * 2],     af0, bf);
                mma16(acc[0][np * 2 + 1], af0, bf + 2);
                mma16(acc[1][np * 2],     af1, bf);
                mma16(acc[1][np * 2 + 1], af1, bf + 2);
            }
        }
    }

    // Epilogue
#pragma unroll
    for (int mi = 0; mi < 2; mi++) {
        int r = bm + mw * 32 + mi * 16 + lr;
#pragma unroll
        for (int ni = 0; ni < 8; ni++) {
            int cc = bn + nw * 64 + ni * 8 + 2 * lc;
            float b0 = bias ? bias[cc] : 0.f;
            float b1 = bias ? bias[cc + 1] : 0.f;
            float v00 = acc[mi][ni][0] + b0, v01 = acc[mi][ni][1] + b1;
            float v10 = acc[mi][ni][2] + b0, v11 = acc[mi][ni][3] + b1;
            if (HOUT) {
                __half* C = (__half*)Cout;
                __half2 h0 = __floats2half2_rn(v00, v01);
                __half2 h1 = __floats2half2_rn(v10, v11);
                *(__half2*)(C + (size_t)r * N + cc)       = h0;
                *(__half2*)(C + (size_t)(r + 8) * N + cc) = h1;
            } else {
                float* C = (float*)Cout;
                *(float2*)(C + (size_t)r * N + cc)       = make_float2(v00, v01);
                *(float2*)(C + (size_t)(r + 8) * N + cc) = make_float2(v10, v11);
            }
        }
    }
}

// ---------------------------------------------------------------------------
// RoPE + repack. Q scaled by (1/sqrt(128))*log2(e) for base-2 softmax.
// ---------------------------------------------------------------------------
__global__ void rope_h()
{
    const int QTOT = NTOK * NHEADS * 64;
    const int KTOT = NTOK * NKV * 64;
    const int VTOT = NTOK * NKV * 64;
    const float scale = 0.12751742522f;   // (1/sqrt(128)) * log2(e)

    int idx = blockIdx.x * blockDim.x + threadIdx.x;
    if (idx < QTOT) {
        int i = idx & 63;
        int h = (idx >> 6) & 15;
        int t = idx >> 10;
        int s = t & (SEQ - 1), b = t >> 11;
        const __half* src = g_qkv16 + (size_t)t * QKVN + h * HDIM + i;
        float x1 = __half2float(src[0]);
        float x2 = __half2float(src[64]);
        float2 cssn = g_rope_tab[s * 64 + i];
        size_t dst = ((size_t)(b * NHEADS + h) * SEQ + s) * HDIM + i;
        g_qh[dst]      = __float2half_rn((x1 * cssn.x - x2 * cssn.y) * scale);
        g_qh[dst + 64] = __float2half_rn((x2 * cssn.x + x1 * cssn.y) * scale);
    } else if (idx < QTOT + KTOT) {
        int j = idx - QTOT;
        int i = j & 63;
        int kvh = (j >> 6) & 3;
        int t = j >> 8;
        int s = t & (SEQ - 1), b = t >> 11;
        const __half* src = g_qkv16 + (size_t)t * QKVN + EMBED + kvh * HDIM + i;
        float x1 = __half2float(src[0]);
        float x2 = __half2float(src[64]);
        float2 cssn = g_rope_tab[s * 64 + i];
        size_t dst = ((size_t)(b * NKV + kvh) * SEQ + s) * HDIM + i;
        g_kh[dst]      = __float2half_rn(x1 * cssn.x - x2 * cssn.y);
        g_kh[dst + 64] = __float2half_rn(x2 * cssn.x + x1 * cssn.y);
    } else if (idx < QTOT + KTOT + VTOT) {
        int j = idx - QTOT - KTOT;
        int d2 = j & 63;
        int rest = j >> 6;
        int kvh = rest & 3;
        int t = rest >> 2;
        int s = t & (SEQ - 1), b = t >> 11;
        const __half2* src = (const __half2*)(g_qkv16 + (size_t)t * QKVN + EMBED + 512 + kvh * HDIM);
        __half2* dst = (__half2*)(g_vh + ((size_t)(b * NKV + kvh) * SEQ + s) * HDIM);
        dst[d2] = src[d2];
    }
}

// ---------------------------------------------------------------------------
// Flash attention fp16: 128 q-rows/CTA, 4 warps x 32 q-rows.
// Base-2 softmax with ex2.approx.f16x2 (p straight into PV fragments).
// Row-sum l accumulated by an extra mma against a CONSTANT ones B-fragment
// (n=0 column of ones: lanes 0-3 hold 0x3C003C00, others 0 — no smem, no
// ldmatrix). l extracted at the end from quad-lane 0, c0/c2.
// 2-stage K/V cp.async, 128 threads, 2 CTAs/SM (smem 104448 B).
// ---------------------------------------------------------------------------
#define AT_QS 0
#define AT_KS 34816
#define AT_VS 69632
#define AT_SMEM 104448

__global__ __launch_bounds__(128, 2) void attn_h()
{
    extern __shared__ char smc[];
    const uint32_t sb = smem_to_u32(smc);

    const int q0   = blockIdx.x * 128;
    const int h    = blockIdx.y;
    const int b    = blockIdx.z;
    const int kvh  = h >> 2;
    const int tid  = threadIdx.x;     // 0..127
    const int lane = tid & 31;
    const int w    = tid >> 5;        // 0..3, rows [w*32, w*32+32)
    const int lr   = lane >> 2;
    const int lc   = lane & 3;

    const __half* qsrc = g_qh + ((size_t)(b * NHEADS + h) * SEQ + q0) * HDIM;
    const __half* ksrc = g_kh + (size_t)(b * NKV + kvh) * SEQ * HDIM;
    const __half* vsrc = g_vh + (size_t)(b * NKV + kvh) * SEQ * HDIM;

    // Constant ones B-fragment: B[k][n] = (n==0). m16n8k16 col-major B layout:
    // n = lane/4, k = (lane%4)*2 + half (+8 for reg1). Lanes 0-3 => n==0.
    const uint32_t bl_ones = (lane < 4) ? 0x3C003C00u : 0u;
    const uint32_t blf[2] = { bl_ones, bl_ones };

    auto issue_kv = [&](int kt) {
        const int buf = kt & 1;
        const int kv0 = kt * 64;
#pragma unroll
        for (int i = 0; i < 8; i++) {
            int slot = tid + i * 128;
            int r = slot >> 4, c = slot & 15;
            cp16(sb + AT_KS + buf * 17408 + r * 272 + c * 16,
                 ksrc + (size_t)(kv0 + r) * HDIM + c * 8);
            cp16(sb + AT_VS + buf * 17408 + r * 272 + c * 16,
                 vsrc + (size_t)(kv0 + r) * HDIM + c * 8);
        }
        CP_COMMIT();
    };

    // Prologue: Q + KV tile 0 in one group
#pragma unroll
    for (int i = 0; i < 16; i++) {
        int slot = tid + i * 128;
        int r = slot >> 4, c = slot & 15;
        cp16(sb + AT_QS + r * 272 + c * 16, qsrc + (size_t)r * HDIM + c * 8);
    }
#pragma unroll
    for (int i = 0; i < 8; i++) {
        int slot = tid + i * 128;
        int r = slot >> 4, c = slot & 15;
        cp16(sb + AT_KS + r * 272 + c * 16, ksrc + (size_t)r * HDIM + c * 8);
        cp16(sb + AT_VS + r * 272 + c * 16, vsrc + (size_t)r * HDIM + c * 8);
    }
    CP_COMMIT();

    // ldmatrix lane bases
    const uint32_t q_base = sb + AT_QS + (w * 32 + (lane & 15)) * 272 + (lane >> 4) * 16;
    const uint32_t k_base = sb + AT_KS
        + (((lane >> 4) << 3) + (lane & 7)) * 272 + ((lane >> 3) & 1) * 16;
    const uint32_t v_base = sb + AT_VS + (lane & 15) * 272 + (lane >> 4) * 16;

    // Softmax max state per (mi, row-half), in base-2 units
    float m00 = -INFINITY, m01 = -INFINITY, m10 = -INFINITY, m11 = -INFINITY;

    float o_acc[2][16][4];
    float o_l[2][4];                    // l accumulator (ones-fragment mma)
#pragma unroll
    for (int mi = 0; mi < 2; mi++) {
#pragma unroll
        for (int ni = 0; ni < 16; ni++)
#pragma unroll
            for (int c = 0; c < 4; c++) o_acc[mi][ni][c] = 0.f;
#pragma unroll
        for (int c = 0; c < 4; c++) o_l[mi][c] = 0.f;
    }

    const int NT = SEQ / 64;   // 32
    for (int kt = 0; kt < NT; kt++) {
        CP_WAIT0();
        __syncthreads();                   // buf kt ready; all warps past kt-1
        if (kt + 1 < NT) issue_kv(kt + 1);

        const uint32_t kb = (kt & 1) * 17408;

        // S = Q @ K^T : warp rows [w*32,+32) x all 64 kv cols (base-2 units)
        float sfr[2][8][4];
#pragma unroll
        for (int mi = 0; mi < 2; mi++)
#pragma unroll
            for (int ni = 0; ni < 8; ni++)
#pragma unroll
                for (int c = 0; c < 4; c++) sfr[mi][ni][c] = 0.f;

#pragma unroll
        for (int ks = 0; ks < 8; ks++) {
            uint32_t af0[4], af1[4];
            ldsm4(af0, q_base + ks * 32);
            ldsm4(af1, q_base + 4352 + ks * 32);   // +16 rows
#pragma unroll
            for (int np = 0; np < 4; np++) {
                uint32_t bf[4];
                ldsm4(bf, k_base + kb + np * 4352 + ks * 32);
                mma16(sfr[0][np * 2],     af0, bf);
                mma16(sfr[0][np * 2 + 1], af0, bf + 2);
                mma16(sfr[1][np * 2],     af1, bf);
                mma16(sfr[1][np * 2 + 1], af1, bf + 2);
            }
        }

        // Warp-local online softmax (base-2): max + ex2.f16x2, pack in-place
        float corr00, corr01, corr10, corr11;
#pragma unroll
        for (int mi = 0; mi < 2; mi++) {
            float mx0 = -INFINITY, mx1 = -INFINITY;
#pragma unroll
            for (int ni = 0; ni < 8; ni++) {
                mx0 = fmaxf(mx0, fmaxf(sfr[mi][ni][0], sfr[mi][ni][1]));
                mx1 = fmaxf(mx1, fmaxf(sfr[mi][ni][2], sfr[mi][ni][3]));
            }
            mx0 = fmaxf(mx0, __shfl_xor_sync(0xffffffffu, mx0, 1));
            mx0 = fmaxf(mx0, __shfl_xor_sync(0xffffffffu, mx0, 2));
            mx1 = fmaxf(mx1, __shfl_xor_sync(0xffffffffu, mx1, 1));
            mx1 = fmaxf(mx1, __shfl_xor_sync(0xffffffffu, mx1, 2));

            float mold0 = mi ? m10 : m00;
            float mold1 = mi ? m11 : m01;
            float mn0 = fmaxf(mold0, mx0);
            float mn1 = fmaxf(mold1, mx1);
            float c0 = ex2f(mold0 - mn0);
            float c1 = ex2f(mold1 - mn1);

#pragma unroll
            for (int ni = 0; ni < 8; ni++) {
                uint32_t* sp = (uint32_t*)&sfr[mi][ni][0];
                sp[0] = h2exp2u(pack_h2(sfr[mi][ni][0] - mn0, sfr[mi][ni][1] - mn0));
                sp[1] = h2exp2u(pack_h2(sfr[mi][ni][2] - mn1, sfr[mi][ni][3] - mn1));
            }

            if (mi == 0) { m00 = mn0; m01 = mn1; corr00 = c0; corr01 = c1; }
            else         { m10 = mn0; m11 = mn1; corr10 = c0; corr11 = c1; }
        }

        // Rescale O (and l) accumulators
#pragma unroll
        for (int ni = 0; ni < 16; ni++) {
            o_acc[0][ni][0] *= corr00; o_acc[0][ni][1] *= corr00;
            o_acc[0][ni][2] *= corr01; o_acc[0][ni][3] *= corr01;
            o_acc[1][ni][0] *= corr10; o_acc[1][ni][1] *= corr10;
            o_acc[1][ni][2] *= corr11; o_acc[1][ni][3] *= corr11;
        }
        o_l[0][0] *= corr00; o_l[0][1] *= corr00; o_l[0][2] *= corr01; o_l[0][3] *= corr01;
        o_l[1][0] *= corr10; o_l[1][1] *= corr10; o_l[1][2] *= corr11; o_l[1][3] *= corr11;

        // O += P @ V ; l += P @ ones (constant fragment, no memory traffic)
#pragma unroll
        for (int kk = 0; kk < 4; kk++) {
            uint32_t pa0[4] = { *(uint32_t*)&sfr[0][kk*2][0], *(uint32_t*)&sfr[0][kk*2][1],
                                *(uint32_t*)&sfr[0][kk*2+1][0], *(uint32_t*)&sfr[0][kk*2+1][1] };
            uint32_t pa1[4] = { *(uint32_t*)&sfr[1][kk*2][0], *(uint32_t*)&sfr[1][kk*2][1],
                                *(uint32_t*)&sfr[1][kk*2+1][0], *(uint32_t*)&sfr[1][kk*2+1][1] };
#pragma unroll
            for (int np = 0; np < 8; np++) {
                uint32_t bf[4];
                ldsm4t(bf, v_base + kb + kk * 4352 + np * 32);
                mma16(o_acc[0][np * 2],     pa0, bf);
                mma16(o_acc[0][np * 2 + 1], pa0, bf + 2);
                mma16(o_acc[1][np * 2],     pa1, bf);
                mma16(o_acc[1][np * 2 + 1], pa1, bf + 2);
            }
            mma16(o_l[0], pa0, blf);
            mma16(o_l[1], pa1, blf);
        }
    }

    // l lives in col 0 -> quad-lane lc==0, c0 (row lr) / c2 (row lr+8).
    // Broadcast within each quad, normalize, write out.
#pragma unroll
    for (int mi = 0; mi < 2; mi++) {
        float lv0 = __shfl_sync(0xffffffffu, o_l[mi][0], lane & ~3);
        float lv1 = __shfl_sync(0xffffffffu, o_l[mi][2], lane & ~3);
        float i0 = 1.0f / lv0;
        float i1 = 1.0f / lv1;
        int row = b * SEQ + q0 + w * 32 + mi * 16 + lr;
#pragma unroll
        for (int ni = 0; ni < 16; ni++) {
            int d = ni * 8 + 2 * lc;
            __half2 h0 = __floats2half2_rn(o_acc[mi][ni][0] * i0, o_acc[mi][ni][1] * i0);
            __half2 h1 = __floats2half2_rn(o_acc[mi][ni][2] * i1, o_acc[mi][ni][3] * i1);
            *(__half2*)(g_oh + (size_t)row * EMBED + h * HDIM + d)       = h0;
            *(__half2*)(g_oh + (size_t)(row + 8) * EMBED + h * HDIM + d) = h1;
        }
    }
}

// ---------------------------------------------------------------------------
extern "C" void kernel_launch(void* const* d_in, const int* in_sizes, int n_in,
                              void* d_out, int out_size)
{
    const float* x   = (const float*)d_in[0];
    const float* Wq  = (const float*)d_in[1];
    const float* bq  = (const float*)d_in[2];
    const float* Wkv = (const float*)d_in[3];
    const float* bkv = (const float*)d_in[4];
    const float* Wo  = (const float*)d_in[5];
    float* out = (float*)d_out;

    __half *xh, *wh, *woh, *qkv16, *oh;
    float* bqkv;
    cudaGetSymbolAddress((void**)&xh,    g_xh);
    cudaGetSymbolAddress((void**)&wh,    g_wh);
    cudaGetSymbolAddress((void**)&woh,   g_woh);
    cudaGetSymbolAddress((void**)&qkv16, g_qkv16);
    cudaGetSymbolAddress((void**)&oh,    g_oh);
    cudaGetSymbolAddress((void**)&bqkv,  g_bqkv);

    const int GEMM_SMEM = 110592;
    cudaFuncSetAttribute(gemm_h<true>,  cudaFuncAttributeMaxDynamicSharedMemorySize, GEMM_SMEM);
    cudaFuncSetAttribute(gemm_h<false>, cudaFuncAttributeMaxDynamicSharedMemorySize, GEMM_SMEM);
    cudaFuncSetAttribute(attn_h, cudaFuncAttributeMaxDynamicSharedMemorySize, AT_SMEM);

    // 0) conversions + rope table + stacked bias (single launch)
    {
        int total = (NTOK * EMBED + 2 * EMBED * EMBED + KVDIM * EMBED) / 4
                  + SEQ * 64 + QKVN;
        prep_all<<<(total + 255) / 256, 256>>>((const float4*)x, (const float4*)Wq,
                                               (const float4*)Wkv, (const float4*)Wo,
                                               bq, bkv);
    }
    // 1) fused qkv = x @ [Wq;Wkv]^T + [bq;bkv]  (fp16 out)
    gemm_h<true><<<dim3(QKVN/128, NTOK/128), 256, GEMM_SMEM>>>(xh, wh, bqkv, qkv16, NTOK, QKVN, EMBED);
    // 2) RoPE + repack (Q pre-scaled for base-2 softmax)
    {
        int total = NTOK*NHEADS*64 + NTOK*NKV*64 + NTOK*NKV*64;
        rope_h<<<(total + 255) / 256, 256>>>();
    }
    // 3) flash attention -> g_oh  (128 threads, 2 CTAs/SM)
    attn_h<<<dim3(SEQ/128, NHEADS, BATCH), 128, AT_SMEM>>>();
    // 4) out = o @ Wo^T  (fp32 out)
    gemm_h<false><<<dim3(EMBED/128, NTOK/128), 256, GEMM_SMEM>>>(oh, woh, nullptr, out, NTOK, EMBED, EMBED);
}